// round 10
// baseline (speedup 1.0000x reference)
#include <cuda_runtime.h>
#include <cuda_bf16.h>
#include <mma.h>
#include <math.h>
#include <cstdint>

using namespace nvcuda;

// ---------------- problem constants ----------------
// B=2, T=8, H=16, W=16, E=512, n_heads=16, d=32, S=4096, L2=512, WINDOW=4
// frames BT=16, padded frames per batch TPAD=11, K of all GEMMs = 512

// ---------------- device scratch ----------------
__device__ __align__(128) float g_teK[4 * 512];
__device__ __align__(128) float g_beta[8192ull * 64];      // [row][head*4+slot]
__device__ __align__(128) float2 g_ropeT[2 * 256 * 16];    // cos/sin table

__device__ __align__(128) __nv_bfloat16 g_hh [8192ull * 512], g_hl [8192ull * 512];
__device__ __align__(128) __nv_bfloat16 g_Wh [1536ull * 512], g_Wl [1536ull * 512];
__device__ __align__(128) __nv_bfloat16 g_Woh[ 512ull * 512], g_Wol[ 512ull * 512];
__device__ __align__(128) __nv_bfloat16 g_qbh[8192ull * 512], g_qbl[8192ull * 512];
__device__ __align__(128) __nv_bfloat16 g_kbh[8192ull * 512], g_kbl[8192ull * 512];
__device__ __align__(128) __nv_bfloat16 g_vbh[8192ull * 512], g_vbl[8192ull * 512];
__device__ __align__(128) __nv_bfloat16 g_obh[8192ull * 512], g_obl[8192ull * 512];

// attention operands, precomputed split (k now PADDED like v — no windowed copies)
__device__ __align__(128) __nv_bfloat16 g_qwh[8192ull * 512], g_qwl[8192ull * 512];
__device__ __align__(128) __nv_bfloat16 g_kph[2ull*11*512*512], g_kpl[2ull*11*512*512];
__device__ __align__(128) __nv_bfloat16 g_vph[2ull*11*512*512], g_vpl[2ull*11*512*512];

// ---------------- helpers ----------------
__device__ __forceinline__ void split2(float x, float y,
                                       __nv_bfloat162& h, __nv_bfloat162& l) {
    __nv_bfloat16 hx = __float2bfloat16_rn(x);
    __nv_bfloat16 hy = __float2bfloat16_rn(y);
    h = __halves2bfloat162(hx, hy);
    l = __halves2bfloat162(__float2bfloat16_rn(x - __bfloat162float(hx)),
                           __float2bfloat16_rn(y - __bfloat162float(hy)));
}
__device__ __forceinline__ uint32_t bfpack_hi(float x, float y) {
    __nv_bfloat162 h = __floats2bfloat162_rn(x, y);
    return *(uint32_t*)&h;
}
__device__ __forceinline__ uint32_t bfpack_lo(float x, float y) {
    float rx = __bfloat162float(__float2bfloat16_rn(x));
    float ry = __bfloat162float(__float2bfloat16_rn(y));
    __nv_bfloat162 l = __floats2bfloat162_rn(x - rx, y - ry);
    return *(uint32_t*)&l;
}
__device__ __forceinline__ uint32_t smem_u32(const void* p) {
    uint32_t a;
    asm("{ .reg .u64 t; cvta.to.shared.u64 t, %1; cvt.u32.u64 %0, t; }" : "=r"(a) : "l"(p));
    return a;
}
__device__ __forceinline__ void ldsm_x2(uint32_t& r0, uint32_t& r1, uint32_t addr) {
    asm volatile("ldmatrix.sync.aligned.m8n8.x2.shared.b16 {%0,%1}, [%2];"
        : "=r"(r0), "=r"(r1) : "r"(addr));
}
__device__ __forceinline__ void ldsm_x2t(uint32_t& r0, uint32_t& r1, uint32_t addr) {
    asm volatile("ldmatrix.sync.aligned.m8n8.x2.trans.shared.b16 {%0,%1}, [%2];"
        : "=r"(r0), "=r"(r1) : "r"(addr));
}
__device__ __forceinline__ void mma16816(float* d, const uint32_t* a, uint32_t b0, uint32_t b1) {
    asm volatile("mma.sync.aligned.m16n8k16.row.col.f32.bf16.bf16.f32 "
        "{%0,%1,%2,%3}, {%4,%5,%6,%7}, {%8,%9}, {%0,%1,%2,%3};"
        : "+f"(d[0]), "+f"(d[1]), "+f"(d[2]), "+f"(d[3])
        : "r"(a[0]), "r"(a[1]), "r"(a[2]), "r"(a[3]), "r"(b0), "r"(b1));
}
__device__ __forceinline__ void cp16(uint32_t dst, const void* src) {
    asm volatile("cp.async.cg.shared.global [%0], [%1], 16;" :: "r"(dst), "l"(src));
}
#define CP_COMMIT() asm volatile("cp.async.commit_group;" ::: "memory")
#define CP_WAIT0()  asm volatile("cp.async.wait_group 0;" ::: "memory")
#define CP_WAIT1()  asm volatile("cp.async.wait_group 1;" ::: "memory")

// ---------------- rope table precompute (identical math to the old rope_cs) ----------------
__global__ void rope_table()
{
    int idx = blockIdx.x * 256 + threadIdx.x;   // 8192 entries
    int tsel = idx >> 12, pos = (idx >> 4) & 255, j = idx & 15;
    int fidx; float posv;
    if (tsel == 0) { fidx = j; posv = (float)pos; }
    else {
        int h = pos >> 4, w = pos & 15;
        if (j < 8) { fidx = 2 * j;           posv = (float)h; }
        else       { fidx = 2 * (j - 8) + 1; posv = (float)w; }
    }
    float freq = __powf(10000.0f, -(float)fidx * (1.0f / 16.0f));
    float sn, cs;
    sincosf(posv * freq, &sn, &cs);
    g_ropeT[idx] = make_float2(cs, sn);
}

// ---------------- fused bf16 split of the 3 fp32 inputs ----------------
__global__ void split_all(const float* __restrict__ hidden, const float* __restrict__ W,
                          const float* __restrict__ Wo)
{
    int bid = blockIdx.x;
    const float* src;
    __nv_bfloat16 *hi, *lo;
    int rb;
    if (bid < 4096)      { src = hidden; hi = g_hh;  lo = g_hl;  rb = bid; }
    else if (bid < 4864) { src = W;      hi = g_Wh;  lo = g_Wl;  rb = bid - 4096; }
    else                 { src = Wo;     hi = g_Woh; lo = g_Wol; rb = bid - 4864; }
    size_t i = ((size_t)rb * 256 + threadIdx.x) * 4;
    float4 v = *(const float4*)(src + i);
    __nv_bfloat162 h0, l0, h1, l1;
    split2(v.x, v.y, h0, l0);
    split2(v.z, v.w, h1, l1);
    *(__nv_bfloat162*)(hi + i)     = h0;
    *(__nv_bfloat162*)(hi + i + 2) = h1;
    *(__nv_bfloat162*)(lo + i)     = l0;
    *(__nv_bfloat162*)(lo + i + 2) = l1;
}

// ---------------- cp.async double-buffered GEMM mainloop ----------------
#define GEMM_MAINLOOP(Ahi, Alo, Bhi, Blo)                                           \
    wmma::fragment<wmma::accumulator, 16, 16, 16, float> fc[4][2];                  \
    _Pragma("unroll") for (int i = 0; i < 4; i++)                                   \
        _Pragma("unroll") for (int j = 0; j < 2; j++) wmma::fill_fragment(fc[i][j], 0.f); \
    auto stage = [&](int st) {                                                      \
        int k0 = st * 32;                                                           \
        int bo = (st & 1) * 20480;                                                  \
        _Pragma("unroll") for (int i = 0; i < 8; i++) {                             \
            int c = tid + i * 256;                                                  \
            int arr = c >> 9, rem = c & 511, row = rem >> 2, seg = rem & 3;         \
            const __nv_bfloat16* src =                                              \
                (arr == 0) ? Ahi + (size_t)(m0 + row) * 512 + k0 + seg * 8 :        \
                (arr == 1) ? Alo + (size_t)(m0 + row) * 512 + k0 + seg * 8 :        \
                (arr == 2) ? Bhi + (size_t)(n0 + row) * 512 + k0 + seg * 8 :        \
                             Blo + (size_t)(n0 + row) * 512 + k0 + seg * 8;         \
            cp16(smem_u32(smp + bo + arr * 5120 + row * 40 + seg * 8), src);        \
        }                                                                           \
        CP_COMMIT();                                                                \
    };                                                                              \
    stage(0);                                                                       \
    for (int st = 0; st < 16; st++) {                                               \
        CP_WAIT0();                                                                 \
        __syncthreads();                                                            \
        if (st + 1 < 16) stage(st + 1);                                             \
        const __nv_bfloat16* sAh = smp + (st & 1) * 20480;                          \
        const __nv_bfloat16* sAl = sAh + 5120;                                      \
        const __nv_bfloat16* sBh = sAh + 10240;                                     \
        const __nv_bfloat16* sBl = sAh + 15360;                                     \
        _Pragma("unroll") for (int ks = 0; ks < 32; ks += 16) {                     \
            wmma::fragment<wmma::matrix_a, 16, 16, 16, __nv_bfloat16, wmma::row_major> fah[4], fal[4]; \
            wmma::fragment<wmma::matrix_b, 16, 16, 16, __nv_bfloat16, wmma::col_major> fbh[2], fbl[2]; \
            _Pragma("unroll") for (int i = 0; i < 4; i++) {                         \
                wmma::load_matrix_sync(fah[i], &sAh[(wm + i * 16) * 40 + ks], 40);  \
                wmma::load_matrix_sync(fal[i], &sAl[(wm + i * 16) * 40 + ks], 40);  \
            }                                                                       \
            _Pragma("unroll") for (int j = 0; j < 2; j++) {                         \
                wmma::load_matrix_sync(fbh[j], &sBh[(wn + j * 16) * 40 + ks], 40);  \
                wmma::load_matrix_sync(fbl[j], &sBl[(wn + j * 16) * 40 + ks], 40);  \
            }                                                                       \
            _Pragma("unroll") for (int i = 0; i < 4; i++)                           \
                _Pragma("unroll") for (int j = 0; j < 2; j++) {                     \
                    wmma::mma_sync(fc[i][j], fah[i], fbh[j], fc[i][j]);             \
                    wmma::mma_sync(fc[i][j], fah[i], fbl[j], fc[i][j]);             \
                    wmma::mma_sync(fc[i][j], fal[i], fbh[j], fc[i][j]);             \
                }                                                                   \
        }                                                                           \
        __syncthreads();                                                            \
    }

static constexpr int GEMM_SMEM = 2 * 4 * 5120 * 2;  // 81920 bytes

// ---------------- big qkv GEMM with fused RoPE + reorder + bf16-split epilogue ----------------
__global__ void __launch_bounds__(256, 2) gemm_rope(
    const __nv_bfloat16* __restrict__ Ahi, const __nv_bfloat16* __restrict__ Alo,
    const __nv_bfloat16* __restrict__ Bhi, const __nv_bfloat16* __restrict__ Blo,
    const float* __restrict__ bias)
{
    extern __shared__ __align__(16) __nv_bfloat16 smp[];
    const int tid = threadIdx.x, w = tid >> 5, lane = tid & 31;
    const int m0 = blockIdx.y * 128, n0 = blockIdx.x * 128;
    const int wm = (w >> 2) * 64, wn = (w & 3) * 32;

    GEMM_MAINLOOP(Ahi, Alo, Bhi, Blo)

    float* cst = reinterpret_cast<float*>(smp) + w * 256;
    const int er = lane >> 1, ec = (lane & 1) * 8;
    #pragma unroll
    for (int i = 0; i < 4; i++)
        #pragma unroll
        for (int j = 0; j < 2; j++) {
            wmma::store_matrix_sync(cst, fc[i][j], 16, wmma::mem_row_major);
            __syncwarp();
            int gr = m0 + wm + i * 16 + er;
            int gn = n0 + wn + j * 16 + ec;
            int b = gr >> 12, s = gr & 4095;
            float v[8];
            #pragma unroll
            for (int c = 0; c < 8; c++) v[c] = cst[er * 16 + ec + c] + bias[gn + c];

            int z = gn >> 9;   // block-uniform (128 | 512)
            if (z == 2) {
                // v: straight reshape, no rope
                int frame = b * 8 + (s >> 9), l = s & 511;
                size_t o = ((size_t)frame * 512 + l) * 512 + (gn & 511);
                #pragma unroll
                for (int c = 0; c < 8; c += 2) {
                    __nv_bfloat162 h2, l2;
                    split2(v[c], v[c + 1], h2, l2);
                    *(__nv_bfloat162*)(g_vbh + o + c) = h2;
                    *(__nv_bfloat162*)(g_vbl + o + c) = l2;
                }
            } else {
                // q or k: stream reorder + rope (table lookup)
                int frame, l;
                if (s < 2048) { frame = b * 8 + (s >> 8); l = s & 255; }
                else { int s2 = s - 2048; frame = b * 8 + (s2 >> 8); l = 256 + (s2 & 255); }
                size_t o = ((size_t)frame * 512 + l) * 512 + (gn & 511);
                __nv_bfloat16* hi = z ? g_kbh : g_qbh;
                __nv_bfloat16* lo = z ? g_kbl : g_qbl;
                int tbase = ((s >> 11) << 12) + ((s & 255) << 4);
                #pragma unroll
                for (int c = 0; c < 8; c += 2) {
                    int pj = ((gn + c) >> 1) & 15;
                    float2 tv = g_ropeT[tbase + pj];
                    float xr = v[c] * tv.x - v[c + 1] * tv.y;
                    float xi = v[c] * tv.y + v[c + 1] * tv.x;
                    __nv_bfloat162 h2, l2;
                    split2(xr, xi, h2, l2);
                    *(__nv_bfloat162*)(hi + o + c) = h2;
                    *(__nv_bfloat162*)(lo + o + c) = l2;
                }
            }
            __syncwarp();
        }
}

// ---------------- GEMM with fp32 output (out-proj) ----------------
__global__ void __launch_bounds__(256, 2) gemm_wmma(
    const __nv_bfloat16* __restrict__ Ahi, const __nv_bfloat16* __restrict__ Alo,
    const __nv_bfloat16* __restrict__ Bhi, const __nv_bfloat16* __restrict__ Blo,
    const float* __restrict__ bias, float* __restrict__ C, int N)
{
    extern __shared__ __align__(16) __nv_bfloat16 smp[];
    const int tid = threadIdx.x, w = tid >> 5, lane = tid & 31;
    const int m0 = blockIdx.y * 128, n0 = blockIdx.x * 128;
    const int wm = (w >> 2) * 64, wn = (w & 3) * 32;

    GEMM_MAINLOOP(Ahi, Alo, Bhi, Blo)

    float* cst = reinterpret_cast<float*>(smp) + w * 256;
    const int er = lane >> 1, ec = (lane & 1) * 8;
    #pragma unroll
    for (int i = 0; i < 4; i++)
        #pragma unroll
        for (int j = 0; j < 2; j++) {
            wmma::store_matrix_sync(cst, fc[i][j], 16, wmma::mem_row_major);
            __syncwarp();
            int gr = m0 + wm + i * 16 + er;
            int gn = n0 + wn + j * 16 + ec;
            float4 v0 = *(float4*)&cst[er * 16 + ec];
            float4 v1 = *(float4*)&cst[er * 16 + ec + 4];
            float4 b0 = *(const float4*)(bias + gn);
            float4 b1 = *(const float4*)(bias + gn + 4);
            v0.x += b0.x; v0.y += b0.y; v0.z += b0.z; v0.w += b0.w;
            v1.x += b1.x; v1.y += b1.y; v1.z += b1.z; v1.w += b1.w;
            float* crow = C + (size_t)gr * N + gn;
            *(float4*)crow = v0;
            *(float4*)(crow + 4) = v1;
            __syncwarp();
        }
}

// ---------------- fused second projections (z = 0:q, 1:k-padded, 2:v-padded) ----------------
__global__ void __launch_bounds__(256, 2) gemm_small(
    const __nv_bfloat16* __restrict__ qAh, const __nv_bfloat16* __restrict__ qAl,
    const __nv_bfloat16* __restrict__ kAh, const __nv_bfloat16* __restrict__ kAl,
    const __nv_bfloat16* __restrict__ vAh, const __nv_bfloat16* __restrict__ vAl,
    const __nv_bfloat16* __restrict__ Wh,  const __nv_bfloat16* __restrict__ Wl,
    const float* __restrict__ bias_all)
{
    extern __shared__ __align__(16) __nv_bfloat16 smp[];
    const int tid = threadIdx.x, w = tid >> 5, lane = tid & 31;
    const int z = blockIdx.z;
    const int m0 = blockIdx.y * 128, n0 = blockIdx.x * 128;
    const int wm = (w >> 2) * 64, wn = (w & 3) * 32;

    const __nv_bfloat16* Ahi = (z == 0) ? qAh : (z == 1) ? kAh : vAh;
    const __nv_bfloat16* Alo = (z == 0) ? qAl : (z == 1) ? kAl : vAl;
    const __nv_bfloat16* Bhi = Wh + (size_t)z * 512 * 512;
    const __nv_bfloat16* Blo = Wl + (size_t)z * 512 * 512;
    const float* bias = bias_all + z * 512;

    GEMM_MAINLOOP(Ahi, Alo, Bhi, Blo)

    float* cst = reinterpret_cast<float*>(smp) + w * 256;
    const int er = lane >> 1, ec = (lane & 1) * 8;
    // q pre-scale folds 1/sqrt(d) AND log2(e) (attention uses exp2)
    const float scale = 0.17677669529663689f * 1.4426950408889634f;
    #pragma unroll
    for (int i = 0; i < 4; i++)
        #pragma unroll
        for (int j = 0; j < 2; j++) {
            wmma::store_matrix_sync(cst, fc[i][j], 16, wmma::mem_row_major);
            __syncwarp();
            int gr = m0 + wm + i * 16 + er;
            int gn = n0 + wn + j * 16 + ec;
            float v[8];
            #pragma unroll
            for (int c = 0; c < 8; c++) v[c] = cst[er * 16 + ec + c] + bias[gn + c];

            if (z == 0) {
                size_t o = (size_t)gr * 512 + gn;
                #pragma unroll
                for (int c = 0; c < 8; c += 2) {
                    __nv_bfloat162 h, l;
                    split2(v[c] * scale, v[c + 1] * scale, h, l);
                    *(__nv_bfloat162*)(g_qwh + o + c) = h;
                    *(__nv_bfloat162*)(g_qwl + o + c) = l;
                }
            } else {
                // k (z=1) and v (z=2): padded layout, single store per element
                int out_r = gr + ((gr >> 12) + 1) * 1536;
                size_t o = (size_t)out_r * 512 + gn;
                __nv_bfloat16* hi = (z == 1) ? g_kph : g_vph;
                __nv_bfloat16* lo = (z == 1) ? g_kpl : g_vpl;
                #pragma unroll
                for (int c = 0; c < 8; c += 2) {
                    __nv_bfloat162 h, l;
                    split2(v[c], v[c + 1], h, l);
                    *(__nv_bfloat162*)(hi + o + c) = h;
                    *(__nv_bfloat162*)(lo + o + c) = l;
                }
            }
            __syncwarp();
        }
}

// ---------------- pad fills: 3 lead frames of kp and vp = projected-zero rows (bias) ----------------
__global__ void fill_pad2(const float* __restrict__ bias)
{
    int rid = blockIdx.x;          // 0..6143
    int e = threadIdx.x * 2;
    int isV = rid >= 3072;
    int r2 = isV ? rid - 3072 : rid;
    int b = r2 / 1536;
    int rem = r2 - b * 1536;
    int fp = rem >> 9, l = rem & 511;
    const float* bs = bias + (isV ? 1024 : 512);
    __nv_bfloat162 h, lo2;
    split2(bs[e], bs[e + 1], h, lo2);
    size_t o = ((size_t)(b * 11 + fp) * 512 + l) * 512 + e;
    __nv_bfloat16* hi = isV ? g_vph : g_kph;
    __nv_bfloat16* lo = isV ? g_vpl : g_kpl;
    *(__nv_bfloat162*)(hi + o) = h;
    *(__nv_bfloat162*)(lo + o) = lo2;
}

// ---------------- teK: warp-per-output ----------------
__global__ void compute_teK(const float* __restrict__ te, const float* __restrict__ W)
{
    int o = blockIdx.x * 8 + (threadIdx.x >> 5);
    int lane = threadIdx.x & 31;
    int i = o >> 9, e = o & 511;
    const float4* wk = (const float4*)(W + (size_t)(512 + e) * 512) + lane * 4;
    const float4* tr = (const float4*)(te + i * 512) + lane * 4;
    float s = 0.f;
    #pragma unroll
    for (int k = 0; k < 4; k++) {
        float4 a = tr[k], b = wk[k];
        s += a.x * b.x + a.y * b.y + a.z * b.z + a.w * b.w;
    }
    #pragma unroll
    for (int d = 16; d > 0; d >>= 1) s += __shfl_xor_sync(0xffffffffu, s, d);
    if (lane == 0) g_teK[i * 512 + e] = s;
}

// ---------------- beta: β[row][head][slot] = q_scaled[row, head-dims] · teK[slot, head-dims] ----------------
// grid 8192 (rows), 128 threads: 16 heads x 8 threads; each thread 4 dims x 4 slots, shfl-reduce over 8.
__global__ void compute_beta()
{
    int row = blockIdx.x;
    int tid = threadIdx.x;
    int head = tid >> 3, sub = tid & 7;
    int d0 = head * 32 + sub * 4;
    float q[4];
    #pragma unroll
    for (int c = 0; c < 4; c++)
        q[c] = __bfloat162float(g_qwh[(size_t)row * 512 + d0 + c]) +
               __bfloat162float(g_qwl[(size_t)row * 512 + d0 + c]);
    float p[4];
    #pragma unroll
    for (int sl = 0; sl < 4; sl++) {
        const float* tk = g_teK + sl * 512 + d0;
        p[sl] = q[0] * tk[0] + q[1] * tk[1] + q[2] * tk[2] + q[3] * tk[3];
    }
    #pragma unroll
    for (int d = 1; d < 8; d <<= 1) {
        #pragma unroll
        for (int sl = 0; sl < 4; sl++)
            p[sl] += __shfl_xor_sync(0xffffffffu, p[sl], d);
    }
    if (sub == 0)
        *(float4*)(g_beta + (size_t)row * 64 + head * 4) = make_float4(p[0], p[1], p[2], p[3]);
}

// ---------------- tensor-core flash attention, 3-stage cp.async pipeline ----------------
// teK folded into softmax: P = exp2(q·kp + β). K read from padded kp (same addressing as v).
__global__ void __launch_bounds__(256) attn_mma()
{
    const int f = blockIdx.z, head = blockIdx.y;
    const int tid = threadIdx.x, w = tid >> 5, lane = tid & 31;
    const int b = f >> 3, t = f & 7;
    const int n32 = head * 32;
    const int qbase = blockIdx.x * 256 + w * 32;

    __shared__ __align__(16) __nv_bfloat16 sKV[3][4][32 * 40];

    uint32_t Qh[2][2][4], Ql[2][2][4];
    float b4[2][2][4];   // [m][row-half][slot]
    {
        int r = lane >> 2, c = (lane & 3) * 2;
        #pragma unroll
        for (int mt = 0; mt < 2; mt++) {
            #pragma unroll
            for (int kt = 0; kt < 2; kt++) {
                size_t base = (size_t)(f * 512 + qbase + mt * 16 + r) * 512 + n32 + kt * 16 + c;
                Qh[mt][kt][0] = *(const uint32_t*)(g_qwh + base);
                Qh[mt][kt][1] = *(const uint32_t*)(g_qwh + base + 8 * 512);
                Qh[mt][kt][2] = *(const uint32_t*)(g_qwh + base + 8);
                Qh[mt][kt][3] = *(const uint32_t*)(g_qwh + base + 8 * 512 + 8);
                Ql[mt][kt][0] = *(const uint32_t*)(g_qwl + base);
                Ql[mt][kt][1] = *(const uint32_t*)(g_qwl + base + 8 * 512);
                Ql[mt][kt][2] = *(const uint32_t*)(g_qwl + base + 8);
                Ql[mt][kt][3] = *(const uint32_t*)(g_qwl + base + 8 * 512 + 8);
            }
            #pragma unroll
            for (int hf = 0; hf < 2; hf++) {
                size_t brow = (size_t)(f * 512 + qbase + mt * 16 + hf * 8 + r) * 64 + head * 4;
                *(float4*)b4[mt][hf] = *(const float4*)(g_beta + brow);
            }
        }
    }

    float O[2][4][4];
    float lsum[2][2] = {{0.f, 0.f}, {0.f, 0.f}};
    #pragma unroll
    for (int m = 0; m < 2; m++)
        #pragma unroll
        for (int n = 0; n < 4; n++)
            #pragma unroll
            for (int c = 0; c < 4; c++) O[m][n][c] = 0.f;

    const int idx0 = tid * 2;
    const int arr0 = idx0 >> 7;
    const int r0s = (idx0 >> 2) & 31, seg0 = idx0 & 3;
    const int r1s = ((idx0 + 1) >> 2) & 31, seg1 = (idx0 + 1) & 3;

    auto stage = [&](int cc, int buf) {
        int slot = cc >> 4, lb = (cc & 15) << 5;
        size_t prow = (size_t)(b * 11 + t + slot) * 512 + lb;
        const __nv_bfloat16* base =
            (arr0 == 0) ? g_kph + (prow * 512 + n32) :
            (arr0 == 1) ? g_kpl + (prow * 512 + n32) :
            (arr0 == 2) ? g_vph + (prow * 512 + n32) :
                          g_vpl + (prow * 512 + n32);
        cp16(smem_u32(&sKV[buf][arr0][r0s * 40 + seg0 * 8]), base + (size_t)r0s * 512 + seg0 * 8);
        cp16(smem_u32(&sKV[buf][arr0][r1s * 40 + seg1 * 8]), base + (size_t)r1s * 512 + seg1 * 8);
        CP_COMMIT();
    };

    stage(0, 0);
    stage(1, 1);

    for (int cc = 0; cc < 64; cc++) {
        CP_WAIT1();
        __syncthreads();
        if (cc + 2 < 64) stage(cc + 2, (cc + 2) % 3); else CP_COMMIT();
        const int buf = cc % 3;
        const int slot = cc >> 4;

        // ---- S = Q @ Kp^T (3-pass split) ----
        float S[2][4][4];
        #pragma unroll
        for (int m = 0; m < 2; m++)
            #pragma unroll
            for (int n = 0; n < 4; n++)
                #pragma unroll
                for (int c = 0; c < 4; c++) S[m][n][c] = 0.f;

        #pragma unroll
        for (int kt = 0; kt < 2; kt++) {
            #pragma unroll
            for (int nt = 0; nt < 4; nt++) {
                int l = lane & 15;
                int ki = (nt * 8 + (l & 7)) * 40 + kt * 16 + (l >> 3) * 8;
                uint32_t kh0, kh1, kl0, kl1;
                ldsm_x2(kh0, kh1, smem_u32(&sKV[buf][0][ki]));
                ldsm_x2(kl0, kl1, smem_u32(&sKV[buf][1][ki]));
                #pragma unroll
                for (int m = 0; m < 2; m++) {
                    mma16816(S[m][nt], Qh[m][kt], kh0, kh1);
                    mma16816(S[m][nt], Qh[m][kt], kl0, kl1);
                    mma16816(S[m][nt], Ql[m][kt], kh0, kh1);
                }
            }
        }

        // ---- exp2(S + β) + lsum ----
        #pragma unroll
        for (int m = 0; m < 2; m++) {
            float b0 = b4[m][0][slot], b1 = b4[m][1][slot];
            #pragma unroll
            for (int n = 0; n < 4; n++) {
                S[m][n][0] = exp2f(S[m][n][0] + b0);
                S[m][n][1] = exp2f(S[m][n][1] + b0);
                S[m][n][2] = exp2f(S[m][n][2] + b1);
                S[m][n][3] = exp2f(S[m][n][3] + b1);
                lsum[m][0] += S[m][n][0] + S[m][n][1];
                lsum[m][1] += S[m][n][2] + S[m][n][3];
            }
        }

        // ---- O += P @ V (3-pass split) ----
        #pragma unroll
        for (int kt = 0; kt < 2; kt++) {
            uint32_t Ph[2][4], Pl[2][4];
            #pragma unroll
            for (int m = 0; m < 2; m++) {
                const float* s0 = S[m][2 * kt];
                const float* s1 = S[m][2 * kt + 1];
                Ph[m][0] = bfpack_hi(s0[0], s0[1]); Pl[m][0] = bfpack_lo(s0[0], s0[1]);
                Ph[m][1] = bfpack_hi(s0[2], s0[3]); Pl[m][1] = bfpack_lo(s0[2], s0[3]);
                Ph[m][2] = bfpack_hi(s1[0], s1[1]); Pl[m][2] = bfpack_lo(s1[0], s1[1]);
                Ph[m][3] = bfpack_hi(s1[2], s1[3]); Pl[m][3] = bfpack_lo(s1[2], s1[3]);
            }
            #pragma unroll
            for (int nt = 0; nt < 4; nt++) {
                int l = lane & 15;
                int vi = (kt * 16 + l) * 40 + nt * 8;
                uint32_t vh0, vh1, vl0, vl1;
                ldsm_x2t(vh0, vh1, smem_u32(&sKV[buf][2][vi]));
                ldsm_x2t(vl0, vl1, smem_u32(&sKV[buf][3][vi]));
                #pragma unroll
                for (int m = 0; m < 2; m++) {
                    mma16816(O[m][nt], Ph[m], vh0, vh1);
                    mma16816(O[m][nt], Ph[m], vl0, vl1);
                    mma16816(O[m][nt], Pl[m], vh0, vh1);
                }
            }
        }
    }

    // ---- epilogue ----
    float inv[2][2];
    #pragma unroll
    for (int m = 0; m < 2; m++)
        #pragma unroll
        for (int h = 0; h < 2; h++) {
            float s = lsum[m][h];
            s += __shfl_xor_sync(0xffffffffu, s, 1);
            s += __shfl_xor_sync(0xffffffffu, s, 2);
            inv[m][h] = 1.f / s;
        }
    #pragma unroll
    for (int m = 0; m < 2; m++) {
        int r0 = f * 512 + qbase + m * 16 + (lane >> 2);
        #pragma unroll
        for (int nt = 0; nt < 4; nt++) {
            int col = n32 + nt * 8 + (lane & 3) * 2;
            float a0 = O[m][nt][0] * inv[m][0], a1 = O[m][nt][1] * inv[m][0];
            float a2 = O[m][nt][2] * inv[m][1], a3 = O[m][nt][3] * inv[m][1];
            __nv_bfloat162 h0, l0, h1, l1;
            split2(a0, a1, h0, l0);
            split2(a2, a3, h1, l1);
            *(__nv_bfloat162*)(g_obh + (size_t)r0 * 512 + col)       = h0;
            *(__nv_bfloat162*)(g_obl + (size_t)r0 * 512 + col)       = l0;
            *(__nv_bfloat162*)(g_obh + (size_t)(r0 + 8) * 512 + col) = h1;
            *(__nv_bfloat162*)(g_obl + (size_t)(r0 + 8) * 512 + col) = l1;
        }
    }
}

// ---------------- launcher ----------------
extern "C" void kernel_launch(void* const* d_in, const int* in_sizes, int n_in,
                              void* d_out, int out_size)
{
    const float* hidden = (const float*)d_in[0];
    const float* W      = (const float*)d_in[1];
    const float* bias   = (const float*)d_in[2];
    const float* Wo     = (const float*)d_in[3];
    const float* bo     = (const float*)d_in[4];
    const float* te     = (const float*)d_in[5];
    float* out = (float*)d_out;

    __nv_bfloat16 *p_hh, *p_hl, *p_Wh, *p_Wl, *p_Woh, *p_Wol;
    __nv_bfloat16 *p_qbh, *p_qbl, *p_kbh, *p_kbl, *p_vbh, *p_vbl, *p_obh, *p_obl;
    cudaGetSymbolAddress((void**)&p_hh,  g_hh);   cudaGetSymbolAddress((void**)&p_hl,  g_hl);
    cudaGetSymbolAddress((void**)&p_Wh,  g_Wh);   cudaGetSymbolAddress((void**)&p_Wl,  g_Wl);
    cudaGetSymbolAddress((void**)&p_Woh, g_Woh);  cudaGetSymbolAddress((void**)&p_Wol, g_Wol);
    cudaGetSymbolAddress((void**)&p_qbh, g_qbh);  cudaGetSymbolAddress((void**)&p_qbl, g_qbl);
    cudaGetSymbolAddress((void**)&p_kbh, g_kbh);  cudaGetSymbolAddress((void**)&p_kbl, g_kbl);
    cudaGetSymbolAddress((void**)&p_vbh, g_vbh);  cudaGetSymbolAddress((void**)&p_vbl, g_vbl);
    cudaGetSymbolAddress((void**)&p_obh, g_obh);  cudaGetSymbolAddress((void**)&p_obl, g_obl);

    cudaFuncSetAttribute(gemm_rope,  cudaFuncAttributeMaxDynamicSharedMemorySize, GEMM_SMEM);
    cudaFuncSetAttribute(gemm_wmma,  cudaFuncAttributeMaxDynamicSharedMemorySize, GEMM_SMEM);
    cudaFuncSetAttribute(gemm_small, cudaFuncAttributeMaxDynamicSharedMemorySize, GEMM_SMEM);

    // 0) rope table + input splits + teK
    rope_table<<<32, 256>>>();
    split_all<<<5120, 256>>>(hidden, W, Wo);
    compute_teK<<<256, 256>>>(te, W);

    // 1) qkv GEMM with fused RoPE + reorder + split epilogue
    gemm_rope<<<dim3(12, 64), 256, GEMM_SMEM>>>(p_hh, p_hl, p_Wh, p_Wl, bias);

    // 2) pad fills (k and v padded layouts)
    fill_pad2<<<6144, 256>>>(bias);

    // 3) fused second projections (k now single padded copy — no windowed fan-out)
    gemm_small<<<dim3(4, 64, 3), 256, GEMM_SMEM>>>(p_qbh, p_qbl, p_kbh, p_kbl, p_vbh, p_vbl,
                                                   p_Wh, p_Wl, bias);

    // 4) beta = q_scaled · teK per (row, head, slot)
    compute_beta<<<8192, 128>>>();

    // 5) sliding-window attention (teK folded into softmax via beta)
    attn_mma<<<dim3(2, 16, 16), 256>>>();

    // 6) out = o @ Wo^T + bo
    gemm_wmma<<<dim3(4, 64), 256, GEMM_SMEM>>>(p_obh, p_obl, p_Woh, p_Wol, bo, out, 512);
}

// round 11
// speedup vs baseline: 1.0832x; 1.0832x over previous
#include <cuda_runtime.h>
#include <cuda_bf16.h>
#include <mma.h>
#include <math.h>
#include <cstdint>

using namespace nvcuda;

// ---------------- problem constants ----------------
// B=2, T=8, H=16, W=16, E=512, n_heads=16, d=32, S=4096, L2=512, WINDOW=4
// frames BT=16, padded frames per batch TPAD=11, K of all GEMMs = 512

// ---------------- device scratch ----------------
__device__ __align__(128) float g_teK[4 * 512];
__device__ __align__(128) float g_beta[8192ull * 64];      // [row][head*4+slot]
__device__ __align__(128) float2 g_ropeT[2 * 256 * 16];    // cos/sin table

__device__ __align__(128) __nv_bfloat16 g_hh [8192ull * 512], g_hl [8192ull * 512];
__device__ __align__(128) __nv_bfloat16 g_Wh [1536ull * 512], g_Wl [1536ull * 512];
__device__ __align__(128) __nv_bfloat16 g_Woh[ 512ull * 512], g_Wol[ 512ull * 512];
__device__ __align__(128) __nv_bfloat16 g_qbh[8192ull * 512], g_qbl[8192ull * 512];
__device__ __align__(128) __nv_bfloat16 g_kbh[8192ull * 512], g_kbl[8192ull * 512];
__device__ __align__(128) __nv_bfloat16 g_vbh[8192ull * 512], g_vbl[8192ull * 512];
__device__ __align__(128) __nv_bfloat16 g_obh[8192ull * 512], g_obl[8192ull * 512];

// attention operands, precomputed split (k PADDED like v — no windowed copies)
__device__ __align__(128) __nv_bfloat16 g_qwh[8192ull * 512], g_qwl[8192ull * 512];
__device__ __align__(128) __nv_bfloat16 g_kph[2ull*11*512*512], g_kpl[2ull*11*512*512];
__device__ __align__(128) __nv_bfloat16 g_vph[2ull*11*512*512], g_vpl[2ull*11*512*512];

// ---------------- helpers ----------------
__device__ __forceinline__ void split2(float x, float y,
                                       __nv_bfloat162& h, __nv_bfloat162& l) {
    __nv_bfloat16 hx = __float2bfloat16_rn(x);
    __nv_bfloat16 hy = __float2bfloat16_rn(y);
    h = __halves2bfloat162(hx, hy);
    l = __halves2bfloat162(__float2bfloat16_rn(x - __bfloat162float(hx)),
                           __float2bfloat16_rn(y - __bfloat162float(hy)));
}
__device__ __forceinline__ uint32_t bfpack_hi(float x, float y) {
    __nv_bfloat162 h = __floats2bfloat162_rn(x, y);
    return *(uint32_t*)&h;
}
__device__ __forceinline__ uint32_t bfpack_lo(float x, float y) {
    float rx = __bfloat162float(__float2bfloat16_rn(x));
    float ry = __bfloat162float(__float2bfloat16_rn(y));
    __nv_bfloat162 l = __floats2bfloat162_rn(x - rx, y - ry);
    return *(uint32_t*)&l;
}
__device__ __forceinline__ uint32_t smem_u32(const void* p) {
    uint32_t a;
    asm("{ .reg .u64 t; cvta.to.shared.u64 t, %1; cvt.u32.u64 %0, t; }" : "=r"(a) : "l"(p));
    return a;
}
__device__ __forceinline__ void ldsm_x2(uint32_t& r0, uint32_t& r1, uint32_t addr) {
    asm volatile("ldmatrix.sync.aligned.m8n8.x2.shared.b16 {%0,%1}, [%2];"
        : "=r"(r0), "=r"(r1) : "r"(addr));
}
__device__ __forceinline__ void ldsm_x2t(uint32_t& r0, uint32_t& r1, uint32_t addr) {
    asm volatile("ldmatrix.sync.aligned.m8n8.x2.trans.shared.b16 {%0,%1}, [%2];"
        : "=r"(r0), "=r"(r1) : "r"(addr));
}
__device__ __forceinline__ void mma16816(float* d, const uint32_t* a, uint32_t b0, uint32_t b1) {
    asm volatile("mma.sync.aligned.m16n8k16.row.col.f32.bf16.bf16.f32 "
        "{%0,%1,%2,%3}, {%4,%5,%6,%7}, {%8,%9}, {%0,%1,%2,%3};"
        : "+f"(d[0]), "+f"(d[1]), "+f"(d[2]), "+f"(d[3])
        : "r"(a[0]), "r"(a[1]), "r"(a[2]), "r"(a[3]), "r"(b0), "r"(b1));
}
__device__ __forceinline__ void cp16(uint32_t dst, const void* src) {
    asm volatile("cp.async.cg.shared.global [%0], [%1], 16;" :: "r"(dst), "l"(src));
}
#define CP_COMMIT() asm volatile("cp.async.commit_group;" ::: "memory")
#define CP_WAIT0()  asm volatile("cp.async.wait_group 0;" ::: "memory")
#define CP_WAIT1()  asm volatile("cp.async.wait_group 1;" ::: "memory")

// ---------------- rope table precompute ----------------
__global__ void rope_table()
{
    int idx = blockIdx.x * 256 + threadIdx.x;   // 8192 entries
    int tsel = idx >> 12, pos = (idx >> 4) & 255, j = idx & 15;
    int fidx; float posv;
    if (tsel == 0) { fidx = j; posv = (float)pos; }
    else {
        int h = pos >> 4, w = pos & 15;
        if (j < 8) { fidx = 2 * j;           posv = (float)h; }
        else       { fidx = 2 * (j - 8) + 1; posv = (float)w; }
    }
    float freq = __powf(10000.0f, -(float)fidx * (1.0f / 16.0f));
    float sn, cs;
    sincosf(posv * freq, &sn, &cs);
    g_ropeT[idx] = make_float2(cs, sn);
}

// ---------------- fused bf16 split of the 3 fp32 inputs ----------------
__global__ void split_all(const float* __restrict__ hidden, const float* __restrict__ W,
                          const float* __restrict__ Wo)
{
    int bid = blockIdx.x;
    const float* src;
    __nv_bfloat16 *hi, *lo;
    int rb;
    if (bid < 4096)      { src = hidden; hi = g_hh;  lo = g_hl;  rb = bid; }
    else if (bid < 4864) { src = W;      hi = g_Wh;  lo = g_Wl;  rb = bid - 4096; }
    else                 { src = Wo;     hi = g_Woh; lo = g_Wol; rb = bid - 4864; }
    size_t i = ((size_t)rb * 256 + threadIdx.x) * 4;
    float4 v = *(const float4*)(src + i);
    __nv_bfloat162 h0, l0, h1, l1;
    split2(v.x, v.y, h0, l0);
    split2(v.z, v.w, h1, l1);
    *(__nv_bfloat162*)(hi + i)     = h0;
    *(__nv_bfloat162*)(hi + i + 2) = h1;
    *(__nv_bfloat162*)(lo + i)     = l0;
    *(__nv_bfloat162*)(lo + i + 2) = l1;
}

// ---------------- cp.async double-buffered GEMM mainloop ----------------
#define GEMM_MAINLOOP(Ahi, Alo, Bhi, Blo)                                           \
    wmma::fragment<wmma::accumulator, 16, 16, 16, float> fc[4][2];                  \
    _Pragma("unroll") for (int i = 0; i < 4; i++)                                   \
        _Pragma("unroll") for (int j = 0; j < 2; j++) wmma::fill_fragment(fc[i][j], 0.f); \
    auto stage = [&](int st) {                                                      \
        int k0 = st * 32;                                                           \
        int bo = (st & 1) * 20480;                                                  \
        _Pragma("unroll") for (int i = 0; i < 8; i++) {                             \
            int c = tid + i * 256;                                                  \
            int arr = c >> 9, rem = c & 511, row = rem >> 2, seg = rem & 3;         \
            const __nv_bfloat16* src =                                              \
                (arr == 0) ? Ahi + (size_t)(m0 + row) * 512 + k0 + seg * 8 :        \
                (arr == 1) ? Alo + (size_t)(m0 + row) * 512 + k0 + seg * 8 :        \
                (arr == 2) ? Bhi + (size_t)(n0 + row) * 512 + k0 + seg * 8 :        \
                             Blo + (size_t)(n0 + row) * 512 + k0 + seg * 8;         \
            cp16(smem_u32(smp + bo + arr * 5120 + row * 40 + seg * 8), src);        \
        }                                                                           \
        CP_COMMIT();                                                                \
    };                                                                              \
    stage(0);                                                                       \
    for (int st = 0; st < 16; st++) {                                               \
        CP_WAIT0();                                                                 \
        __syncthreads();                                                            \
        if (st + 1 < 16) stage(st + 1);                                             \
        const __nv_bfloat16* sAh = smp + (st & 1) * 20480;                          \
        const __nv_bfloat16* sAl = sAh + 5120;                                      \
        const __nv_bfloat16* sBh = sAh + 10240;                                     \
        const __nv_bfloat16* sBl = sAh + 15360;                                     \
        _Pragma("unroll") for (int ks = 0; ks < 32; ks += 16) {                     \
            wmma::fragment<wmma::matrix_a, 16, 16, 16, __nv_bfloat16, wmma::row_major> fah[4], fal[4]; \
            wmma::fragment<wmma::matrix_b, 16, 16, 16, __nv_bfloat16, wmma::col_major> fbh[2], fbl[2]; \
            _Pragma("unroll") for (int i = 0; i < 4; i++) {                         \
                wmma::load_matrix_sync(fah[i], &sAh[(wm + i * 16) * 40 + ks], 40);  \
                wmma::load_matrix_sync(fal[i], &sAl[(wm + i * 16) * 40 + ks], 40);  \
            }                                                                       \
            _Pragma("unroll") for (int j = 0; j < 2; j++) {                         \
                wmma::load_matrix_sync(fbh[j], &sBh[(wn + j * 16) * 40 + ks], 40);  \
                wmma::load_matrix_sync(fbl[j], &sBl[(wn + j * 16) * 40 + ks], 40);  \
            }                                                                       \
            _Pragma("unroll") for (int i = 0; i < 4; i++)                           \
                _Pragma("unroll") for (int j = 0; j < 2; j++) {                     \
                    wmma::mma_sync(fc[i][j], fah[i], fbh[j], fc[i][j]);             \
                    wmma::mma_sync(fc[i][j], fah[i], fbl[j], fc[i][j]);             \
                    wmma::mma_sync(fc[i][j], fal[i], fbh[j], fc[i][j]);             \
                }                                                                   \
        }                                                                           \
        __syncthreads();                                                            \
    }

static constexpr int GEMM_SMEM = 2 * 4 * 5120 * 2;  // 81920 bytes

// ---------------- big qkv GEMM with fused RoPE + reorder + bf16-split epilogue ----------------
__global__ void __launch_bounds__(256, 2) gemm_rope(
    const __nv_bfloat16* __restrict__ Ahi, const __nv_bfloat16* __restrict__ Alo,
    const __nv_bfloat16* __restrict__ Bhi, const __nv_bfloat16* __restrict__ Blo,
    const float* __restrict__ bias)
{
    extern __shared__ __align__(16) __nv_bfloat16 smp[];
    const int tid = threadIdx.x, w = tid >> 5, lane = tid & 31;
    const int m0 = blockIdx.y * 128, n0 = blockIdx.x * 128;
    const int wm = (w >> 2) * 64, wn = (w & 3) * 32;

    GEMM_MAINLOOP(Ahi, Alo, Bhi, Blo)

    float* cst = reinterpret_cast<float*>(smp) + w * 256;
    const int er = lane >> 1, ec = (lane & 1) * 8;
    #pragma unroll
    for (int i = 0; i < 4; i++)
        #pragma unroll
        for (int j = 0; j < 2; j++) {
            wmma::store_matrix_sync(cst, fc[i][j], 16, wmma::mem_row_major);
            __syncwarp();
            int gr = m0 + wm + i * 16 + er;
            int gn = n0 + wn + j * 16 + ec;
            int b = gr >> 12, s = gr & 4095;
            float v[8];
            #pragma unroll
            for (int c = 0; c < 8; c++) v[c] = cst[er * 16 + ec + c] + bias[gn + c];

            int z = gn >> 9;   // block-uniform (128 | 512)
            if (z == 2) {
                int frame = b * 8 + (s >> 9), l = s & 511;
                size_t o = ((size_t)frame * 512 + l) * 512 + (gn & 511);
                #pragma unroll
                for (int c = 0; c < 8; c += 2) {
                    __nv_bfloat162 h2, l2;
                    split2(v[c], v[c + 1], h2, l2);
                    *(__nv_bfloat162*)(g_vbh + o + c) = h2;
                    *(__nv_bfloat162*)(g_vbl + o + c) = l2;
                }
            } else {
                int frame, l;
                if (s < 2048) { frame = b * 8 + (s >> 8); l = s & 255; }
                else { int s2 = s - 2048; frame = b * 8 + (s2 >> 8); l = 256 + (s2 & 255); }
                size_t o = ((size_t)frame * 512 + l) * 512 + (gn & 511);
                __nv_bfloat16* hi = z ? g_kbh : g_qbh;
                __nv_bfloat16* lo = z ? g_kbl : g_qbl;
                int tbase = ((s >> 11) << 12) + ((s & 255) << 4);
                #pragma unroll
                for (int c = 0; c < 8; c += 2) {
                    int pj = ((gn + c) >> 1) & 15;
                    float2 tv = g_ropeT[tbase + pj];
                    float xr = v[c] * tv.x - v[c + 1] * tv.y;
                    float xi = v[c] * tv.y + v[c + 1] * tv.x;
                    __nv_bfloat162 h2, l2;
                    split2(xr, xi, h2, l2);
                    *(__nv_bfloat162*)(hi + o + c) = h2;
                    *(__nv_bfloat162*)(lo + o + c) = l2;
                }
            }
            __syncwarp();
        }
}

// ---------------- GEMM with fp32 output (out-proj) ----------------
__global__ void __launch_bounds__(256, 2) gemm_wmma(
    const __nv_bfloat16* __restrict__ Ahi, const __nv_bfloat16* __restrict__ Alo,
    const __nv_bfloat16* __restrict__ Bhi, const __nv_bfloat16* __restrict__ Blo,
    const float* __restrict__ bias, float* __restrict__ C, int N)
{
    extern __shared__ __align__(16) __nv_bfloat16 smp[];
    const int tid = threadIdx.x, w = tid >> 5, lane = tid & 31;
    const int m0 = blockIdx.y * 128, n0 = blockIdx.x * 128;
    const int wm = (w >> 2) * 64, wn = (w & 3) * 32;

    GEMM_MAINLOOP(Ahi, Alo, Bhi, Blo)

    float* cst = reinterpret_cast<float*>(smp) + w * 256;
    const int er = lane >> 1, ec = (lane & 1) * 8;
    #pragma unroll
    for (int i = 0; i < 4; i++)
        #pragma unroll
        for (int j = 0; j < 2; j++) {
            wmma::store_matrix_sync(cst, fc[i][j], 16, wmma::mem_row_major);
            __syncwarp();
            int gr = m0 + wm + i * 16 + er;
            int gn = n0 + wn + j * 16 + ec;
            float4 v0 = *(float4*)&cst[er * 16 + ec];
            float4 v1 = *(float4*)&cst[er * 16 + ec + 4];
            float4 b0 = *(const float4*)(bias + gn);
            float4 b1 = *(const float4*)(bias + gn + 4);
            v0.x += b0.x; v0.y += b0.y; v0.z += b0.z; v0.w += b0.w;
            v1.x += b1.x; v1.y += b1.y; v1.z += b1.z; v1.w += b1.w;
            float* crow = C + (size_t)gr * N + gn;
            *(float4*)crow = v0;
            *(float4*)(crow + 4) = v1;
            __syncwarp();
        }
}

// ---------------- fused second projections (z = 0:q, 1:k-padded, 2:v-padded) ----------------
__global__ void __launch_bounds__(256, 2) gemm_small(
    const __nv_bfloat16* __restrict__ qAh, const __nv_bfloat16* __restrict__ qAl,
    const __nv_bfloat16* __restrict__ kAh, const __nv_bfloat16* __restrict__ kAl,
    const __nv_bfloat16* __restrict__ vAh, const __nv_bfloat16* __restrict__ vAl,
    const __nv_bfloat16* __restrict__ Wh,  const __nv_bfloat16* __restrict__ Wl,
    const float* __restrict__ bias_all)
{
    extern __shared__ __align__(16) __nv_bfloat16 smp[];
    const int tid = threadIdx.x, w = tid >> 5, lane = tid & 31;
    const int z = blockIdx.z;
    const int m0 = blockIdx.y * 128, n0 = blockIdx.x * 128;
    const int wm = (w >> 2) * 64, wn = (w & 3) * 32;

    const __nv_bfloat16* Ahi = (z == 0) ? qAh : (z == 1) ? kAh : vAh;
    const __nv_bfloat16* Alo = (z == 0) ? qAl : (z == 1) ? kAl : vAl;
    const __nv_bfloat16* Bhi = Wh + (size_t)z * 512 * 512;
    const __nv_bfloat16* Blo = Wl + (size_t)z * 512 * 512;
    const float* bias = bias_all + z * 512;

    GEMM_MAINLOOP(Ahi, Alo, Bhi, Blo)

    float* cst = reinterpret_cast<float*>(smp) + w * 256;
    const int er = lane >> 1, ec = (lane & 1) * 8;
    // q pre-scale folds 1/sqrt(d) AND log2(e)
    const float scale = 0.17677669529663689f * 1.4426950408889634f;
    #pragma unroll
    for (int i = 0; i < 4; i++)
        #pragma unroll
        for (int j = 0; j < 2; j++) {
            wmma::store_matrix_sync(cst, fc[i][j], 16, wmma::mem_row_major);
            __syncwarp();
            int gr = m0 + wm + i * 16 + er;
            int gn = n0 + wn + j * 16 + ec;
            float v[8];
            #pragma unroll
            for (int c = 0; c < 8; c++) v[c] = cst[er * 16 + ec + c] + bias[gn + c];

            if (z == 0) {
                size_t o = (size_t)gr * 512 + gn;
                #pragma unroll
                for (int c = 0; c < 8; c += 2) {
                    __nv_bfloat162 h, l;
                    split2(v[c] * scale, v[c + 1] * scale, h, l);
                    *(__nv_bfloat162*)(g_qwh + o + c) = h;
                    *(__nv_bfloat162*)(g_qwl + o + c) = l;
                }
            } else {
                int out_r = gr + ((gr >> 12) + 1) * 1536;
                size_t o = (size_t)out_r * 512 + gn;
                __nv_bfloat16* hi = (z == 1) ? g_kph : g_vph;
                __nv_bfloat16* lo = (z == 1) ? g_kpl : g_vpl;
                #pragma unroll
                for (int c = 0; c < 8; c += 2) {
                    __nv_bfloat162 h, l;
                    split2(v[c], v[c + 1], h, l);
                    *(__nv_bfloat162*)(hi + o + c) = h;
                    *(__nv_bfloat162*)(lo + o + c) = l;
                }
            }
            __syncwarp();
        }
}

// ---------------- pad fills ----------------
__global__ void fill_pad2(const float* __restrict__ bias)
{
    int rid = blockIdx.x;          // 0..6143
    int e = threadIdx.x * 2;
    int isV = rid >= 3072;
    int r2 = isV ? rid - 3072 : rid;
    int b = r2 / 1536;
    int rem = r2 - b * 1536;
    int fp = rem >> 9, l = rem & 511;
    const float* bs = bias + (isV ? 1024 : 512);
    __nv_bfloat162 h, lo2;
    split2(bs[e], bs[e + 1], h, lo2);
    size_t o = ((size_t)(b * 11 + fp) * 512 + l) * 512 + e;
    __nv_bfloat16* hi = isV ? g_vph : g_kph;
    __nv_bfloat16* lo = isV ? g_vpl : g_kpl;
    *(__nv_bfloat162*)(hi + o) = h;
    *(__nv_bfloat162*)(lo + o) = lo2;
}

// ---------------- teK: warp-per-output ----------------
__global__ void compute_teK(const float* __restrict__ te, const float* __restrict__ W)
{
    int o = blockIdx.x * 8 + (threadIdx.x >> 5);
    int lane = threadIdx.x & 31;
    int i = o >> 9, e = o & 511;
    const float4* wk = (const float4*)(W + (size_t)(512 + e) * 512) + lane * 4;
    const float4* tr = (const float4*)(te + i * 512) + lane * 4;
    float s = 0.f;
    #pragma unroll
    for (int k = 0; k < 4; k++) {
        float4 a = tr[k], b = wk[k];
        s += a.x * b.x + a.y * b.y + a.z * b.z + a.w * b.w;
    }
    #pragma unroll
    for (int d = 16; d > 0; d >>= 1) s += __shfl_xor_sync(0xffffffffu, s, d);
    if (lane == 0) g_teK[i * 512 + e] = s;
}

// ---------------- beta: β[row][head][slot] = q_scaled · teK[slot] per head ----------------
__global__ void compute_beta()
{
    int row = blockIdx.x;
    int tid = threadIdx.x;
    int head = tid >> 3, sub = tid & 7;
    int d0 = head * 32 + sub * 4;
    float q[4];
    #pragma unroll
    for (int c = 0; c < 4; c++)
        q[c] = __bfloat162float(g_qwh[(size_t)row * 512 + d0 + c]) +
               __bfloat162float(g_qwl[(size_t)row * 512 + d0 + c]);
    float p[4];
    #pragma unroll
    for (int sl = 0; sl < 4; sl++) {
        const float* tk = g_teK + sl * 512 + d0;
        p[sl] = q[0] * tk[0] + q[1] * tk[1] + q[2] * tk[2] + q[3] * tk[3];
    }
    #pragma unroll
    for (int d = 1; d < 8; d <<= 1) {
        #pragma unroll
        for (int sl = 0; sl < 4; sl++)
            p[sl] += __shfl_xor_sync(0xffffffffu, p[sl], d);
    }
    if (sub == 0)
        *(float4*)(g_beta + (size_t)row * 64 + head * 4) = make_float4(p[0], p[1], p[2], p[3]);
}

// ---------------- tensor-core flash attention, 3-stage cp.async pipeline ----------------
// β held in SMEM (not registers) so the kernel fits 128 regs -> 2 CTAs/SM.
__global__ void __launch_bounds__(256, 2) attn_mma()
{
    const int f = blockIdx.z, head = blockIdx.y;
    const int tid = threadIdx.x, w = tid >> 5, lane = tid & 31;
    const int b = f >> 3, t = f & 7;
    const int n32 = head * 32;
    const int qblk = blockIdx.x * 256;
    const int qbase = qblk + w * 32;

    __shared__ __align__(16) __nv_bfloat16 sKV[3][4][32 * 40];
    __shared__ float sBeta[256][4];   // β for this block's 256 q-rows x 4 slots

    // load β tile (256 rows x 4 slots for this head)
    {
        int r = tid;  // 256 threads, one row each
        *(float4*)sBeta[r] = *(const float4*)(g_beta + (size_t)(f * 512 + qblk + r) * 64 + head * 4);
    }

    uint32_t Qh[2][2][4], Ql[2][2][4];
    {
        int r = lane >> 2, c = (lane & 3) * 2;
        #pragma unroll
        for (int mt = 0; mt < 2; mt++)
            #pragma unroll
            for (int kt = 0; kt < 2; kt++) {
                size_t base = (size_t)(f * 512 + qbase + mt * 16 + r) * 512 + n32 + kt * 16 + c;
                Qh[mt][kt][0] = *(const uint32_t*)(g_qwh + base);
                Qh[mt][kt][1] = *(const uint32_t*)(g_qwh + base + 8 * 512);
                Qh[mt][kt][2] = *(const uint32_t*)(g_qwh + base + 8);
                Qh[mt][kt][3] = *(const uint32_t*)(g_qwh + base + 8 * 512 + 8);
                Ql[mt][kt][0] = *(const uint32_t*)(g_qwl + base);
                Ql[mt][kt][1] = *(const uint32_t*)(g_qwl + base + 8 * 512);
                Ql[mt][kt][2] = *(const uint32_t*)(g_qwl + base + 8);
                Ql[mt][kt][3] = *(const uint32_t*)(g_qwl + base + 8 * 512 + 8);
            }
    }

    float O[2][4][4];
    float lsum[2][2] = {{0.f, 0.f}, {0.f, 0.f}};
    #pragma unroll
    for (int m = 0; m < 2; m++)
        #pragma unroll
        for (int n = 0; n < 4; n++)
            #pragma unroll
            for (int c = 0; c < 4; c++) O[m][n][c] = 0.f;

    const int idx0 = tid * 2;
    const int arr0 = idx0 >> 7;
    const int r0s = (idx0 >> 2) & 31, seg0 = idx0 & 3;
    const int r1s = ((idx0 + 1) >> 2) & 31, seg1 = (idx0 + 1) & 3;

    auto stage = [&](int cc, int buf) {
        int slot = cc >> 4, lb = (cc & 15) << 5;
        size_t prow = (size_t)(b * 11 + t + slot) * 512 + lb;
        const __nv_bfloat16* base =
            (arr0 == 0) ? g_kph + (prow * 512 + n32) :
            (arr0 == 1) ? g_kpl + (prow * 512 + n32) :
            (arr0 == 2) ? g_vph + (prow * 512 + n32) :
                          g_vpl + (prow * 512 + n32);
        cp16(smem_u32(&sKV[buf][arr0][r0s * 40 + seg0 * 8]), base + (size_t)r0s * 512 + seg0 * 8);
        cp16(smem_u32(&sKV[buf][arr0][r1s * 40 + seg1 * 8]), base + (size_t)r1s * 512 + seg1 * 8);
        CP_COMMIT();
    };

    stage(0, 0);
    stage(1, 1);

    const int rloc0 = w * 32 + (lane >> 2);   // local row for m=0,hf=0

    for (int cc = 0; cc < 64; cc++) {
        CP_WAIT1();
        __syncthreads();
        if (cc + 2 < 64) stage(cc + 2, (cc + 2) % 3); else CP_COMMIT();
        const int buf = cc % 3;
        const int slot = cc >> 4;

        // ---- S = Q @ Kp^T (3-pass split) ----
        float S[2][4][4];
        #pragma unroll
        for (int m = 0; m < 2; m++)
            #pragma unroll
            for (int n = 0; n < 4; n++)
                #pragma unroll
                for (int c = 0; c < 4; c++) S[m][n][c] = 0.f;

        #pragma unroll
        for (int kt = 0; kt < 2; kt++) {
            #pragma unroll
            for (int nt = 0; nt < 4; nt++) {
                int l = lane & 15;
                int ki = (nt * 8 + (l & 7)) * 40 + kt * 16 + (l >> 3) * 8;
                uint32_t kh0, kh1, kl0, kl1;
                ldsm_x2(kh0, kh1, smem_u32(&sKV[buf][0][ki]));
                ldsm_x2(kl0, kl1, smem_u32(&sKV[buf][1][ki]));
                #pragma unroll
                for (int m = 0; m < 2; m++) {
                    mma16816(S[m][nt], Qh[m][kt], kh0, kh1);
                    mma16816(S[m][nt], Qh[m][kt], kl0, kl1);
                    mma16816(S[m][nt], Ql[m][kt], kh0, kh1);
                }
            }
        }

        // ---- exp2(S + β) + lsum (β from SMEM, 4 LDS per chunk) ----
        #pragma unroll
        for (int m = 0; m < 2; m++) {
            float b0 = sBeta[rloc0 + m * 16][slot];
            float b1 = sBeta[rloc0 + m * 16 + 8][slot];
            #pragma unroll
            for (int n = 0; n < 4; n++) {
                S[m][n][0] = exp2f(S[m][n][0] + b0);
                S[m][n][1] = exp2f(S[m][n][1] + b0);
                S[m][n][2] = exp2f(S[m][n][2] + b1);
                S[m][n][3] = exp2f(S[m][n][3] + b1);
                lsum[m][0] += S[m][n][0] + S[m][n][1];
                lsum[m][1] += S[m][n][2] + S[m][n][3];
            }
        }

        // ---- O += P @ V (3-pass split) ----
        #pragma unroll
        for (int kt = 0; kt < 2; kt++) {
            uint32_t Ph[2][4], Pl[2][4];
            #pragma unroll
            for (int m = 0; m < 2; m++) {
                const float* s0 = S[m][2 * kt];
                const float* s1 = S[m][2 * kt + 1];
                Ph[m][0] = bfpack_hi(s0[0], s0[1]); Pl[m][0] = bfpack_lo(s0[0], s0[1]);
                Ph[m][1] = bfpack_hi(s0[2], s0[3]); Pl[m][1] = bfpack_lo(s0[2], s0[3]);
                Ph[m][2] = bfpack_hi(s1[0], s1[1]); Pl[m][2] = bfpack_lo(s1[0], s1[1]);
                Ph[m][3] = bfpack_hi(s1[2], s1[3]); Pl[m][3] = bfpack_lo(s1[2], s1[3]);
            }
            #pragma unroll
            for (int nt = 0; nt < 4; nt++) {
                int l = lane & 15;
                int vi = (kt * 16 + l) * 40 + nt * 8;
                uint32_t vh0, vh1, vl0, vl1;
                ldsm_x2t(vh0, vh1, smem_u32(&sKV[buf][2][vi]));
                ldsm_x2t(vl0, vl1, smem_u32(&sKV[buf][3][vi]));
                #pragma unroll
                for (int m = 0; m < 2; m++) {
                    mma16816(O[m][nt], Ph[m], vh0, vh1);
                    mma16816(O[m][nt], Ph[m], vl0, vl1);
                    mma16816(O[m][nt], Pl[m], vh0, vh1);
                }
            }
        }
    }

    // ---- epilogue ----
    float inv[2][2];
    #pragma unroll
    for (int m = 0; m < 2; m++)
        #pragma unroll
        for (int h = 0; h < 2; h++) {
            float s = lsum[m][h];
            s += __shfl_xor_sync(0xffffffffu, s, 1);
            s += __shfl_xor_sync(0xffffffffu, s, 2);
            inv[m][h] = 1.f / s;
        }
    #pragma unroll
    for (int m = 0; m < 2; m++) {
        int r0 = f * 512 + qbase + m * 16 + (lane >> 2);
        #pragma unroll
        for (int nt = 0; nt < 4; nt++) {
            int col = n32 + nt * 8 + (lane & 3) * 2;
            float a0 = O[m][nt][0] * inv[m][0], a1 = O[m][nt][1] * inv[m][0];
            float a2 = O[m][nt][2] * inv[m][1], a3 = O[m][nt][3] * inv[m][1];
            __nv_bfloat162 h0, l0, h1, l1;
            split2(a0, a1, h0, l0);
            split2(a2, a3, h1, l1);
            *(__nv_bfloat162*)(g_obh + (size_t)r0 * 512 + col)       = h0;
            *(__nv_bfloat162*)(g_obl + (size_t)r0 * 512 + col)       = l0;
            *(__nv_bfloat162*)(g_obh + (size_t)(r0 + 8) * 512 + col) = h1;
            *(__nv_bfloat162*)(g_obl + (size_t)(r0 + 8) * 512 + col) = l1;
        }
    }
}

// ---------------- launcher ----------------
extern "C" void kernel_launch(void* const* d_in, const int* in_sizes, int n_in,
                              void* d_out, int out_size)
{
    const float* hidden = (const float*)d_in[0];
    const float* W      = (const float*)d_in[1];
    const float* bias   = (const float*)d_in[2];
    const float* Wo     = (const float*)d_in[3];
    const float* bo     = (const float*)d_in[4];
    const float* te     = (const float*)d_in[5];
    float* out = (float*)d_out;

    __nv_bfloat16 *p_hh, *p_hl, *p_Wh, *p_Wl, *p_Woh, *p_Wol;
    __nv_bfloat16 *p_qbh, *p_qbl, *p_kbh, *p_kbl, *p_vbh, *p_vbl, *p_obh, *p_obl;
    cudaGetSymbolAddress((void**)&p_hh,  g_hh);   cudaGetSymbolAddress((void**)&p_hl,  g_hl);
    cudaGetSymbolAddress((void**)&p_Wh,  g_Wh);   cudaGetSymbolAddress((void**)&p_Wl,  g_Wl);
    cudaGetSymbolAddress((void**)&p_Woh, g_Woh);  cudaGetSymbolAddress((void**)&p_Wol, g_Wol);
    cudaGetSymbolAddress((void**)&p_qbh, g_qbh);  cudaGetSymbolAddress((void**)&p_qbl, g_qbl);
    cudaGetSymbolAddress((void**)&p_kbh, g_kbh);  cudaGetSymbolAddress((void**)&p_kbl, g_kbl);
    cudaGetSymbolAddress((void**)&p_vbh, g_vbh);  cudaGetSymbolAddress((void**)&p_vbl, g_vbl);
    cudaGetSymbolAddress((void**)&p_obh, g_obh);  cudaGetSymbolAddress((void**)&p_obl, g_obl);

    cudaFuncSetAttribute(gemm_rope,  cudaFuncAttributeMaxDynamicSharedMemorySize, GEMM_SMEM);
    cudaFuncSetAttribute(gemm_wmma,  cudaFuncAttributeMaxDynamicSharedMemorySize, GEMM_SMEM);
    cudaFuncSetAttribute(gemm_small, cudaFuncAttributeMaxDynamicSharedMemorySize, GEMM_SMEM);

    // 0) rope table + input splits + teK
    rope_table<<<32, 256>>>();
    split_all<<<5120, 256>>>(hidden, W, Wo);
    compute_teK<<<256, 256>>>(te, W);

    // 1) qkv GEMM with fused RoPE + reorder + split epilogue
    gemm_rope<<<dim3(12, 64), 256, GEMM_SMEM>>>(p_hh, p_hl, p_Wh, p_Wl, bias);

    // 2) pad fills
    fill_pad2<<<6144, 256>>>(bias);

    // 3) fused second projections
    gemm_small<<<dim3(4, 64, 3), 256, GEMM_SMEM>>>(p_qbh, p_qbl, p_kbh, p_kbl, p_vbh, p_vbl,
                                                   p_Wh, p_Wl, bias);

    // 4) beta = q_scaled · teK per (row, head, slot)
    compute_beta<<<8192, 128>>>();

    // 5) sliding-window attention (β in smem, 2 CTAs/SM)
    attn_mma<<<dim3(2, 16, 16), 256>>>();

    // 6) out = o @ Wo^T + bo
    gemm_wmma<<<dim3(4, 64), 256, GEMM_SMEM>>>(p_obh, p_obl, p_Woh, p_Wol, bo, out, 512);
}

// round 12
// speedup vs baseline: 1.1194x; 1.0334x over previous
#include <cuda_runtime.h>
#include <cuda_bf16.h>
#include <mma.h>
#include <math.h>
#include <cstdint>

using namespace nvcuda;

// ---------------- problem constants ----------------
// B=2, T=8, H=16, W=16, E=512, n_heads=16, d=32, S=4096, L2=512, WINDOW=4
// frames BT=16, padded frames per batch TPAD=11, K of all GEMMs = 512

// ---------------- device scratch ----------------
__device__ __align__(128) float g_teK[4 * 512];
__device__ __align__(128) float2 g_ropeT[2 * 256 * 16];    // cos/sin table

__device__ __align__(128) __nv_bfloat16 g_hh [8192ull * 512], g_hl [8192ull * 512];
__device__ __align__(128) __nv_bfloat16 g_Wh [1536ull * 512], g_Wl [1536ull * 512];
__device__ __align__(128) __nv_bfloat16 g_Woh[ 512ull * 512], g_Wol[ 512ull * 512];
__device__ __align__(128) __nv_bfloat16 g_qbh[8192ull * 512], g_qbl[8192ull * 512];
__device__ __align__(128) __nv_bfloat16 g_kbh[8192ull * 512], g_kbl[8192ull * 512];
__device__ __align__(128) __nv_bfloat16 g_vbh[8192ull * 512], g_vbl[8192ull * 512];
__device__ __align__(128) __nv_bfloat16 g_obh[8192ull * 512], g_obl[8192ull * 512];

// attention operands, precomputed split (windowed K — R9 design)
__device__ __align__(128) __nv_bfloat16 g_qwh[8192ull * 512], g_qwl[8192ull * 512];
__device__ __align__(128) __nv_bfloat16 g_kwh[2ull*8*4*512*512], g_kwl[2ull*8*4*512*512];
__device__ __align__(128) __nv_bfloat16 g_vph[2ull*11*512*512],  g_vpl[2ull*11*512*512];

// ---------------- helpers ----------------
__device__ __forceinline__ void split2(float x, float y,
                                       __nv_bfloat162& h, __nv_bfloat162& l) {
    __nv_bfloat16 hx = __float2bfloat16_rn(x);
    __nv_bfloat16 hy = __float2bfloat16_rn(y);
    h = __halves2bfloat162(hx, hy);
    l = __halves2bfloat162(__float2bfloat16_rn(x - __bfloat162float(hx)),
                           __float2bfloat16_rn(y - __bfloat162float(hy)));
}
__device__ __forceinline__ uint32_t bfpack_hi(float x, float y) {
    __nv_bfloat162 h = __floats2bfloat162_rn(x, y);
    return *(uint32_t*)&h;
}
__device__ __forceinline__ uint32_t bfpack_lo(float x, float y) {
    float rx = __bfloat162float(__float2bfloat16_rn(x));
    float ry = __bfloat162float(__float2bfloat16_rn(y));
    __nv_bfloat162 l = __floats2bfloat162_rn(x - rx, y - ry);
    return *(uint32_t*)&l;
}
__device__ __forceinline__ uint32_t smem_u32(const void* p) {
    uint32_t a;
    asm("{ .reg .u64 t; cvta.to.shared.u64 t, %1; cvt.u32.u64 %0, t; }" : "=r"(a) : "l"(p));
    return a;
}
__device__ __forceinline__ void ldsm_x2(uint32_t& r0, uint32_t& r1, uint32_t addr) {
    asm volatile("ldmatrix.sync.aligned.m8n8.x2.shared.b16 {%0,%1}, [%2];"
        : "=r"(r0), "=r"(r1) : "r"(addr));
}
__device__ __forceinline__ void ldsm_x2t(uint32_t& r0, uint32_t& r1, uint32_t addr) {
    asm volatile("ldmatrix.sync.aligned.m8n8.x2.trans.shared.b16 {%0,%1}, [%2];"
        : "=r"(r0), "=r"(r1) : "r"(addr));
}
__device__ __forceinline__ void mma16816(float* d, const uint32_t* a, uint32_t b0, uint32_t b1) {
    asm volatile("mma.sync.aligned.m16n8k16.row.col.f32.bf16.bf16.f32 "
        "{%0,%1,%2,%3}, {%4,%5,%6,%7}, {%8,%9}, {%0,%1,%2,%3};"
        : "+f"(d[0]), "+f"(d[1]), "+f"(d[2]), "+f"(d[3])
        : "r"(a[0]), "r"(a[1]), "r"(a[2]), "r"(a[3]), "r"(b0), "r"(b1));
}
__device__ __forceinline__ void cp16(uint32_t dst, const void* src) {
    asm volatile("cp.async.cg.shared.global [%0], [%1], 16;" :: "r"(dst), "l"(src));
}
#define CP_COMMIT() asm volatile("cp.async.commit_group;" ::: "memory")
#define CP_WAIT0()  asm volatile("cp.async.wait_group 0;" ::: "memory")
#define CP_WAIT1()  asm volatile("cp.async.wait_group 1;" ::: "memory")

// ---------------- rope table precompute (bit-identical to R9's per-element rope_cs) ----------------
__global__ void rope_table()
{
    int idx = blockIdx.x * 256 + threadIdx.x;   // 8192 entries
    int tsel = idx >> 12, pos = (idx >> 4) & 255, j = idx & 15;
    int fidx; float posv;
    if (tsel == 0) { fidx = j; posv = (float)pos; }
    else {
        int h = pos >> 4, w = pos & 15;
        if (j < 8) { fidx = 2 * j;           posv = (float)h; }
        else       { fidx = 2 * (j - 8) + 1; posv = (float)w; }
    }
    float freq = __powf(10000.0f, -(float)fidx * (1.0f / 16.0f));
    float sn, cs;
    sincosf(posv * freq, &sn, &cs);
    g_ropeT[idx] = make_float2(cs, sn);
}

// ---------------- fused bf16 split of the 3 fp32 inputs ----------------
__global__ void split_all(const float* __restrict__ hidden, const float* __restrict__ W,
                          const float* __restrict__ Wo)
{
    int bid = blockIdx.x;
    const float* src;
    __nv_bfloat16 *hi, *lo;
    int rb;
    if (bid < 4096)      { src = hidden; hi = g_hh;  lo = g_hl;  rb = bid; }
    else if (bid < 4864) { src = W;      hi = g_Wh;  lo = g_Wl;  rb = bid - 4096; }
    else                 { src = Wo;     hi = g_Woh; lo = g_Wol; rb = bid - 4864; }
    size_t i = ((size_t)rb * 256 + threadIdx.x) * 4;
    float4 v = *(const float4*)(src + i);
    __nv_bfloat162 h0, l0, h1, l1;
    split2(v.x, v.y, h0, l0);
    split2(v.z, v.w, h1, l1);
    *(__nv_bfloat162*)(hi + i)     = h0;
    *(__nv_bfloat162*)(hi + i + 2) = h1;
    *(__nv_bfloat162*)(lo + i)     = l0;
    *(__nv_bfloat162*)(lo + i + 2) = l1;
}

// ---------------- cp.async double-buffered GEMM mainloop ----------------
#define GEMM_MAINLOOP(Ahi, Alo, Bhi, Blo)                                           \
    wmma::fragment<wmma::accumulator, 16, 16, 16, float> fc[4][2];                  \
    _Pragma("unroll") for (int i = 0; i < 4; i++)                                   \
        _Pragma("unroll") for (int j = 0; j < 2; j++) wmma::fill_fragment(fc[i][j], 0.f); \
    auto stage = [&](int st) {                                                      \
        int k0 = st * 32;                                                           \
        int bo = (st & 1) * 20480;                                                  \
        _Pragma("unroll") for (int i = 0; i < 8; i++) {                             \
            int c = tid + i * 256;                                                  \
            int arr = c >> 9, rem = c & 511, row = rem >> 2, seg = rem & 3;         \
            const __nv_bfloat16* src =                                              \
                (arr == 0) ? Ahi + (size_t)(m0 + row) * 512 + k0 + seg * 8 :        \
                (arr == 1) ? Alo + (size_t)(m0 + row) * 512 + k0 + seg * 8 :        \
                (arr == 2) ? Bhi + (size_t)(n0 + row) * 512 + k0 + seg * 8 :        \
                             Blo + (size_t)(n0 + row) * 512 + k0 + seg * 8;         \
            cp16(smem_u32(smp + bo + arr * 5120 + row * 40 + seg * 8), src);        \
        }                                                                           \
        CP_COMMIT();                                                                \
    };                                                                              \
    stage(0);                                                                       \
    for (int st = 0; st < 16; st++) {                                               \
        CP_WAIT0();                                                                 \
        __syncthreads();                                                            \
        if (st + 1 < 16) stage(st + 1);                                             \
        const __nv_bfloat16* sAh = smp + (st & 1) * 20480;                          \
        const __nv_bfloat16* sAl = sAh + 5120;                                      \
        const __nv_bfloat16* sBh = sAh + 10240;                                     \
        const __nv_bfloat16* sBl = sAh + 15360;                                     \
        _Pragma("unroll") for (int ks = 0; ks < 32; ks += 16) {                     \
            wmma::fragment<wmma::matrix_a, 16, 16, 16, __nv_bfloat16, wmma::row_major> fah[4], fal[4]; \
            wmma::fragment<wmma::matrix_b, 16, 16, 16, __nv_bfloat16, wmma::col_major> fbh[2], fbl[2]; \
            _Pragma("unroll") for (int i = 0; i < 4; i++) {                         \
                wmma::load_matrix_sync(fah[i], &sAh[(wm + i * 16) * 40 + ks], 40);  \
                wmma::load_matrix_sync(fal[i], &sAl[(wm + i * 16) * 40 + ks], 40);  \
            }                                                                       \
            _Pragma("unroll") for (int j = 0; j < 2; j++) {                         \
                wmma::load_matrix_sync(fbh[j], &sBh[(wn + j * 16) * 40 + ks], 40);  \
                wmma::load_matrix_sync(fbl[j], &sBl[(wn + j * 16) * 40 + ks], 40);  \
            }                                                                       \
            _Pragma("unroll") for (int i = 0; i < 4; i++)                           \
                _Pragma("unroll") for (int j = 0; j < 2; j++) {                     \
                    wmma::mma_sync(fc[i][j], fah[i], fbh[j], fc[i][j]);             \
                    wmma::mma_sync(fc[i][j], fah[i], fbl[j], fc[i][j]);             \
                    wmma::mma_sync(fc[i][j], fal[i], fbh[j], fc[i][j]);             \
                }                                                                   \
        }                                                                           \
        __syncthreads();                                                            \
    }

static constexpr int GEMM_SMEM = 2 * 4 * 5120 * 2;  // 81920 bytes

// ---------------- big qkv GEMM with fused RoPE + reorder + bf16-split epilogue ----------------
__global__ void __launch_bounds__(256, 2) gemm_rope(
    const __nv_bfloat16* __restrict__ Ahi, const __nv_bfloat16* __restrict__ Alo,
    const __nv_bfloat16* __restrict__ Bhi, const __nv_bfloat16* __restrict__ Blo,
    const float* __restrict__ bias)
{
    extern __shared__ __align__(16) __nv_bfloat16 smp[];
    const int tid = threadIdx.x, w = tid >> 5, lane = tid & 31;
    const int m0 = blockIdx.y * 128, n0 = blockIdx.x * 128;
    const int wm = (w >> 2) * 64, wn = (w & 3) * 32;

    GEMM_MAINLOOP(Ahi, Alo, Bhi, Blo)

    float* cst = reinterpret_cast<float*>(smp) + w * 256;
    const int er = lane >> 1, ec = (lane & 1) * 8;
    #pragma unroll
    for (int i = 0; i < 4; i++)
        #pragma unroll
        for (int j = 0; j < 2; j++) {
            wmma::store_matrix_sync(cst, fc[i][j], 16, wmma::mem_row_major);
            __syncwarp();
            int gr = m0 + wm + i * 16 + er;
            int gn = n0 + wn + j * 16 + ec;
            int b = gr >> 12, s = gr & 4095;
            float v[8];
            #pragma unroll
            for (int c = 0; c < 8; c++) v[c] = cst[er * 16 + ec + c] + bias[gn + c];

            int z = gn >> 9;   // block-uniform (128 | 512)
            if (z == 2) {
                // v: straight reshape, no rope
                int frame = b * 8 + (s >> 9), l = s & 511;
                size_t o = ((size_t)frame * 512 + l) * 512 + (gn & 511);
                #pragma unroll
                for (int c = 0; c < 8; c += 2) {
                    __nv_bfloat162 h2, l2;
                    split2(v[c], v[c + 1], h2, l2);
                    *(__nv_bfloat162*)(g_vbh + o + c) = h2;
                    *(__nv_bfloat162*)(g_vbl + o + c) = l2;
                }
            } else {
                // q or k: stream reorder + rope (table lookup)
                int frame, l;
                if (s < 2048) { frame = b * 8 + (s >> 8); l = s & 255; }
                else { int s2 = s - 2048; frame = b * 8 + (s2 >> 8); l = 256 + (s2 & 255); }
                size_t o = ((size_t)frame * 512 + l) * 512 + (gn & 511);
                __nv_bfloat16* hi = z ? g_kbh : g_qbh;
                __nv_bfloat16* lo = z ? g_kbl : g_qbl;
                int tbase = ((s >> 11) << 12) + ((s & 255) << 4);
                #pragma unroll
                for (int c = 0; c < 8; c += 2) {
                    int pj = ((gn + c) >> 1) & 15;
                    float2 tv = g_ropeT[tbase + pj];
                    float xr = v[c] * tv.x - v[c + 1] * tv.y;
                    float xi = v[c] * tv.y + v[c + 1] * tv.x;
                    __nv_bfloat162 h2, l2;
                    split2(xr, xi, h2, l2);
                    *(__nv_bfloat162*)(hi + o + c) = h2;
                    *(__nv_bfloat162*)(lo + o + c) = l2;
                }
            }
            __syncwarp();
        }
}

// ---------------- GEMM with fp32 output (out-proj) ----------------
__global__ void __launch_bounds__(256, 2) gemm_wmma(
    const __nv_bfloat16* __restrict__ Ahi, const __nv_bfloat16* __restrict__ Alo,
    const __nv_bfloat16* __restrict__ Bhi, const __nv_bfloat16* __restrict__ Blo,
    const float* __restrict__ bias, float* __restrict__ C, int N)
{
    extern __shared__ __align__(16) __nv_bfloat16 smp[];
    const int tid = threadIdx.x, w = tid >> 5, lane = tid & 31;
    const int m0 = blockIdx.y * 128, n0 = blockIdx.x * 128;
    const int wm = (w >> 2) * 64, wn = (w & 3) * 32;

    GEMM_MAINLOOP(Ahi, Alo, Bhi, Blo)

    float* cst = reinterpret_cast<float*>(smp) + w * 256;
    const int er = lane >> 1, ec = (lane & 1) * 8;
    #pragma unroll
    for (int i = 0; i < 4; i++)
        #pragma unroll
        for (int j = 0; j < 2; j++) {
            wmma::store_matrix_sync(cst, fc[i][j], 16, wmma::mem_row_major);
            __syncwarp();
            int gr = m0 + wm + i * 16 + er;
            int gn = n0 + wn + j * 16 + ec;
            float4 v0 = *(float4*)&cst[er * 16 + ec];
            float4 v1 = *(float4*)&cst[er * 16 + ec + 4];
            float4 b0 = *(const float4*)(bias + gn);
            float4 b1 = *(const float4*)(bias + gn + 4);
            v0.x += b0.x; v0.y += b0.y; v0.z += b0.z; v0.w += b0.w;
            v1.x += b1.x; v1.y += b1.y; v1.z += b1.z; v1.w += b1.w;
            float* crow = C + (size_t)gr * N + gn;
            *(float4*)crow = v0;
            *(float4*)(crow + 4) = v1;
            __syncwarp();
        }
}

// ---------------- fused second projections (z = 0:q, 1:k-window, 2:v-padded) ----------------
__global__ void __launch_bounds__(256, 2) gemm_small(
    const __nv_bfloat16* __restrict__ qAh, const __nv_bfloat16* __restrict__ qAl,
    const __nv_bfloat16* __restrict__ kAh, const __nv_bfloat16* __restrict__ kAl,
    const __nv_bfloat16* __restrict__ vAh, const __nv_bfloat16* __restrict__ vAl,
    const __nv_bfloat16* __restrict__ Wh,  const __nv_bfloat16* __restrict__ Wl,
    const float* __restrict__ bias_all)
{
    extern __shared__ __align__(16) __nv_bfloat16 smp[];
    const int tid = threadIdx.x, w = tid >> 5, lane = tid & 31;
    const int z = blockIdx.z;
    const int m0 = blockIdx.y * 128, n0 = blockIdx.x * 128;
    const int wm = (w >> 2) * 64, wn = (w & 3) * 32;

    const __nv_bfloat16* Ahi = (z == 0) ? qAh : (z == 1) ? kAh : vAh;
    const __nv_bfloat16* Alo = (z == 0) ? qAl : (z == 1) ? kAl : vAl;
    const __nv_bfloat16* Bhi = Wh + (size_t)z * 512 * 512;
    const __nv_bfloat16* Blo = Wl + (size_t)z * 512 * 512;
    const float* bias = bias_all + z * 512;

    GEMM_MAINLOOP(Ahi, Alo, Bhi, Blo)

    float* cst = reinterpret_cast<float*>(smp) + w * 256;
    const int er = lane >> 1, ec = (lane & 1) * 8;
    // q pre-scale folds 1/sqrt(d) AND log2(e) (attention uses exp2)
    const float scale = 0.17677669529663689f * 1.4426950408889634f;
    #pragma unroll
    for (int i = 0; i < 4; i++)
        #pragma unroll
        for (int j = 0; j < 2; j++) {
            wmma::store_matrix_sync(cst, fc[i][j], 16, wmma::mem_row_major);
            __syncwarp();
            int gr = m0 + wm + i * 16 + er;
            int gn = n0 + wn + j * 16 + ec;
            float v[8];
            #pragma unroll
            for (int c = 0; c < 8; c++) v[c] = cst[er * 16 + ec + c] + bias[gn + c];

            if (z == 0) {
                size_t o = (size_t)gr * 512 + gn;
                #pragma unroll
                for (int c = 0; c < 8; c += 2) {
                    __nv_bfloat162 h, l;
                    split2(v[c] * scale, v[c + 1] * scale, h, l);
                    *(__nv_bfloat162*)(g_qwh + o + c) = h;
                    *(__nv_bfloat162*)(g_qwl + o + c) = l;
                }
            } else if (z == 1) {
                int b = gr >> 12, f = (gr >> 9) & 7, l = gr & 511;
                #pragma unroll
                for (int ii = 0; ii < 4; ii++) {
                    int t = f + 3 - ii;
                    if ((unsigned)t < 8u) {
                        size_t o = ((size_t)((b * 8 + t) * 4 + ii) * 512 + l) * 512 + gn;
                        const float* tek = g_teK + ii * 512 + gn;
                        #pragma unroll
                        for (int c = 0; c < 8; c += 2) {
                            __nv_bfloat162 h, lo2;
                            split2(v[c] + tek[c], v[c + 1] + tek[c + 1], h, lo2);
                            *(__nv_bfloat162*)(g_kwh + o + c) = h;
                            *(__nv_bfloat162*)(g_kwl + o + c) = lo2;
                        }
                    }
                }
            } else {
                int out_r = gr + ((gr >> 12) + 1) * 1536;
                size_t o = (size_t)out_r * 512 + gn;
                #pragma unroll
                for (int c = 0; c < 8; c += 2) {
                    __nv_bfloat162 h, l;
                    split2(v[c], v[c + 1], h, l);
                    *(__nv_bfloat162*)(g_vph + o + c) = h;
                    *(__nv_bfloat162*)(g_vpl + o + c) = l;
                }
            }
            __syncwarp();
        }
}

// ---------------- pad fills: k-window pads (bias_k + teK) and v pads (bias_v) ----------------
__global__ void fill_pad2(const float* __restrict__ bias)
{
    int rid = blockIdx.x;
    int e = threadIdx.x * 2;
    if (rid < 6144) {
        int b = rid / 3072;
        int rem = rid - b * 3072;
        int pr = rem >> 9, l = rem & 511;
        const int tt[6] = {0, 0, 1, 0, 1, 2};
        const int ii[6] = {0, 1, 0, 2, 1, 0};
        int t = tt[pr], i = ii[pr];
        float x = bias[512 + e]     + g_teK[i * 512 + e];
        float y = bias[512 + e + 1] + g_teK[i * 512 + e + 1];
        __nv_bfloat162 h, lo2;
        split2(x, y, h, lo2);
        size_t o = ((size_t)((b * 8 + t) * 4 + i) * 512 + l) * 512 + e;
        *(__nv_bfloat162*)(g_kwh + o) = h;
        *(__nv_bfloat162*)(g_kwl + o) = lo2;
    } else {
        int rid2 = rid - 6144;
        int b = rid2 / 1536;
        int rem = rid2 - b * 1536;
        int fp = rem >> 9, l = rem & 511;
        __nv_bfloat162 h, lo2;
        split2(bias[1024 + e], bias[1024 + e + 1], h, lo2);
        size_t o = ((size_t)(b * 11 + fp) * 512 + l) * 512 + e;
        *(__nv_bfloat162*)(g_vph + o) = h;
        *(__nv_bfloat162*)(g_vpl + o) = lo2;
    }
}

// ---------------- teK: warp-per-output ----------------
__global__ void compute_teK(const float* __restrict__ te, const float* __restrict__ W)
{
    int o = blockIdx.x * 8 + (threadIdx.x >> 5);
    int lane = threadIdx.x & 31;
    int i = o >> 9, e = o & 511;
    const float4* wk = (const float4*)(W + (size_t)(512 + e) * 512) + lane * 4;
    const float4* tr = (const float4*)(te + i * 512) + lane * 4;
    float s = 0.f;
    #pragma unroll
    for (int k = 0; k < 4; k++) {
        float4 a = tr[k], b = wk[k];
        s += a.x * b.x + a.y * b.y + a.z * b.z + a.w * b.w;
    }
    #pragma unroll
    for (int d = 16; d > 0; d >>= 1) s += __shfl_xor_sync(0xffffffffu, s, d);
    if (lane == 0) g_teK[i * 512 + e] = s;
}

// ---------------- tensor-core flash attention, 3-stage cp.async pipeline (R9) ----------------
__global__ void __launch_bounds__(256) attn_mma()
{
    const int f = blockIdx.z, head = blockIdx.y;
    const int tid = threadIdx.x, w = tid >> 5, lane = tid & 31;
    const int b = f >> 3, t = f & 7;
    const int n32 = head * 32;
    const int qbase = blockIdx.x * 256 + w * 32;

    __shared__ __align__(16) __nv_bfloat16 sKV[3][4][32 * 40];

    uint32_t Qh[2][2][4], Ql[2][2][4];
    {
        int r = lane >> 2, c = (lane & 3) * 2;
        #pragma unroll
        for (int mt = 0; mt < 2; mt++)
            #pragma unroll
            for (int kt = 0; kt < 2; kt++) {
                size_t base = (size_t)(f * 512 + qbase + mt * 16 + r) * 512 + n32 + kt * 16 + c;
                Qh[mt][kt][0] = *(const uint32_t*)(g_qwh + base);
                Qh[mt][kt][1] = *(const uint32_t*)(g_qwh + base + 8 * 512);
                Qh[mt][kt][2] = *(const uint32_t*)(g_qwh + base + 8);
                Qh[mt][kt][3] = *(const uint32_t*)(g_qwh + base + 8 * 512 + 8);
                Ql[mt][kt][0] = *(const uint32_t*)(g_qwl + base);
                Ql[mt][kt][1] = *(const uint32_t*)(g_qwl + base + 8 * 512);
                Ql[mt][kt][2] = *(const uint32_t*)(g_qwl + base + 8);
                Ql[mt][kt][3] = *(const uint32_t*)(g_qwl + base + 8 * 512 + 8);
            }
    }

    float O[2][4][4];
    float lsum[2][2] = {{0.f, 0.f}, {0.f, 0.f}};
    #pragma unroll
    for (int m = 0; m < 2; m++)
        #pragma unroll
        for (int n = 0; n < 4; n++)
            #pragma unroll
            for (int c = 0; c < 4; c++) O[m][n][c] = 0.f;

    const int idx0 = tid * 2;
    const int arr0 = idx0 >> 7;
    const int r0s = (idx0 >> 2) & 31, seg0 = idx0 & 3;
    const int r1s = ((idx0 + 1) >> 2) & 31, seg1 = (idx0 + 1) & 3;

    auto stage = [&](int cc, int buf) {
        int slot = cc >> 4, lb = (cc & 15) << 5;
        size_t krow = (size_t)((b * 8 + t) * 4 + slot) * 512 + lb;
        size_t vrow = (size_t)(b * 11 + t + slot) * 512 + lb;
        const __nv_bfloat16* base =
            (arr0 == 0) ? g_kwh + (krow * 512 + n32) :
            (arr0 == 1) ? g_kwl + (krow * 512 + n32) :
            (arr0 == 2) ? g_vph + (vrow * 512 + n32) :
                          g_vpl + (vrow * 512 + n32);
        cp16(smem_u32(&sKV[buf][arr0][r0s * 40 + seg0 * 8]), base + (size_t)r0s * 512 + seg0 * 8);
        cp16(smem_u32(&sKV[buf][arr0][r1s * 40 + seg1 * 8]), base + (size_t)r1s * 512 + seg1 * 8);
        CP_COMMIT();
    };

    stage(0, 0);
    stage(1, 1);

    for (int cc = 0; cc < 64; cc++) {
        CP_WAIT1();
        __syncthreads();
        if (cc + 2 < 64) stage(cc + 2, (cc + 2) % 3); else CP_COMMIT();
        const int buf = cc % 3;

        // ---- S = Q @ K^T (3-pass split) ----
        float S[2][4][4];
        #pragma unroll
        for (int m = 0; m < 2; m++)
            #pragma unroll
            for (int n = 0; n < 4; n++)
                #pragma unroll
                for (int c = 0; c < 4; c++) S[m][n][c] = 0.f;

        #pragma unroll
        for (int kt = 0; kt < 2; kt++) {
            #pragma unroll
            for (int nt = 0; nt < 4; nt++) {
                int l = lane & 15;
                int ki = (nt * 8 + (l & 7)) * 40 + kt * 16 + (l >> 3) * 8;
                uint32_t kh0, kh1, kl0, kl1;
                ldsm_x2(kh0, kh1, smem_u32(&sKV[buf][0][ki]));
                ldsm_x2(kl0, kl1, smem_u32(&sKV[buf][1][ki]));
                #pragma unroll
                for (int m = 0; m < 2; m++) {
                    mma16816(S[m][nt], Qh[m][kt], kh0, kh1);
                    mma16816(S[m][nt], Qh[m][kt], kl0, kl1);
                    mma16816(S[m][nt], Ql[m][kt], kh0, kh1);
                }
            }
        }

        // ---- exp2 + lsum ----
        #pragma unroll
        for (int m = 0; m < 2; m++)
            #pragma unroll
            for (int n = 0; n < 4; n++) {
                S[m][n][0] = exp2f(S[m][n][0]);
                S[m][n][1] = exp2f(S[m][n][1]);
                S[m][n][2] = exp2f(S[m][n][2]);
                S[m][n][3] = exp2f(S[m][n][3]);
                lsum[m][0] += S[m][n][0] + S[m][n][1];
                lsum[m][1] += S[m][n][2] + S[m][n][3];
            }

        // ---- O += P @ V (3-pass split) ----
        #pragma unroll
        for (int kt = 0; kt < 2; kt++) {
            uint32_t Ph[2][4], Pl[2][4];
            #pragma unroll
            for (int m = 0; m < 2; m++) {
                const float* s0 = S[m][2 * kt];
                const float* s1 = S[m][2 * kt + 1];
                Ph[m][0] = bfpack_hi(s0[0], s0[1]); Pl[m][0] = bfpack_lo(s0[0], s0[1]);
                Ph[m][1] = bfpack_hi(s0[2], s0[3]); Pl[m][1] = bfpack_lo(s0[2], s0[3]);
                Ph[m][2] = bfpack_hi(s1[0], s1[1]); Pl[m][2] = bfpack_lo(s1[0], s1[1]);
                Ph[m][3] = bfpack_hi(s1[2], s1[3]); Pl[m][3] = bfpack_lo(s1[2], s1[3]);
            }
            #pragma unroll
            for (int nt = 0; nt < 4; nt++) {
                int l = lane & 15;
                int vi = (kt * 16 + l) * 40 + nt * 8;
                uint32_t vh0, vh1, vl0, vl1;
                ldsm_x2t(vh0, vh1, smem_u32(&sKV[buf][2][vi]));
                ldsm_x2t(vl0, vl1, smem_u32(&sKV[buf][3][vi]));
                #pragma unroll
                for (int m = 0; m < 2; m++) {
                    mma16816(O[m][nt], Ph[m], vh0, vh1);
                    mma16816(O[m][nt], Ph[m], vl0, vl1);
                    mma16816(O[m][nt], Pl[m], vh0, vh1);
                }
            }
        }
    }

    // ---- epilogue ----
    float inv[2][2];
    #pragma unroll
    for (int m = 0; m < 2; m++)
        #pragma unroll
        for (int h = 0; h < 2; h++) {
            float s = lsum[m][h];
            s += __shfl_xor_sync(0xffffffffu, s, 1);
            s += __shfl_xor_sync(0xffffffffu, s, 2);
            inv[m][h] = 1.f / s;
        }
    #pragma unroll
    for (int m = 0; m < 2; m++) {
        int r0 = f * 512 + qbase + m * 16 + (lane >> 2);
        #pragma unroll
        for (int nt = 0; nt < 4; nt++) {
            int col = n32 + nt * 8 + (lane & 3) * 2;
            float a0 = O[m][nt][0] * inv[m][0], a1 = O[m][nt][1] * inv[m][0];
            float a2 = O[m][nt][2] * inv[m][1], a3 = O[m][nt][3] * inv[m][1];
            __nv_bfloat162 h0, l0, h1, l1;
            split2(a0, a1, h0, l0);
            split2(a2, a3, h1, l1);
            *(__nv_bfloat162*)(g_obh + (size_t)r0 * 512 + col)       = h0;
            *(__nv_bfloat162*)(g_obl + (size_t)r0 * 512 + col)       = l0;
            *(__nv_bfloat162*)(g_obh + (size_t)(r0 + 8) * 512 + col) = h1;
            *(__nv_bfloat162*)(g_obl + (size_t)(r0 + 8) * 512 + col) = l1;
        }
    }
}

// ---------------- launcher ----------------
extern "C" void kernel_launch(void* const* d_in, const int* in_sizes, int n_in,
                              void* d_out, int out_size)
{
    const float* hidden = (const float*)d_in[0];
    const float* W      = (const float*)d_in[1];
    const float* bias   = (const float*)d_in[2];
    const float* Wo     = (const float*)d_in[3];
    const float* bo     = (const float*)d_in[4];
    const float* te     = (const float*)d_in[5];
    float* out = (float*)d_out;

    __nv_bfloat16 *p_hh, *p_hl, *p_Wh, *p_Wl, *p_Woh, *p_Wol;
    __nv_bfloat16 *p_qbh, *p_qbl, *p_kbh, *p_kbl, *p_vbh, *p_vbl, *p_obh, *p_obl;
    cudaGetSymbolAddress((void**)&p_hh,  g_hh);   cudaGetSymbolAddress((void**)&p_hl,  g_hl);
    cudaGetSymbolAddress((void**)&p_Wh,  g_Wh);   cudaGetSymbolAddress((void**)&p_Wl,  g_Wl);
    cudaGetSymbolAddress((void**)&p_Woh, g_Woh);  cudaGetSymbolAddress((void**)&p_Wol, g_Wol);
    cudaGetSymbolAddress((void**)&p_qbh, g_qbh);  cudaGetSymbolAddress((void**)&p_qbl, g_qbl);
    cudaGetSymbolAddress((void**)&p_kbh, g_kbh);  cudaGetSymbolAddress((void**)&p_kbl, g_kbl);
    cudaGetSymbolAddress((void**)&p_vbh, g_vbh);  cudaGetSymbolAddress((void**)&p_vbl, g_vbl);
    cudaGetSymbolAddress((void**)&p_obh, g_obh);  cudaGetSymbolAddress((void**)&p_obl, g_obl);

    cudaFuncSetAttribute(gemm_rope,  cudaFuncAttributeMaxDynamicSharedMemorySize, GEMM_SMEM);
    cudaFuncSetAttribute(gemm_wmma,  cudaFuncAttributeMaxDynamicSharedMemorySize, GEMM_SMEM);
    cudaFuncSetAttribute(gemm_small, cudaFuncAttributeMaxDynamicSharedMemorySize, GEMM_SMEM);

    // 0) rope table + input splits + teK
    rope_table<<<32, 256>>>();
    split_all<<<5120, 256>>>(hidden, W, Wo);
    compute_teK<<<256, 256>>>(te, W);

    // 1) qkv GEMM with fused RoPE + reorder + split epilogue (table-driven rope)
    gemm_rope<<<dim3(12, 64), 256, GEMM_SMEM>>>(p_hh, p_hl, p_Wh, p_Wl, bias);

    // 2) pad fills
    fill_pad2<<<6144 + 3072, 256>>>(bias);

    // 3) fused second projections (windowed-k fan-out, R9 design)
    gemm_small<<<dim3(4, 64, 3), 256, GEMM_SMEM>>>(p_qbh, p_qbl, p_kbh, p_kbl, p_vbh, p_vbl,
                                                   p_Wh, p_Wl, bias);

    // 4) sliding-window attention
    attn_mma<<<dim3(2, 16, 16), 256>>>();

    // 5) out = o @ Wo^T + bo
    gemm_wmma<<<dim3(4, 64), 256, GEMM_SMEM>>>(p_obh, p_obl, p_Woh, p_Wol, bo, out, 512);
}

// round 13
// speedup vs baseline: 1.2791x; 1.1426x over previous
#include <cuda_runtime.h>
#include <cuda_bf16.h>
#include <cuda_fp16.h>
#include <mma.h>
#include <math.h>
#include <cstdint>

using namespace nvcuda;

// ---------------- problem constants ----------------
// B=2, T=8, H=16, W=16, E=512, n_heads=16, d=32, S=4096, L2=512, WINDOW=4
// frames BT=16, padded frames per batch TPAD=11, K of all GEMMs = 512

// ---------------- device scratch ----------------
__device__ __align__(128) float g_teK[4 * 512];
__device__ __align__(128) float2 g_ropeT[2 * 256 * 16];    // cos/sin table

__device__ __align__(128) __nv_bfloat16 g_hh [8192ull * 512], g_hl [8192ull * 512];
__device__ __align__(128) __nv_bfloat16 g_Wh [1536ull * 512], g_Wl [1536ull * 512];
__device__ __align__(128) __nv_bfloat16 g_Woh[ 512ull * 512], g_Wol[ 512ull * 512];
__device__ __align__(128) __nv_bfloat16 g_qbh[8192ull * 512], g_qbl[8192ull * 512];
__device__ __align__(128) __nv_bfloat16 g_kbh[8192ull * 512], g_kbl[8192ull * 512];
__device__ __align__(128) __nv_bfloat16 g_vbh[8192ull * 512], g_vbl[8192ull * 512];
__device__ __align__(128) __nv_bfloat16 g_obh[8192ull * 512], g_obl[8192ull * 512];

// attention operands: fp16 (Q single, K/V hi+lo), windowed K
__device__ __align__(128) __half g_qw [8192ull * 512];
__device__ __align__(128) __half g_kwh[2ull*8*4*512*512], g_kwl[2ull*8*4*512*512];
__device__ __align__(128) __half g_vph[2ull*11*512*512],  g_vpl[2ull*11*512*512];

// ---------------- helpers ----------------
__device__ __forceinline__ void split2(float x, float y,
                                       __nv_bfloat162& h, __nv_bfloat162& l) {
    __nv_bfloat16 hx = __float2bfloat16_rn(x);
    __nv_bfloat16 hy = __float2bfloat16_rn(y);
    h = __halves2bfloat162(hx, hy);
    l = __halves2bfloat162(__float2bfloat16_rn(x - __bfloat162float(hx)),
                           __float2bfloat16_rn(y - __bfloat162float(hy)));
}
__device__ __forceinline__ void split2h(float x, float y, __half2& h, __half2& l) {
    __half hx = __float2half_rn(x);
    __half hy = __float2half_rn(y);
    h = __halves2half2(hx, hy);
    l = __halves2half2(__float2half_rn(x - __half2float(hx)),
                       __float2half_rn(y - __half2float(hy)));
}
__device__ __forceinline__ uint32_t hpack(float x, float y) {
    __half2 h = __floats2half2_rn(x, y);
    return *(uint32_t*)&h;
}
__device__ __forceinline__ uint32_t smem_u32(const void* p) {
    uint32_t a;
    asm("{ .reg .u64 t; cvta.to.shared.u64 t, %1; cvt.u32.u64 %0, t; }" : "=r"(a) : "l"(p));
    return a;
}
__device__ __forceinline__ void ldsm_x2(uint32_t& r0, uint32_t& r1, uint32_t addr) {
    asm volatile("ldmatrix.sync.aligned.m8n8.x2.shared.b16 {%0,%1}, [%2];"
        : "=r"(r0), "=r"(r1) : "r"(addr));
}
__device__ __forceinline__ void ldsm_x2t(uint32_t& r0, uint32_t& r1, uint32_t addr) {
    asm volatile("ldmatrix.sync.aligned.m8n8.x2.trans.shared.b16 {%0,%1}, [%2];"
        : "=r"(r0), "=r"(r1) : "r"(addr));
}
__device__ __forceinline__ void mma16816h(float* d, const uint32_t* a, uint32_t b0, uint32_t b1) {
    asm volatile("mma.sync.aligned.m16n8k16.row.col.f32.f16.f16.f32 "
        "{%0,%1,%2,%3}, {%4,%5,%6,%7}, {%8,%9}, {%0,%1,%2,%3};"
        : "+f"(d[0]), "+f"(d[1]), "+f"(d[2]), "+f"(d[3])
        : "r"(a[0]), "r"(a[1]), "r"(a[2]), "r"(a[3]), "r"(b0), "r"(b1));
}
__device__ __forceinline__ void cp16(uint32_t dst, const void* src) {
    asm volatile("cp.async.cg.shared.global [%0], [%1], 16;" :: "r"(dst), "l"(src));
}
#define CP_COMMIT() asm volatile("cp.async.commit_group;" ::: "memory")
#define CP_WAIT0()  asm volatile("cp.async.wait_group 0;" ::: "memory")
#define CP_WAIT1()  asm volatile("cp.async.wait_group 1;" ::: "memory")

// ---------------- rope table precompute ----------------
__global__ void rope_table()
{
    int idx = blockIdx.x * 256 + threadIdx.x;   // 8192 entries
    int tsel = idx >> 12, pos = (idx >> 4) & 255, j = idx & 15;
    int fidx; float posv;
    if (tsel == 0) { fidx = j; posv = (float)pos; }
    else {
        int h = pos >> 4, w = pos & 15;
        if (j < 8) { fidx = 2 * j;           posv = (float)h; }
        else       { fidx = 2 * (j - 8) + 1; posv = (float)w; }
    }
    float freq = __powf(10000.0f, -(float)fidx * (1.0f / 16.0f));
    float sn, cs;
    sincosf(posv * freq, &sn, &cs);
    g_ropeT[idx] = make_float2(cs, sn);
}

// ---------------- fused bf16 split of the 3 fp32 inputs ----------------
__global__ void split_all(const float* __restrict__ hidden, const float* __restrict__ W,
                          const float* __restrict__ Wo)
{
    int bid = blockIdx.x;
    const float* src;
    __nv_bfloat16 *hi, *lo;
    int rb;
    if (bid < 4096)      { src = hidden; hi = g_hh;  lo = g_hl;  rb = bid; }
    else if (bid < 4864) { src = W;      hi = g_Wh;  lo = g_Wl;  rb = bid - 4096; }
    else                 { src = Wo;     hi = g_Woh; lo = g_Wol; rb = bid - 4864; }
    size_t i = ((size_t)rb * 256 + threadIdx.x) * 4;
    float4 v = *(const float4*)(src + i);
    __nv_bfloat162 h0, l0, h1, l1;
    split2(v.x, v.y, h0, l0);
    split2(v.z, v.w, h1, l1);
    *(__nv_bfloat162*)(hi + i)     = h0;
    *(__nv_bfloat162*)(hi + i + 2) = h1;
    *(__nv_bfloat162*)(lo + i)     = l0;
    *(__nv_bfloat162*)(lo + i + 2) = l1;
}

// ---------------- cp.async double-buffered GEMM mainloop (bf16 3-pass) ----------------
#define GEMM_MAINLOOP(Ahi, Alo, Bhi, Blo)                                           \
    wmma::fragment<wmma::accumulator, 16, 16, 16, float> fc[4][2];                  \
    _Pragma("unroll") for (int i = 0; i < 4; i++)                                   \
        _Pragma("unroll") for (int j = 0; j < 2; j++) wmma::fill_fragment(fc[i][j], 0.f); \
    auto stage = [&](int st) {                                                      \
        int k0 = st * 32;                                                           \
        int bo = (st & 1) * 20480;                                                  \
        _Pragma("unroll") for (int i = 0; i < 8; i++) {                             \
            int c = tid + i * 256;                                                  \
            int arr = c >> 9, rem = c & 511, row = rem >> 2, seg = rem & 3;         \
            const __nv_bfloat16* src =                                              \
                (arr == 0) ? Ahi + (size_t)(m0 + row) * 512 + k0 + seg * 8 :        \
                (arr == 1) ? Alo + (size_t)(m0 + row) * 512 + k0 + seg * 8 :        \
                (arr == 2) ? Bhi + (size_t)(n0 + row) * 512 + k0 + seg * 8 :        \
                             Blo + (size_t)(n0 + row) * 512 + k0 + seg * 8;         \
            cp16(smem_u32(smp + bo + arr * 5120 + row * 40 + seg * 8), src);        \
        }                                                                           \
        CP_COMMIT();                                                                \
    };                                                                              \
    stage(0);                                                                       \
    for (int st = 0; st < 16; st++) {                                               \
        CP_WAIT0();                                                                 \
        __syncthreads();                                                            \
        if (st + 1 < 16) stage(st + 1);                                             \
        const __nv_bfloat16* sAh = smp + (st & 1) * 20480;                          \
        const __nv_bfloat16* sAl = sAh + 5120;                                      \
        const __nv_bfloat16* sBh = sAh + 10240;                                     \
        const __nv_bfloat16* sBl = sAh + 15360;                                     \
        _Pragma("unroll") for (int ks = 0; ks < 32; ks += 16) {                     \
            wmma::fragment<wmma::matrix_a, 16, 16, 16, __nv_bfloat16, wmma::row_major> fah[4], fal[4]; \
            wmma::fragment<wmma::matrix_b, 16, 16, 16, __nv_bfloat16, wmma::col_major> fbh[2], fbl[2]; \
            _Pragma("unroll") for (int i = 0; i < 4; i++) {                         \
                wmma::load_matrix_sync(fah[i], &sAh[(wm + i * 16) * 40 + ks], 40);  \
                wmma::load_matrix_sync(fal[i], &sAl[(wm + i * 16) * 40 + ks], 40);  \
            }                                                                       \
            _Pragma("unroll") for (int j = 0; j < 2; j++) {                         \
                wmma::load_matrix_sync(fbh[j], &sBh[(wn + j * 16) * 40 + ks], 40);  \
                wmma::load_matrix_sync(fbl[j], &sBl[(wn + j * 16) * 40 + ks], 40);  \
            }                                                                       \
            _Pragma("unroll") for (int i = 0; i < 4; i++)                           \
                _Pragma("unroll") for (int j = 0; j < 2; j++) {                     \
                    wmma::mma_sync(fc[i][j], fah[i], fbh[j], fc[i][j]);             \
                    wmma::mma_sync(fc[i][j], fah[i], fbl[j], fc[i][j]);             \
                    wmma::mma_sync(fc[i][j], fal[i], fbh[j], fc[i][j]);             \
                }                                                                   \
        }                                                                           \
        __syncthreads();                                                            \
    }

static constexpr int GEMM_SMEM = 2 * 4 * 5120 * 2;  // 81920 bytes

// ---------------- big qkv GEMM with fused RoPE + reorder + bf16-split epilogue ----------------
__global__ void __launch_bounds__(256, 2) gemm_rope(
    const __nv_bfloat16* __restrict__ Ahi, const __nv_bfloat16* __restrict__ Alo,
    const __nv_bfloat16* __restrict__ Bhi, const __nv_bfloat16* __restrict__ Blo,
    const float* __restrict__ bias)
{
    extern __shared__ __align__(16) __nv_bfloat16 smp[];
    const int tid = threadIdx.x, w = tid >> 5, lane = tid & 31;
    const int m0 = blockIdx.y * 128, n0 = blockIdx.x * 128;
    const int wm = (w >> 2) * 64, wn = (w & 3) * 32;

    GEMM_MAINLOOP(Ahi, Alo, Bhi, Blo)

    float* cst = reinterpret_cast<float*>(smp) + w * 256;
    const int er = lane >> 1, ec = (lane & 1) * 8;
    #pragma unroll
    for (int i = 0; i < 4; i++)
        #pragma unroll
        for (int j = 0; j < 2; j++) {
            wmma::store_matrix_sync(cst, fc[i][j], 16, wmma::mem_row_major);
            __syncwarp();
            int gr = m0 + wm + i * 16 + er;
            int gn = n0 + wn + j * 16 + ec;
            int b = gr >> 12, s = gr & 4095;
            float v[8];
            #pragma unroll
            for (int c = 0; c < 8; c++) v[c] = cst[er * 16 + ec + c] + bias[gn + c];

            int z = gn >> 9;   // block-uniform (128 | 512)
            if (z == 2) {
                int frame = b * 8 + (s >> 9), l = s & 511;
                size_t o = ((size_t)frame * 512 + l) * 512 + (gn & 511);
                #pragma unroll
                for (int c = 0; c < 8; c += 2) {
                    __nv_bfloat162 h2, l2;
                    split2(v[c], v[c + 1], h2, l2);
                    *(__nv_bfloat162*)(g_vbh + o + c) = h2;
                    *(__nv_bfloat162*)(g_vbl + o + c) = l2;
                }
            } else {
                int frame, l;
                if (s < 2048) { frame = b * 8 + (s >> 8); l = s & 255; }
                else { int s2 = s - 2048; frame = b * 8 + (s2 >> 8); l = 256 + (s2 & 255); }
                size_t o = ((size_t)frame * 512 + l) * 512 + (gn & 511);
                __nv_bfloat16* hi = z ? g_kbh : g_qbh;
                __nv_bfloat16* lo = z ? g_kbl : g_qbl;
                int tbase = ((s >> 11) << 12) + ((s & 255) << 4);
                #pragma unroll
                for (int c = 0; c < 8; c += 2) {
                    int pj = ((gn + c) >> 1) & 15;
                    float2 tv = g_ropeT[tbase + pj];
                    float xr = v[c] * tv.x - v[c + 1] * tv.y;
                    float xi = v[c] * tv.y + v[c + 1] * tv.x;
                    __nv_bfloat162 h2, l2;
                    split2(xr, xi, h2, l2);
                    *(__nv_bfloat162*)(hi + o + c) = h2;
                    *(__nv_bfloat162*)(lo + o + c) = l2;
                }
            }
            __syncwarp();
        }
}

// ---------------- GEMM with fp32 output (out-proj) ----------------
__global__ void __launch_bounds__(256, 2) gemm_wmma(
    const __nv_bfloat16* __restrict__ Ahi, const __nv_bfloat16* __restrict__ Alo,
    const __nv_bfloat16* __restrict__ Bhi, const __nv_bfloat16* __restrict__ Blo,
    const float* __restrict__ bias, float* __restrict__ C, int N)
{
    extern __shared__ __align__(16) __nv_bfloat16 smp[];
    const int tid = threadIdx.x, w = tid >> 5, lane = tid & 31;
    const int m0 = blockIdx.y * 128, n0 = blockIdx.x * 128;
    const int wm = (w >> 2) * 64, wn = (w & 3) * 32;

    GEMM_MAINLOOP(Ahi, Alo, Bhi, Blo)

    float* cst = reinterpret_cast<float*>(smp) + w * 256;
    const int er = lane >> 1, ec = (lane & 1) * 8;
    #pragma unroll
    for (int i = 0; i < 4; i++)
        #pragma unroll
        for (int j = 0; j < 2; j++) {
            wmma::store_matrix_sync(cst, fc[i][j], 16, wmma::mem_row_major);
            __syncwarp();
            int gr = m0 + wm + i * 16 + er;
            int gn = n0 + wn + j * 16 + ec;
            float4 v0 = *(float4*)&cst[er * 16 + ec];
            float4 v1 = *(float4*)&cst[er * 16 + ec + 4];
            float4 b0 = *(const float4*)(bias + gn);
            float4 b1 = *(const float4*)(bias + gn + 4);
            v0.x += b0.x; v0.y += b0.y; v0.z += b0.z; v0.w += b0.w;
            v1.x += b1.x; v1.y += b1.y; v1.z += b1.z; v1.w += b1.w;
            float* crow = C + (size_t)gr * N + gn;
            *(float4*)crow = v0;
            *(float4*)(crow + 4) = v1;
            __syncwarp();
        }
}

// ---------------- fused second projections (z = 0:q fp16, 1:k-window fp16, 2:v-padded fp16) ----------------
__global__ void __launch_bounds__(256, 2) gemm_small(
    const __nv_bfloat16* __restrict__ qAh, const __nv_bfloat16* __restrict__ qAl,
    const __nv_bfloat16* __restrict__ kAh, const __nv_bfloat16* __restrict__ kAl,
    const __nv_bfloat16* __restrict__ vAh, const __nv_bfloat16* __restrict__ vAl,
    const __nv_bfloat16* __restrict__ Wh,  const __nv_bfloat16* __restrict__ Wl,
    const float* __restrict__ bias_all)
{
    extern __shared__ __align__(16) __nv_bfloat16 smp[];
    const int tid = threadIdx.x, w = tid >> 5, lane = tid & 31;
    const int z = blockIdx.z;
    const int m0 = blockIdx.y * 128, n0 = blockIdx.x * 128;
    const int wm = (w >> 2) * 64, wn = (w & 3) * 32;

    const __nv_bfloat16* Ahi = (z == 0) ? qAh : (z == 1) ? kAh : vAh;
    const __nv_bfloat16* Alo = (z == 0) ? qAl : (z == 1) ? kAl : vAl;
    const __nv_bfloat16* Bhi = Wh + (size_t)z * 512 * 512;
    const __nv_bfloat16* Blo = Wl + (size_t)z * 512 * 512;
    const float* bias = bias_all + z * 512;

    GEMM_MAINLOOP(Ahi, Alo, Bhi, Blo)

    float* cst = reinterpret_cast<float*>(smp) + w * 256;
    const int er = lane >> 1, ec = (lane & 1) * 8;
    // q pre-scale folds 1/sqrt(d) AND log2(e) (attention uses exp2)
    const float scale = 0.17677669529663689f * 1.4426950408889634f;
    #pragma unroll
    for (int i = 0; i < 4; i++)
        #pragma unroll
        for (int j = 0; j < 2; j++) {
            wmma::store_matrix_sync(cst, fc[i][j], 16, wmma::mem_row_major);
            __syncwarp();
            int gr = m0 + wm + i * 16 + er;
            int gn = n0 + wn + j * 16 + ec;
            float v[8];
            #pragma unroll
            for (int c = 0; c < 8; c++) v[c] = cst[er * 16 + ec + c] + bias[gn + c];

            if (z == 0) {
                // q: scale + single fp16
                size_t o = (size_t)gr * 512 + gn;
                #pragma unroll
                for (int c = 0; c < 8; c += 2)
                    *(__half2*)(g_qw + o + c) = __floats2half2_rn(v[c] * scale, v[c + 1] * scale);
            } else if (z == 1) {
                // k: windowed fan-out with teK added, fp16 hi/lo
                int b = gr >> 12, f = (gr >> 9) & 7, l = gr & 511;
                #pragma unroll
                for (int ii = 0; ii < 4; ii++) {
                    int t = f + 3 - ii;
                    if ((unsigned)t < 8u) {
                        size_t o = ((size_t)((b * 8 + t) * 4 + ii) * 512 + l) * 512 + gn;
                        const float* tek = g_teK + ii * 512 + gn;
                        #pragma unroll
                        for (int c = 0; c < 8; c += 2) {
                            __half2 h, lo2;
                            split2h(v[c] + tek[c], v[c + 1] + tek[c + 1], h, lo2);
                            *(__half2*)(g_kwh + o + c) = h;
                            *(__half2*)(g_kwl + o + c) = lo2;
                        }
                    }
                }
            } else {
                // v: padded layout, fp16 hi/lo
                int out_r = gr + ((gr >> 12) + 1) * 1536;
                size_t o = (size_t)out_r * 512 + gn;
                #pragma unroll
                for (int c = 0; c < 8; c += 2) {
                    __half2 h, lo2;
                    split2h(v[c], v[c + 1], h, lo2);
                    *(__half2*)(g_vph + o + c) = h;
                    *(__half2*)(g_vpl + o + c) = lo2;
                }
            }
            __syncwarp();
        }
}

// ---------------- pad fills: k-window pads (bias_k + teK) and v pads (bias_v), fp16 ----------------
__global__ void fill_pad2(const float* __restrict__ bias)
{
    int rid = blockIdx.x;
    int e = threadIdx.x * 2;
    if (rid < 6144) {
        int b = rid / 3072;
        int rem = rid - b * 3072;
        int pr = rem >> 9, l = rem & 511;
        const int tt[6] = {0, 0, 1, 0, 1, 2};
        const int ii[6] = {0, 1, 0, 2, 1, 0};
        int t = tt[pr], i = ii[pr];
        float x = bias[512 + e]     + g_teK[i * 512 + e];
        float y = bias[512 + e + 1] + g_teK[i * 512 + e + 1];
        __half2 h, lo2;
        split2h(x, y, h, lo2);
        size_t o = ((size_t)((b * 8 + t) * 4 + i) * 512 + l) * 512 + e;
        *(__half2*)(g_kwh + o) = h;
        *(__half2*)(g_kwl + o) = lo2;
    } else {
        int rid2 = rid - 6144;
        int b = rid2 / 1536;
        int rem = rid2 - b * 1536;
        int fp = rem >> 9, l = rem & 511;
        __half2 h, lo2;
        split2h(bias[1024 + e], bias[1024 + e + 1], h, lo2);
        size_t o = ((size_t)(b * 11 + fp) * 512 + l) * 512 + e;
        *(__half2*)(g_vph + o) = h;
        *(__half2*)(g_vpl + o) = lo2;
    }
}

// ---------------- teK: warp-per-output ----------------
__global__ void compute_teK(const float* __restrict__ te, const float* __restrict__ W)
{
    int o = blockIdx.x * 8 + (threadIdx.x >> 5);
    int lane = threadIdx.x & 31;
    int i = o >> 9, e = o & 511;
    const float4* wk = (const float4*)(W + (size_t)(512 + e) * 512) + lane * 4;
    const float4* tr = (const float4*)(te + i * 512) + lane * 4;
    float s = 0.f;
    #pragma unroll
    for (int k = 0; k < 4; k++) {
        float4 a = tr[k], b = wk[k];
        s += a.x * b.x + a.y * b.y + a.z * b.z + a.w * b.w;
    }
    #pragma unroll
    for (int d = 16; d > 0; d >>= 1) s += __shfl_xor_sync(0xffffffffu, s, d);
    if (lane == 0) g_teK[i * 512 + e] = s;
}

// ---------------- tensor-core flash attention, fp16 2-pass, 3-stage cp.async pipeline ----------------
// Q single fp16; K fp16 hi+lo (2-pass QK); V fp16 hi+lo (2-pass PV, P as fp16 hi only).
__global__ void __launch_bounds__(256) attn_mma()
{
    const int f = blockIdx.z, head = blockIdx.y;
    const int tid = threadIdx.x, w = tid >> 5, lane = tid & 31;
    const int b = f >> 3, t = f & 7;
    const int n32 = head * 32;
    const int qbase = blockIdx.x * 256 + w * 32;

    __shared__ __align__(16) __half sKV[3][4][32 * 40];

    uint32_t Qh[2][2][4];
    {
        int r = lane >> 2, c = (lane & 3) * 2;
        #pragma unroll
        for (int mt = 0; mt < 2; mt++)
            #pragma unroll
            for (int kt = 0; kt < 2; kt++) {
                size_t base = (size_t)(f * 512 + qbase + mt * 16 + r) * 512 + n32 + kt * 16 + c;
                Qh[mt][kt][0] = *(const uint32_t*)(g_qw + base);
                Qh[mt][kt][1] = *(const uint32_t*)(g_qw + base + 8 * 512);
                Qh[mt][kt][2] = *(const uint32_t*)(g_qw + base + 8);
                Qh[mt][kt][3] = *(const uint32_t*)(g_qw + base + 8 * 512 + 8);
            }
    }

    float O[2][4][4];
    float lsum[2][2] = {{0.f, 0.f}, {0.f, 0.f}};
    #pragma unroll
    for (int m = 0; m < 2; m++)
        #pragma unroll
        for (int n = 0; n < 4; n++)
            #pragma unroll
            for (int c = 0; c < 4; c++) O[m][n][c] = 0.f;

    const int idx0 = tid * 2;
    const int arr0 = idx0 >> 7;
    const int r0s = (idx0 >> 2) & 31, seg0 = idx0 & 3;
    const int r1s = ((idx0 + 1) >> 2) & 31, seg1 = (idx0 + 1) & 3;

    auto stage = [&](int cc, int buf) {
        int slot = cc >> 4, lb = (cc & 15) << 5;
        size_t krow = (size_t)((b * 8 + t) * 4 + slot) * 512 + lb;
        size_t vrow = (size_t)(b * 11 + t + slot) * 512 + lb;
        const __half* base =
            (arr0 == 0) ? g_kwh + (krow * 512 + n32) :
            (arr0 == 1) ? g_kwl + (krow * 512 + n32) :
            (arr0 == 2) ? g_vph + (vrow * 512 + n32) :
                          g_vpl + (vrow * 512 + n32);
        cp16(smem_u32(&sKV[buf][arr0][r0s * 40 + seg0 * 8]), base + (size_t)r0s * 512 + seg0 * 8);
        cp16(smem_u32(&sKV[buf][arr0][r1s * 40 + seg1 * 8]), base + (size_t)r1s * 512 + seg1 * 8);
        CP_COMMIT();
    };

    stage(0, 0);
    stage(1, 1);

    for (int cc = 0; cc < 64; cc++) {
        CP_WAIT1();
        __syncthreads();
        if (cc + 2 < 64) stage(cc + 2, (cc + 2) % 3); else CP_COMMIT();
        const int buf = cc % 3;

        // ---- S = Q @ K^T (2-pass: Qh·Kh + Qh·Kl) ----
        float S[2][4][4];
        #pragma unroll
        for (int m = 0; m < 2; m++)
            #pragma unroll
            for (int n = 0; n < 4; n++)
                #pragma unroll
                for (int c = 0; c < 4; c++) S[m][n][c] = 0.f;

        #pragma unroll
        for (int kt = 0; kt < 2; kt++) {
            #pragma unroll
            for (int nt = 0; nt < 4; nt++) {
                int l = lane & 15;
                int ki = (nt * 8 + (l & 7)) * 40 + kt * 16 + (l >> 3) * 8;
                uint32_t kh0, kh1, kl0, kl1;
                ldsm_x2(kh0, kh1, smem_u32(&sKV[buf][0][ki]));
                ldsm_x2(kl0, kl1, smem_u32(&sKV[buf][1][ki]));
                #pragma unroll
                for (int m = 0; m < 2; m++) {
                    mma16816h(S[m][nt], Qh[m][kt], kh0, kh1);
                    mma16816h(S[m][nt], Qh[m][kt], kl0, kl1);
                }
            }
        }

        // ---- exp2 + lsum ----
        #pragma unroll
        for (int m = 0; m < 2; m++)
            #pragma unroll
            for (int n = 0; n < 4; n++) {
                S[m][n][0] = exp2f(S[m][n][0]);
                S[m][n][1] = exp2f(S[m][n][1]);
                S[m][n][2] = exp2f(S[m][n][2]);
                S[m][n][3] = exp2f(S[m][n][3]);
                lsum[m][0] += S[m][n][0] + S[m][n][1];
                lsum[m][1] += S[m][n][2] + S[m][n][3];
            }

        // ---- O += P @ V (2-pass: Ph·Vh + Ph·Vl) ----
        #pragma unroll
        for (int kt = 0; kt < 2; kt++) {
            uint32_t Ph[2][4];
            #pragma unroll
            for (int m = 0; m < 2; m++) {
                const float* s0 = S[m][2 * kt];
                const float* s1 = S[m][2 * kt + 1];
                Ph[m][0] = hpack(s0[0], s0[1]);
                Ph[m][1] = hpack(s0[2], s0[3]);
                Ph[m][2] = hpack(s1[0], s1[1]);
                Ph[m][3] = hpack(s1[2], s1[3]);
            }
            #pragma unroll
            for (int nt = 0; nt < 4; nt++) {
                int l = lane & 15;
                int vi = (kt * 16 + l) * 40 + nt * 8;
                uint32_t vh0, vh1, vl0, vl1;
                ldsm_x2t(vh0, vh1, smem_u32(&sKV[buf][2][vi]));
                ldsm_x2t(vl0, vl1, smem_u32(&sKV[buf][3][vi]));
                #pragma unroll
                for (int m = 0; m < 2; m++) {
                    mma16816h(O[m][nt], Ph[m], vh0, vh1);
                    mma16816h(O[m][nt], Ph[m], vl0, vl1);
                }
            }
        }
    }

    // ---- epilogue ----
    float inv[2][2];
    #pragma unroll
    for (int m = 0; m < 2; m++)
        #pragma unroll
        for (int h = 0; h < 2; h++) {
            float s = lsum[m][h];
            s += __shfl_xor_sync(0xffffffffu, s, 1);
            s += __shfl_xor_sync(0xffffffffu, s, 2);
            inv[m][h] = 1.f / s;
        }
    #pragma unroll
    for (int m = 0; m < 2; m++) {
        int r0 = f * 512 + qbase + m * 16 + (lane >> 2);
        #pragma unroll
        for (int nt = 0; nt < 4; nt++) {
            int col = n32 + nt * 8 + (lane & 3) * 2;
            float a0 = O[m][nt][0] * inv[m][0], a1 = O[m][nt][1] * inv[m][0];
            float a2 = O[m][nt][2] * inv[m][1], a3 = O[m][nt][3] * inv[m][1];
            __nv_bfloat162 h0, l0, h1, l1;
            split2(a0, a1, h0, l0);
            split2(a2, a3, h1, l1);
            *(__nv_bfloat162*)(g_obh + (size_t)r0 * 512 + col)       = h0;
            *(__nv_bfloat162*)(g_obl + (size_t)r0 * 512 + col)       = l0;
            *(__nv_bfloat162*)(g_obh + (size_t)(r0 + 8) * 512 + col) = h1;
            *(__nv_bfloat162*)(g_obl + (size_t)(r0 + 8) * 512 + col) = l1;
        }
    }
}

// ---------------- launcher ----------------
extern "C" void kernel_launch(void* const* d_in, const int* in_sizes, int n_in,
                              void* d_out, int out_size)
{
    const float* hidden = (const float*)d_in[0];
    const float* W      = (const float*)d_in[1];
    const float* bias   = (const float*)d_in[2];
    const float* Wo     = (const float*)d_in[3];
    const float* bo     = (const float*)d_in[4];
    const float* te     = (const float*)d_in[5];
    float* out = (float*)d_out;

    __nv_bfloat16 *p_hh, *p_hl, *p_Wh, *p_Wl, *p_Woh, *p_Wol;
    __nv_bfloat16 *p_qbh, *p_qbl, *p_kbh, *p_kbl, *p_vbh, *p_vbl, *p_obh, *p_obl;
    cudaGetSymbolAddress((void**)&p_hh,  g_hh);   cudaGetSymbolAddress((void**)&p_hl,  g_hl);
    cudaGetSymbolAddress((void**)&p_Wh,  g_Wh);   cudaGetSymbolAddress((void**)&p_Wl,  g_Wl);
    cudaGetSymbolAddress((void**)&p_Woh, g_Woh);  cudaGetSymbolAddress((void**)&p_Wol, g_Wol);
    cudaGetSymbolAddress((void**)&p_qbh, g_qbh);  cudaGetSymbolAddress((void**)&p_qbl, g_qbl);
    cudaGetSymbolAddress((void**)&p_kbh, g_kbh);  cudaGetSymbolAddress((void**)&p_kbl, g_kbl);
    cudaGetSymbolAddress((void**)&p_vbh, g_vbh);  cudaGetSymbolAddress((void**)&p_vbl, g_vbl);
    cudaGetSymbolAddress((void**)&p_obh, g_obh);  cudaGetSymbolAddress((void**)&p_obl, g_obl);

    cudaFuncSetAttribute(gemm_rope,  cudaFuncAttributeMaxDynamicSharedMemorySize, GEMM_SMEM);
    cudaFuncSetAttribute(gemm_wmma,  cudaFuncAttributeMaxDynamicSharedMemorySize, GEMM_SMEM);
    cudaFuncSetAttribute(gemm_small, cudaFuncAttributeMaxDynamicSharedMemorySize, GEMM_SMEM);

    // 0) rope table + input splits + teK
    rope_table<<<32, 256>>>();
    split_all<<<5120, 256>>>(hidden, W, Wo);
    compute_teK<<<256, 256>>>(te, W);

    // 1) qkv GEMM with fused RoPE + reorder + split epilogue
    gemm_rope<<<dim3(12, 64), 256, GEMM_SMEM>>>(p_hh, p_hl, p_Wh, p_Wl, bias);

    // 2) pad fills
    fill_pad2<<<6144 + 3072, 256>>>(bias);

    // 3) fused second projections (attention operands emitted as fp16)
    gemm_small<<<dim3(4, 64, 3), 256, GEMM_SMEM>>>(p_qbh, p_qbl, p_kbh, p_kbl, p_vbh, p_vbl,
                                                   p_Wh, p_Wl, bias);

    // 4) sliding-window attention (fp16 2-pass)
    attn_mma<<<dim3(2, 16, 16), 256>>>();

    // 5) out = o @ Wo^T + bo
    gemm_wmma<<<dim3(4, 64), 256, GEMM_SMEM>>>(p_obh, p_obl, p_Woh, p_Wol, bo, out, 512);
}

// round 14
// speedup vs baseline: 1.2793x; 1.0002x over previous
#include <cuda_runtime.h>
#include <cuda_bf16.h>
#include <cuda_fp16.h>
#include <mma.h>
#include <math.h>
#include <cstdint>

using namespace nvcuda;

// ---------------- problem constants ----------------
// B=2, T=8, H=16, W=16, E=512, n_heads=16, d=32, S=4096, L2=512, WINDOW=4
// frames BT=16, padded frames per batch TPAD=11, K of all GEMMs = 512

// ---------------- device scratch ----------------
__device__ __align__(128) float g_teK[4 * 512];
__device__ __align__(128) float2 g_ropeT[2 * 256 * 16];    // cos/sin table

__device__ __align__(128) __nv_bfloat16 g_hh [8192ull * 512], g_hl [8192ull * 512];
__device__ __align__(128) __nv_bfloat16 g_Wh [1536ull * 512], g_Wl [1536ull * 512];
__device__ __align__(128) __nv_bfloat16 g_Woh[ 512ull * 512], g_Wol[ 512ull * 512];
__device__ __align__(128) __nv_bfloat16 g_qbh[8192ull * 512], g_qbl[8192ull * 512];
__device__ __align__(128) __nv_bfloat16 g_kbh[8192ull * 512], g_kbl[8192ull * 512];
__device__ __align__(128) __nv_bfloat16 g_vbh[8192ull * 512], g_vbl[8192ull * 512];
__device__ __align__(128) __nv_bfloat16 g_obh[8192ull * 512], g_obl[8192ull * 512];

// attention operands: fp16 (Q single, K/V hi+lo), windowed K
__device__ __align__(128) __half g_qw [8192ull * 512];
__device__ __align__(128) __half g_kwh[2ull*8*4*512*512], g_kwl[2ull*8*4*512*512];
__device__ __align__(128) __half g_vph[2ull*11*512*512],  g_vpl[2ull*11*512*512];

// ---------------- helpers ----------------
__device__ __forceinline__ void split2(float x, float y,
                                       __nv_bfloat162& h, __nv_bfloat162& l) {
    __nv_bfloat16 hx = __float2bfloat16_rn(x);
    __nv_bfloat16 hy = __float2bfloat16_rn(y);
    h = __halves2bfloat162(hx, hy);
    l = __halves2bfloat162(__float2bfloat16_rn(x - __bfloat162float(hx)),
                           __float2bfloat16_rn(y - __bfloat162float(hy)));
}
__device__ __forceinline__ void split2h(float x, float y, __half2& h, __half2& l) {
    __half hx = __float2half_rn(x);
    __half hy = __float2half_rn(y);
    h = __halves2half2(hx, hy);
    l = __halves2half2(__float2half_rn(x - __half2float(hx)),
                       __float2half_rn(y - __half2float(hy)));
}
__device__ __forceinline__ uint32_t hpack(float x, float y) {
    __half2 h = __floats2half2_rn(x, y);
    return *(uint32_t*)&h;
}
__device__ __forceinline__ uint32_t smem_u32(const void* p) {
    uint32_t a;
    asm("{ .reg .u64 t; cvta.to.shared.u64 t, %1; cvt.u32.u64 %0, t; }" : "=r"(a) : "l"(p));
    return a;
}
__device__ __forceinline__ void ldsm_x2(uint32_t& r0, uint32_t& r1, uint32_t addr) {
    asm volatile("ldmatrix.sync.aligned.m8n8.x2.shared.b16 {%0,%1}, [%2];"
        : "=r"(r0), "=r"(r1) : "r"(addr));
}
__device__ __forceinline__ void ldsm_x2t(uint32_t& r0, uint32_t& r1, uint32_t addr) {
    asm volatile("ldmatrix.sync.aligned.m8n8.x2.trans.shared.b16 {%0,%1}, [%2];"
        : "=r"(r0), "=r"(r1) : "r"(addr));
}
__device__ __forceinline__ void mma16816h(float* d, const uint32_t* a, uint32_t b0, uint32_t b1) {
    asm volatile("mma.sync.aligned.m16n8k16.row.col.f32.f16.f16.f32 "
        "{%0,%1,%2,%3}, {%4,%5,%6,%7}, {%8,%9}, {%0,%1,%2,%3};"
        : "+f"(d[0]), "+f"(d[1]), "+f"(d[2]), "+f"(d[3])
        : "r"(a[0]), "r"(a[1]), "r"(a[2]), "r"(a[3]), "r"(b0), "r"(b1));
}
__device__ __forceinline__ void cp16(uint32_t dst, const void* src) {
    asm volatile("cp.async.cg.shared.global [%0], [%1], 16;" :: "r"(dst), "l"(src));
}
#define CP_COMMIT() asm volatile("cp.async.commit_group;" ::: "memory")
#define CP_WAIT0()  asm volatile("cp.async.wait_group 0;" ::: "memory")
#define CP_WAIT1()  asm volatile("cp.async.wait_group 1;" ::: "memory")

// ---------------- rope table precompute ----------------
__global__ void rope_table()
{
    int idx = blockIdx.x * 256 + threadIdx.x;   // 8192 entries
    int tsel = idx >> 12, pos = (idx >> 4) & 255, j = idx & 15;
    int fidx; float posv;
    if (tsel == 0) { fidx = j; posv = (float)pos; }
    else {
        int h = pos >> 4, w = pos & 15;
        if (j < 8) { fidx = 2 * j;           posv = (float)h; }
        else       { fidx = 2 * (j - 8) + 1; posv = (float)w; }
    }
    float freq = __powf(10000.0f, -(float)fidx * (1.0f / 16.0f));
    float sn, cs;
    sincosf(posv * freq, &sn, &cs);
    g_ropeT[idx] = make_float2(cs, sn);
}

// ---------------- fused bf16 split of the 3 fp32 inputs ----------------
__global__ void split_all(const float* __restrict__ hidden, const float* __restrict__ W,
                          const float* __restrict__ Wo)
{
    int bid = blockIdx.x;
    const float* src;
    __nv_bfloat16 *hi, *lo;
    int rb;
    if (bid < 4096)      { src = hidden; hi = g_hh;  lo = g_hl;  rb = bid; }
    else if (bid < 4864) { src = W;      hi = g_Wh;  lo = g_Wl;  rb = bid - 4096; }
    else                 { src = Wo;     hi = g_Woh; lo = g_Wol; rb = bid - 4864; }
    size_t i = ((size_t)rb * 256 + threadIdx.x) * 4;
    float4 v = *(const float4*)(src + i);
    __nv_bfloat162 h0, l0, h1, l1;
    split2(v.x, v.y, h0, l0);
    split2(v.z, v.w, h1, l1);
    *(__nv_bfloat162*)(hi + i)     = h0;
    *(__nv_bfloat162*)(hi + i + 2) = h1;
    *(__nv_bfloat162*)(lo + i)     = l0;
    *(__nv_bfloat162*)(lo + i + 2) = l1;
}

// ---------------- cp.async double-buffered GEMM mainloop (bf16 3-pass) ----------------
#define GEMM_MAINLOOP(Ahi, Alo, Bhi, Blo)                                           \
    wmma::fragment<wmma::accumulator, 16, 16, 16, float> fc[4][2];                  \
    _Pragma("unroll") for (int i = 0; i < 4; i++)                                   \
        _Pragma("unroll") for (int j = 0; j < 2; j++) wmma::fill_fragment(fc[i][j], 0.f); \
    auto stage = [&](int st) {                                                      \
        int k0 = st * 32;                                                           \
        int bo = (st & 1) * 20480;                                                  \
        _Pragma("unroll") for (int i = 0; i < 8; i++) {                             \
            int c = tid + i * 256;                                                  \
            int arr = c >> 9, rem = c & 511, row = rem >> 2, seg = rem & 3;         \
            const __nv_bfloat16* src =                                              \
                (arr == 0) ? Ahi + (size_t)(m0 + row) * 512 + k0 + seg * 8 :        \
                (arr == 1) ? Alo + (size_t)(m0 + row) * 512 + k0 + seg * 8 :        \
                (arr == 2) ? Bhi + (size_t)(n0 + row) * 512 + k0 + seg * 8 :        \
                             Blo + (size_t)(n0 + row) * 512 + k0 + seg * 8;         \
            cp16(smem_u32(smp + bo + arr * 5120 + row * 40 + seg * 8), src);        \
        }                                                                           \
        CP_COMMIT();                                                                \
    };                                                                              \
    stage(0);                                                                       \
    for (int st = 0; st < 16; st++) {                                               \
        CP_WAIT0();                                                                 \
        __syncthreads();                                                            \
        if (st + 1 < 16) stage(st + 1);                                             \
        const __nv_bfloat16* sAh = smp + (st & 1) * 20480;                          \
        const __nv_bfloat16* sAl = sAh + 5120;                                      \
        const __nv_bfloat16* sBh = sAh + 10240;                                     \
        const __nv_bfloat16* sBl = sAh + 15360;                                     \
        _Pragma("unroll") for (int ks = 0; ks < 32; ks += 16) {                     \
            wmma::fragment<wmma::matrix_a, 16, 16, 16, __nv_bfloat16, wmma::row_major> fah[4], fal[4]; \
            wmma::fragment<wmma::matrix_b, 16, 16, 16, __nv_bfloat16, wmma::col_major> fbh[2], fbl[2]; \
            _Pragma("unroll") for (int i = 0; i < 4; i++) {                         \
                wmma::load_matrix_sync(fah[i], &sAh[(wm + i * 16) * 40 + ks], 40);  \
                wmma::load_matrix_sync(fal[i], &sAl[(wm + i * 16) * 40 + ks], 40);  \
            }                                                                       \
            _Pragma("unroll") for (int j = 0; j < 2; j++) {                         \
                wmma::load_matrix_sync(fbh[j], &sBh[(wn + j * 16) * 40 + ks], 40);  \
                wmma::load_matrix_sync(fbl[j], &sBl[(wn + j * 16) * 40 + ks], 40);  \
            }                                                                       \
            _Pragma("unroll") for (int i = 0; i < 4; i++)                           \
                _Pragma("unroll") for (int j = 0; j < 2; j++) {                     \
                    wmma::mma_sync(fc[i][j], fah[i], fbh[j], fc[i][j]);             \
                    wmma::mma_sync(fc[i][j], fah[i], fbl[j], fc[i][j]);             \
                    wmma::mma_sync(fc[i][j], fal[i], fbh[j], fc[i][j]);             \
                }                                                                   \
        }                                                                           \
        __syncthreads();                                                            \
    }

static constexpr int GEMM_SMEM = 2 * 4 * 5120 * 2;  // 81920 bytes

// ---------------- big qkv GEMM with fused RoPE + reorder + bf16-split epilogue ----------------
__global__ void __launch_bounds__(256, 2) gemm_rope(
    const __nv_bfloat16* __restrict__ Ahi, const __nv_bfloat16* __restrict__ Alo,
    const __nv_bfloat16* __restrict__ Bhi, const __nv_bfloat16* __restrict__ Blo,
    const float* __restrict__ bias)
{
    extern __shared__ __align__(16) __nv_bfloat16 smp[];
    const int tid = threadIdx.x, w = tid >> 5, lane = tid & 31;
    const int m0 = blockIdx.y * 128, n0 = blockIdx.x * 128;
    const int wm = (w >> 2) * 64, wn = (w & 3) * 32;

    GEMM_MAINLOOP(Ahi, Alo, Bhi, Blo)

    float* cst = reinterpret_cast<float*>(smp) + w * 256;
    const int er = lane >> 1, ec = (lane & 1) * 8;
    #pragma unroll
    for (int i = 0; i < 4; i++)
        #pragma unroll
        for (int j = 0; j < 2; j++) {
            wmma::store_matrix_sync(cst, fc[i][j], 16, wmma::mem_row_major);
            __syncwarp();
            int gr = m0 + wm + i * 16 + er;
            int gn = n0 + wn + j * 16 + ec;
            int b = gr >> 12, s = gr & 4095;
            float v[8];
            #pragma unroll
            for (int c = 0; c < 8; c++) v[c] = cst[er * 16 + ec + c] + bias[gn + c];

            int z = gn >> 9;   // block-uniform (128 | 512)
            if (z == 2) {
                int frame = b * 8 + (s >> 9), l = s & 511;
                size_t o = ((size_t)frame * 512 + l) * 512 + (gn & 511);
                #pragma unroll
                for (int c = 0; c < 8; c += 2) {
                    __nv_bfloat162 h2, l2;
                    split2(v[c], v[c + 1], h2, l2);
                    *(__nv_bfloat162*)(g_vbh + o + c) = h2;
                    *(__nv_bfloat162*)(g_vbl + o + c) = l2;
                }
            } else {
                int frame, l;
                if (s < 2048) { frame = b * 8 + (s >> 8); l = s & 255; }
                else { int s2 = s - 2048; frame = b * 8 + (s2 >> 8); l = 256 + (s2 & 255); }
                size_t o = ((size_t)frame * 512 + l) * 512 + (gn & 511);
                __nv_bfloat16* hi = z ? g_kbh : g_qbh;
                __nv_bfloat16* lo = z ? g_kbl : g_qbl;
                int tbase = ((s >> 11) << 12) + ((s & 255) << 4);
                #pragma unroll
                for (int c = 0; c < 8; c += 2) {
                    int pj = ((gn + c) >> 1) & 15;
                    float2 tv = g_ropeT[tbase + pj];
                    float xr = v[c] * tv.x - v[c + 1] * tv.y;
                    float xi = v[c] * tv.y + v[c + 1] * tv.x;
                    __nv_bfloat162 h2, l2;
                    split2(xr, xi, h2, l2);
                    *(__nv_bfloat162*)(hi + o + c) = h2;
                    *(__nv_bfloat162*)(lo + o + c) = l2;
                }
            }
            __syncwarp();
        }
}

// ---------------- GEMM with fp32 output (out-proj) ----------------
__global__ void __launch_bounds__(256, 2) gemm_wmma(
    const __nv_bfloat16* __restrict__ Ahi, const __nv_bfloat16* __restrict__ Alo,
    const __nv_bfloat16* __restrict__ Bhi, const __nv_bfloat16* __restrict__ Blo,
    const float* __restrict__ bias, float* __restrict__ C, int N)
{
    extern __shared__ __align__(16) __nv_bfloat16 smp[];
    const int tid = threadIdx.x, w = tid >> 5, lane = tid & 31;
    const int m0 = blockIdx.y * 128, n0 = blockIdx.x * 128;
    const int wm = (w >> 2) * 64, wn = (w & 3) * 32;

    GEMM_MAINLOOP(Ahi, Alo, Bhi, Blo)

    float* cst = reinterpret_cast<float*>(smp) + w * 256;
    const int er = lane >> 1, ec = (lane & 1) * 8;
    #pragma unroll
    for (int i = 0; i < 4; i++)
        #pragma unroll
        for (int j = 0; j < 2; j++) {
            wmma::store_matrix_sync(cst, fc[i][j], 16, wmma::mem_row_major);
            __syncwarp();
            int gr = m0 + wm + i * 16 + er;
            int gn = n0 + wn + j * 16 + ec;
            float4 v0 = *(float4*)&cst[er * 16 + ec];
            float4 v1 = *(float4*)&cst[er * 16 + ec + 4];
            float4 b0 = *(const float4*)(bias + gn);
            float4 b1 = *(const float4*)(bias + gn + 4);
            v0.x += b0.x; v0.y += b0.y; v0.z += b0.z; v0.w += b0.w;
            v1.x += b1.x; v1.y += b1.y; v1.z += b1.z; v1.w += b1.w;
            float* crow = C + (size_t)gr * N + gn;
            *(float4*)crow = v0;
            *(float4*)(crow + 4) = v1;
            __syncwarp();
        }
}

// ---------------- fused second projections (z = 0:q fp16, 1:k-window fp16, 2:v-padded fp16) ----------------
__global__ void __launch_bounds__(256, 2) gemm_small(
    const __nv_bfloat16* __restrict__ qAh, const __nv_bfloat16* __restrict__ qAl,
    const __nv_bfloat16* __restrict__ kAh, const __nv_bfloat16* __restrict__ kAl,
    const __nv_bfloat16* __restrict__ vAh, const __nv_bfloat16* __restrict__ vAl,
    const __nv_bfloat16* __restrict__ Wh,  const __nv_bfloat16* __restrict__ Wl,
    const float* __restrict__ bias_all)
{
    extern __shared__ __align__(16) __nv_bfloat16 smp[];
    const int tid = threadIdx.x, w = tid >> 5, lane = tid & 31;
    const int z = blockIdx.z;
    const int m0 = blockIdx.y * 128, n0 = blockIdx.x * 128;
    const int wm = (w >> 2) * 64, wn = (w & 3) * 32;

    const __nv_bfloat16* Ahi = (z == 0) ? qAh : (z == 1) ? kAh : vAh;
    const __nv_bfloat16* Alo = (z == 0) ? qAl : (z == 1) ? kAl : vAl;
    const __nv_bfloat16* Bhi = Wh + (size_t)z * 512 * 512;
    const __nv_bfloat16* Blo = Wl + (size_t)z * 512 * 512;
    const float* bias = bias_all + z * 512;

    GEMM_MAINLOOP(Ahi, Alo, Bhi, Blo)

    float* cst = reinterpret_cast<float*>(smp) + w * 256;
    const int er = lane >> 1, ec = (lane & 1) * 8;
    // q pre-scale folds 1/sqrt(d) AND log2(e) (attention uses exp2)
    const float scale = 0.17677669529663689f * 1.4426950408889634f;
    #pragma unroll
    for (int i = 0; i < 4; i++)
        #pragma unroll
        for (int j = 0; j < 2; j++) {
            wmma::store_matrix_sync(cst, fc[i][j], 16, wmma::mem_row_major);
            __syncwarp();
            int gr = m0 + wm + i * 16 + er;
            int gn = n0 + wn + j * 16 + ec;
            float v[8];
            #pragma unroll
            for (int c = 0; c < 8; c++) v[c] = cst[er * 16 + ec + c] + bias[gn + c];

            if (z == 0) {
                // q: scale + single fp16
                size_t o = (size_t)gr * 512 + gn;
                #pragma unroll
                for (int c = 0; c < 8; c += 2)
                    *(__half2*)(g_qw + o + c) = __floats2half2_rn(v[c] * scale, v[c + 1] * scale);
            } else if (z == 1) {
                // k: windowed fan-out with teK added, fp16 hi/lo
                int b = gr >> 12, f = (gr >> 9) & 7, l = gr & 511;
                #pragma unroll
                for (int ii = 0; ii < 4; ii++) {
                    int t = f + 3 - ii;
                    if ((unsigned)t < 8u) {
                        size_t o = ((size_t)((b * 8 + t) * 4 + ii) * 512 + l) * 512 + gn;
                        const float* tek = g_teK + ii * 512 + gn;
                        #pragma unroll
                        for (int c = 0; c < 8; c += 2) {
                            __half2 h, lo2;
                            split2h(v[c] + tek[c], v[c + 1] + tek[c + 1], h, lo2);
                            *(__half2*)(g_kwh + o + c) = h;
                            *(__half2*)(g_kwl + o + c) = lo2;
                        }
                    }
                }
            } else {
                // v: padded layout, fp16 hi/lo
                int out_r = gr + ((gr >> 12) + 1) * 1536;
                size_t o = (size_t)out_r * 512 + gn;
                #pragma unroll
                for (int c = 0; c < 8; c += 2) {
                    __half2 h, lo2;
                    split2h(v[c], v[c + 1], h, lo2);
                    *(__half2*)(g_vph + o + c) = h;
                    *(__half2*)(g_vpl + o + c) = lo2;
                }
            }
            __syncwarp();
        }
}

// ---------------- pad fills: k-window pads (bias_k + teK) and v pads (bias_v), fp16 ----------------
__global__ void fill_pad2(const float* __restrict__ bias)
{
    int rid = blockIdx.x;
    int e = threadIdx.x * 2;
    if (rid < 6144) {
        int b = rid / 3072;
        int rem = rid - b * 3072;
        int pr = rem >> 9, l = rem & 511;
        const int tt[6] = {0, 0, 1, 0, 1, 2};
        const int ii[6] = {0, 1, 0, 2, 1, 0};
        int t = tt[pr], i = ii[pr];
        float x = bias[512 + e]     + g_teK[i * 512 + e];
        float y = bias[512 + e + 1] + g_teK[i * 512 + e + 1];
        __half2 h, lo2;
        split2h(x, y, h, lo2);
        size_t o = ((size_t)((b * 8 + t) * 4 + i) * 512 + l) * 512 + e;
        *(__half2*)(g_kwh + o) = h;
        *(__half2*)(g_kwl + o) = lo2;
    } else {
        int rid2 = rid - 6144;
        int b = rid2 / 1536;
        int rem = rid2 - b * 1536;
        int fp = rem >> 9, l = rem & 511;
        __half2 h, lo2;
        split2h(bias[1024 + e], bias[1024 + e + 1], h, lo2);
        size_t o = ((size_t)(b * 11 + fp) * 512 + l) * 512 + e;
        *(__half2*)(g_vph + o) = h;
        *(__half2*)(g_vpl + o) = lo2;
    }
}

// ---------------- teK: warp-per-output ----------------
__global__ void compute_teK(const float* __restrict__ te, const float* __restrict__ W)
{
    int o = blockIdx.x * 8 + (threadIdx.x >> 5);
    int lane = threadIdx.x & 31;
    int i = o >> 9, e = o & 511;
    const float4* wk = (const float4*)(W + (size_t)(512 + e) * 512) + lane * 4;
    const float4* tr = (const float4*)(te + i * 512) + lane * 4;
    float s = 0.f;
    #pragma unroll
    for (int k = 0; k < 4; k++) {
        float4 a = tr[k], b = wk[k];
        s += a.x * b.x + a.y * b.y + a.z * b.z + a.w * b.w;
    }
    #pragma unroll
    for (int d = 16; d > 0; d >>= 1) s += __shfl_xor_sync(0xffffffffu, s, d);
    if (lane == 0) g_teK[i * 512 + e] = s;
}

// ---------------- tensor-core flash attention, fp16 2-pass, 3-stage cp.async pipeline ----------------
// Q single fp16; K fp16 hi+lo (2-pass QK); V fp16 hi+lo (2-pass PV, P as fp16 hi only).
__global__ void __launch_bounds__(256) attn_mma()
{
    const int f = blockIdx.z, head = blockIdx.y;
    const int tid = threadIdx.x, w = tid >> 5, lane = tid & 31;
    const int b = f >> 3, t = f & 7;
    const int n32 = head * 32;
    const int qbase = blockIdx.x * 256 + w * 32;

    __shared__ __align__(16) __half sKV[3][4][32 * 40];

    uint32_t Qh[2][2][4];
    {
        int r = lane >> 2, c = (lane & 3) * 2;
        #pragma unroll
        for (int mt = 0; mt < 2; mt++)
            #pragma unroll
            for (int kt = 0; kt < 2; kt++) {
                size_t base = (size_t)(f * 512 + qbase + mt * 16 + r) * 512 + n32 + kt * 16 + c;
                Qh[mt][kt][0] = *(const uint32_t*)(g_qw + base);
                Qh[mt][kt][1] = *(const uint32_t*)(g_qw + base + 8 * 512);
                Qh[mt][kt][2] = *(const uint32_t*)(g_qw + base + 8);
                Qh[mt][kt][3] = *(const uint32_t*)(g_qw + base + 8 * 512 + 8);
            }
    }

    float O[2][4][4];
    float lsum[2][2] = {{0.f, 0.f}, {0.f, 0.f}};
    #pragma unroll
    for (int m = 0; m < 2; m++)
        #pragma unroll
        for (int n = 0; n < 4; n++)
            #pragma unroll
            for (int c = 0; c < 4; c++) O[m][n][c] = 0.f;

    const int idx0 = tid * 2;
    const int arr0 = idx0 >> 7;
    const int r0s = (idx0 >> 2) & 31, seg0 = idx0 & 3;
    const int r1s = ((idx0 + 1) >> 2) & 31, seg1 = (idx0 + 1) & 3;

    auto stage = [&](int cc, int buf) {
        int slot = cc >> 4, lb = (cc & 15) << 5;
        size_t krow = (size_t)((b * 8 + t) * 4 + slot) * 512 + lb;
        size_t vrow = (size_t)(b * 11 + t + slot) * 512 + lb;
        const __half* base =
            (arr0 == 0) ? g_kwh + (krow * 512 + n32) :
            (arr0 == 1) ? g_kwl + (krow * 512 + n32) :
            (arr0 == 2) ? g_vph + (vrow * 512 + n32) :
                          g_vpl + (vrow * 512 + n32);
        cp16(smem_u32(&sKV[buf][arr0][r0s * 40 + seg0 * 8]), base + (size_t)r0s * 512 + seg0 * 8);
        cp16(smem_u32(&sKV[buf][arr0][r1s * 40 + seg1 * 8]), base + (size_t)r1s * 512 + seg1 * 8);
        CP_COMMIT();
    };

    stage(0, 0);
    stage(1, 1);

    for (int cc = 0; cc < 64; cc++) {
        CP_WAIT1();
        __syncthreads();
        if (cc + 2 < 64) stage(cc + 2, (cc + 2) % 3); else CP_COMMIT();
        const int buf = cc % 3;

        // ---- S = Q @ K^T (2-pass: Qh·Kh + Qh·Kl) ----
        float S[2][4][4];
        #pragma unroll
        for (int m = 0; m < 2; m++)
            #pragma unroll
            for (int n = 0; n < 4; n++)
                #pragma unroll
                for (int c = 0; c < 4; c++) S[m][n][c] = 0.f;

        #pragma unroll
        for (int kt = 0; kt < 2; kt++) {
            #pragma unroll
            for (int nt = 0; nt < 4; nt++) {
                int l = lane & 15;
                int ki = (nt * 8 + (l & 7)) * 40 + kt * 16 + (l >> 3) * 8;
                uint32_t kh0, kh1, kl0, kl1;
                ldsm_x2(kh0, kh1, smem_u32(&sKV[buf][0][ki]));
                ldsm_x2(kl0, kl1, smem_u32(&sKV[buf][1][ki]));
                #pragma unroll
                for (int m = 0; m < 2; m++) {
                    mma16816h(S[m][nt], Qh[m][kt], kh0, kh1);
                    mma16816h(S[m][nt], Qh[m][kt], kl0, kl1);
                }
            }
        }

        // ---- exp2 + lsum ----
        #pragma unroll
        for (int m = 0; m < 2; m++)
            #pragma unroll
            for (int n = 0; n < 4; n++) {
                S[m][n][0] = exp2f(S[m][n][0]);
                S[m][n][1] = exp2f(S[m][n][1]);
                S[m][n][2] = exp2f(S[m][n][2]);
                S[m][n][3] = exp2f(S[m][n][3]);
                lsum[m][0] += S[m][n][0] + S[m][n][1];
                lsum[m][1] += S[m][n][2] + S[m][n][3];
            }

        // ---- O += P @ V (2-pass: Ph·Vh + Ph·Vl) ----
        #pragma unroll
        for (int kt = 0; kt < 2; kt++) {
            uint32_t Ph[2][4];
            #pragma unroll
            for (int m = 0; m < 2; m++) {
                const float* s0 = S[m][2 * kt];
                const float* s1 = S[m][2 * kt + 1];
                Ph[m][0] = hpack(s0[0], s0[1]);
                Ph[m][1] = hpack(s0[2], s0[3]);
                Ph[m][2] = hpack(s1[0], s1[1]);
                Ph[m][3] = hpack(s1[2], s1[3]);
            }
            #pragma unroll
            for (int nt = 0; nt < 4; nt++) {
                int l = lane & 15;
                int vi = (kt * 16 + l) * 40 + nt * 8;
                uint32_t vh0, vh1, vl0, vl1;
                ldsm_x2t(vh0, vh1, smem_u32(&sKV[buf][2][vi]));
                ldsm_x2t(vl0, vl1, smem_u32(&sKV[buf][3][vi]));
                #pragma unroll
                for (int m = 0; m < 2; m++) {
                    mma16816h(O[m][nt], Ph[m], vh0, vh1);
                    mma16816h(O[m][nt], Ph[m], vl0, vl1);
                }
            }
        }
    }

    // ---- epilogue ----
    float inv[2][2];
    #pragma unroll
    for (int m = 0; m < 2; m++)
        #pragma unroll
        for (int h = 0; h < 2; h++) {
            float s = lsum[m][h];
            s += __shfl_xor_sync(0xffffffffu, s, 1);
            s += __shfl_xor_sync(0xffffffffu, s, 2);
            inv[m][h] = 1.f / s;
        }
    #pragma unroll
    for (int m = 0; m < 2; m++) {
        int r0 = f * 512 + qbase + m * 16 + (lane >> 2);
        #pragma unroll
        for (int nt = 0; nt < 4; nt++) {
            int col = n32 + nt * 8 + (lane & 3) * 2;
            float a0 = O[m][nt][0] * inv[m][0], a1 = O[m][nt][1] * inv[m][0];
            float a2 = O[m][nt][2] * inv[m][1], a3 = O[m][nt][3] * inv[m][1];
            __nv_bfloat162 h0, l0, h1, l1;
            split2(a0, a1, h0, l0);
            split2(a2, a3, h1, l1);
            *(__nv_bfloat162*)(g_obh + (size_t)r0 * 512 + col)       = h0;
            *(__nv_bfloat162*)(g_obl + (size_t)r0 * 512 + col)       = l0;
            *(__nv_bfloat162*)(g_obh + (size_t)(r0 + 8) * 512 + col) = h1;
            *(__nv_bfloat162*)(g_obl + (size_t)(r0 + 8) * 512 + col) = l1;
        }
    }
}

// ---------------- launcher ----------------
extern "C" void kernel_launch(void* const* d_in, const int* in_sizes, int n_in,
                              void* d_out, int out_size)
{
    const float* hidden = (const float*)d_in[0];
    const float* W      = (const float*)d_in[1];
    const float* bias   = (const float*)d_in[2];
    const float* Wo     = (const float*)d_in[3];
    const float* bo     = (const float*)d_in[4];
    const float* te     = (const float*)d_in[5];
    float* out = (float*)d_out;

    __nv_bfloat16 *p_hh, *p_hl, *p_Wh, *p_Wl, *p_Woh, *p_Wol;
    __nv_bfloat16 *p_qbh, *p_qbl, *p_kbh, *p_kbl, *p_vbh, *p_vbl, *p_obh, *p_obl;
    cudaGetSymbolAddress((void**)&p_hh,  g_hh);   cudaGetSymbolAddress((void**)&p_hl,  g_hl);
    cudaGetSymbolAddress((void**)&p_Wh,  g_Wh);   cudaGetSymbolAddress((void**)&p_Wl,  g_Wl);
    cudaGetSymbolAddress((void**)&p_Woh, g_Woh);  cudaGetSymbolAddress((void**)&p_Wol, g_Wol);
    cudaGetSymbolAddress((void**)&p_qbh, g_qbh);  cudaGetSymbolAddress((void**)&p_qbl, g_qbl);
    cudaGetSymbolAddress((void**)&p_kbh, g_kbh);  cudaGetSymbolAddress((void**)&p_kbl, g_kbl);
    cudaGetSymbolAddress((void**)&p_vbh, g_vbh);  cudaGetSymbolAddress((void**)&p_vbl, g_vbl);
    cudaGetSymbolAddress((void**)&p_obh, g_obh);  cudaGetSymbolAddress((void**)&p_obl, g_obl);

    cudaFuncSetAttribute(gemm_rope,  cudaFuncAttributeMaxDynamicSharedMemorySize, GEMM_SMEM);
    cudaFuncSetAttribute(gemm_wmma,  cudaFuncAttributeMaxDynamicSharedMemorySize, GEMM_SMEM);
    cudaFuncSetAttribute(gemm_small, cudaFuncAttributeMaxDynamicSharedMemorySize, GEMM_SMEM);

    // 0) rope table + input splits + teK
    rope_table<<<32, 256>>>();
    split_all<<<5120, 256>>>(hidden, W, Wo);
    compute_teK<<<256, 256>>>(te, W);

    // 1) qkv GEMM with fused RoPE + reorder + split epilogue
    gemm_rope<<<dim3(12, 64), 256, GEMM_SMEM>>>(p_hh, p_hl, p_Wh, p_Wl, bias);

    // 2) pad fills
    fill_pad2<<<6144 + 3072, 256>>>(bias);

    // 3) fused second projections (attention operands emitted as fp16)
    gemm_small<<<dim3(4, 64, 3), 256, GEMM_SMEM>>>(p_qbh, p_qbl, p_kbh, p_kbl, p_vbh, p_vbl,
                                                   p_Wh, p_Wl, bias);

    // 4) sliding-window attention (fp16 2-pass)
    attn_mma<<<dim3(2, 16, 16), 256>>>();

    // 5) out = o @ Wo^T + bo
    gemm_wmma<<<dim3(4, 64), 256, GEMM_SMEM>>>(p_obh, p_obl, p_Woh, p_Wol, bo, out, 512);
}

// round 15
// speedup vs baseline: 1.2801x; 1.0006x over previous
#include <cuda_runtime.h>
#include <cuda_bf16.h>
#include <cuda_fp16.h>
#include <mma.h>
#include <math.h>
#include <cstdint>

using namespace nvcuda;

// ---------------- problem constants ----------------
// B=2, T=8, H=16, W=16, E=512, n_heads=16, d=32, S=4096, L2=512, WINDOW=4
// frames BT=16, padded frames per batch TPAD=11, K of all GEMMs = 512

// ---------------- device scratch ----------------
__device__ __align__(128) float g_teK[4 * 512];
__device__ __align__(128) float2 g_ropeT[2 * 256 * 16];    // cos/sin table

__device__ __align__(128) __nv_bfloat16 g_hh [8192ull * 512], g_hl [8192ull * 512];
__device__ __align__(128) __nv_bfloat16 g_Wh [1536ull * 512], g_Wl [1536ull * 512];
__device__ __align__(128) __nv_bfloat16 g_Woh[ 512ull * 512], g_Wol[ 512ull * 512];
__device__ __align__(128) __nv_bfloat16 g_qbh[8192ull * 512], g_qbl[8192ull * 512];
__device__ __align__(128) __nv_bfloat16 g_kbh[8192ull * 512], g_kbl[8192ull * 512];
__device__ __align__(128) __nv_bfloat16 g_vbh[8192ull * 512], g_vbl[8192ull * 512];
__device__ __align__(128) __nv_bfloat16 g_obh[8192ull * 512], g_obl[8192ull * 512];

// attention operands: fp16 (Q single, K/V hi+lo), windowed K
__device__ __align__(128) __half g_qw [8192ull * 512];
__device__ __align__(128) __half g_kwh[2ull*8*4*512*512], g_kwl[2ull*8*4*512*512];
__device__ __align__(128) __half g_vph[2ull*11*512*512],  g_vpl[2ull*11*512*512];

// ---------------- helpers ----------------
__device__ __forceinline__ void split2(float x, float y,
                                       __nv_bfloat162& h, __nv_bfloat162& l) {
    __nv_bfloat16 hx = __float2bfloat16_rn(x);
    __nv_bfloat16 hy = __float2bfloat16_rn(y);
    h = __halves2bfloat162(hx, hy);
    l = __halves2bfloat162(__float2bfloat16_rn(x - __bfloat162float(hx)),
                           __float2bfloat16_rn(y - __bfloat162float(hy)));
}
__device__ __forceinline__ void split2h(float x, float y, __half2& h, __half2& l) {
    __half hx = __float2half_rn(x);
    __half hy = __float2half_rn(y);
    h = __halves2half2(hx, hy);
    l = __halves2half2(__float2half_rn(x - __half2float(hx)),
                       __float2half_rn(y - __half2float(hy)));
}
__device__ __forceinline__ uint32_t hpack(float x, float y) {
    __half2 h = __floats2half2_rn(x, y);
    return *(uint32_t*)&h;
}
__device__ __forceinline__ uint32_t smem_u32(const void* p) {
    uint32_t a;
    asm("{ .reg .u64 t; cvta.to.shared.u64 t, %1; cvt.u32.u64 %0, t; }" : "=r"(a) : "l"(p));
    return a;
}
__device__ __forceinline__ void ldsm_x2(uint32_t& r0, uint32_t& r1, uint32_t addr) {
    asm volatile("ldmatrix.sync.aligned.m8n8.x2.shared.b16 {%0,%1}, [%2];"
        : "=r"(r0), "=r"(r1) : "r"(addr));
}
__device__ __forceinline__ void ldsm_x2t(uint32_t& r0, uint32_t& r1, uint32_t addr) {
    asm volatile("ldmatrix.sync.aligned.m8n8.x2.trans.shared.b16 {%0,%1}, [%2];"
        : "=r"(r0), "=r"(r1) : "r"(addr));
}
__device__ __forceinline__ void mma16816h(float* d, const uint32_t* a, uint32_t b0, uint32_t b1) {
    asm volatile("mma.sync.aligned.m16n8k16.row.col.f32.f16.f16.f32 "
        "{%0,%1,%2,%3}, {%4,%5,%6,%7}, {%8,%9}, {%0,%1,%2,%3};"
        : "+f"(d[0]), "+f"(d[1]), "+f"(d[2]), "+f"(d[3])
        : "r"(a[0]), "r"(a[1]), "r"(a[2]), "r"(a[3]), "r"(b0), "r"(b1));
}
__device__ __forceinline__ void cp16(uint32_t dst, const void* src) {
    asm volatile("cp.async.cg.shared.global [%0], [%1], 16;" :: "r"(dst), "l"(src));
}
#define CP_COMMIT() asm volatile("cp.async.commit_group;" ::: "memory")
#define CP_WAIT0()  asm volatile("cp.async.wait_group 0;" ::: "memory")
#define CP_WAIT1()  asm volatile("cp.async.wait_group 1;" ::: "memory")

// ---------------- rope table precompute ----------------
__global__ void rope_table()
{
    int idx = blockIdx.x * 256 + threadIdx.x;   // 8192 entries
    int tsel = idx >> 12, pos = (idx >> 4) & 255, j = idx & 15;
    int fidx; float posv;
    if (tsel == 0) { fidx = j; posv = (float)pos; }
    else {
        int h = pos >> 4, w = pos & 15;
        if (j < 8) { fidx = 2 * j;           posv = (float)h; }
        else       { fidx = 2 * (j - 8) + 1; posv = (float)w; }
    }
    float freq = __powf(10000.0f, -(float)fidx * (1.0f / 16.0f));
    float sn, cs;
    sincosf(posv * freq, &sn, &cs);
    g_ropeT[idx] = make_float2(cs, sn);
}

// ---------------- fused bf16 split of the 3 fp32 inputs ----------------
__global__ void split_all(const float* __restrict__ hidden, const float* __restrict__ W,
                          const float* __restrict__ Wo)
{
    int bid = blockIdx.x;
    const float* src;
    __nv_bfloat16 *hi, *lo;
    int rb;
    if (bid < 4096)      { src = hidden; hi = g_hh;  lo = g_hl;  rb = bid; }
    else if (bid < 4864) { src = W;      hi = g_Wh;  lo = g_Wl;  rb = bid - 4096; }
    else                 { src = Wo;     hi = g_Woh; lo = g_Wol; rb = bid - 4864; }
    size_t i = ((size_t)rb * 256 + threadIdx.x) * 4;
    float4 v = *(const float4*)(src + i);
    __nv_bfloat162 h0, l0, h1, l1;
    split2(v.x, v.y, h0, l0);
    split2(v.z, v.w, h1, l1);
    *(__nv_bfloat162*)(hi + i)     = h0;
    *(__nv_bfloat162*)(hi + i + 2) = h1;
    *(__nv_bfloat162*)(lo + i)     = l0;
    *(__nv_bfloat162*)(lo + i + 2) = l1;
}

// ---------------- cp.async double-buffered GEMM mainloop (bf16 3-pass) ----------------
#define GEMM_MAINLOOP(Ahi, Alo, Bhi, Blo)                                           \
    wmma::fragment<wmma::accumulator, 16, 16, 16, float> fc[4][2];                  \
    _Pragma("unroll") for (int i = 0; i < 4; i++)                                   \
        _Pragma("unroll") for (int j = 0; j < 2; j++) wmma::fill_fragment(fc[i][j], 0.f); \
    auto stage = [&](int st) {                                                      \
        int k0 = st * 32;                                                           \
        int bo = (st & 1) * 20480;                                                  \
        _Pragma("unroll") for (int i = 0; i < 8; i++) {                             \
            int c = tid + i * 256;                                                  \
            int arr = c >> 9, rem = c & 511, row = rem >> 2, seg = rem & 3;         \
            const __nv_bfloat16* src =                                              \
                (arr == 0) ? Ahi + (size_t)(m0 + row) * 512 + k0 + seg * 8 :        \
                (arr == 1) ? Alo + (size_t)(m0 + row) * 512 + k0 + seg * 8 :        \
                (arr == 2) ? Bhi + (size_t)(n0 + row) * 512 + k0 + seg * 8 :        \
                             Blo + (size_t)(n0 + row) * 512 + k0 + seg * 8;         \
            cp16(smem_u32(smp + bo + arr * 5120 + row * 40 + seg * 8), src);        \
        }                                                                           \
        CP_COMMIT();                                                                \
    };                                                                              \
    stage(0);                                                                       \
    for (int st = 0; st < 16; st++) {                                               \
        CP_WAIT0();                                                                 \
        __syncthreads();                                                            \
        if (st + 1 < 16) stage(st + 1);                                             \
        const __nv_bfloat16* sAh = smp + (st & 1) * 20480;                          \
        const __nv_bfloat16* sAl = sAh + 5120;                                      \
        const __nv_bfloat16* sBh = sAh + 10240;                                     \
        const __nv_bfloat16* sBl = sAh + 15360;                                     \
        _Pragma("unroll") for (int ks = 0; ks < 32; ks += 16) {                     \
            wmma::fragment<wmma::matrix_a, 16, 16, 16, __nv_bfloat16, wmma::row_major> fah[4], fal[4]; \
            wmma::fragment<wmma::matrix_b, 16, 16, 16, __nv_bfloat16, wmma::col_major> fbh[2], fbl[2]; \
            _Pragma("unroll") for (int i = 0; i < 4; i++) {                         \
                wmma::load_matrix_sync(fah[i], &sAh[(wm + i * 16) * 40 + ks], 40);  \
                wmma::load_matrix_sync(fal[i], &sAl[(wm + i * 16) * 40 + ks], 40);  \
            }                                                                       \
            _Pragma("unroll") for (int j = 0; j < 2; j++) {                         \
                wmma::load_matrix_sync(fbh[j], &sBh[(wn + j * 16) * 40 + ks], 40);  \
                wmma::load_matrix_sync(fbl[j], &sBl[(wn + j * 16) * 40 + ks], 40);  \
            }                                                                       \
            _Pragma("unroll") for (int i = 0; i < 4; i++)                           \
                _Pragma("unroll") for (int j = 0; j < 2; j++) {                     \
                    wmma::mma_sync(fc[i][j], fah[i], fbh[j], fc[i][j]);             \
                    wmma::mma_sync(fc[i][j], fah[i], fbl[j], fc[i][j]);             \
                    wmma::mma_sync(fc[i][j], fal[i], fbh[j], fc[i][j]);             \
                }                                                                   \
        }                                                                           \
        __syncthreads();                                                            \
    }

static constexpr int GEMM_SMEM = 2 * 4 * 5120 * 2;  // 81920 bytes

// ---------------- big qkv GEMM with fused RoPE + reorder + bf16-split epilogue ----------------
__global__ void __launch_bounds__(256, 2) gemm_rope(
    const __nv_bfloat16* __restrict__ Ahi, const __nv_bfloat16* __restrict__ Alo,
    const __nv_bfloat16* __restrict__ Bhi, const __nv_bfloat16* __restrict__ Blo,
    const float* __restrict__ bias)
{
    extern __shared__ __align__(16) __nv_bfloat16 smp[];
    const int tid = threadIdx.x, w = tid >> 5, lane = tid & 31;
    const int m0 = blockIdx.y * 128, n0 = blockIdx.x * 128;
    const int wm = (w >> 2) * 64, wn = (w & 3) * 32;

    GEMM_MAINLOOP(Ahi, Alo, Bhi, Blo)

    float* cst = reinterpret_cast<float*>(smp) + w * 256;
    const int er = lane >> 1, ec = (lane & 1) * 8;
    #pragma unroll
    for (int i = 0; i < 4; i++)
        #pragma unroll
        for (int j = 0; j < 2; j++) {
            wmma::store_matrix_sync(cst, fc[i][j], 16, wmma::mem_row_major);
            __syncwarp();
            int gr = m0 + wm + i * 16 + er;
            int gn = n0 + wn + j * 16 + ec;
            int b = gr >> 12, s = gr & 4095;
            float v[8];
            #pragma unroll
            for (int c = 0; c < 8; c++) v[c] = cst[er * 16 + ec + c] + bias[gn + c];

            int z = gn >> 9;   // block-uniform (128 | 512)
            if (z == 2) {
                int frame = b * 8 + (s >> 9), l = s & 511;
                size_t o = ((size_t)frame * 512 + l) * 512 + (gn & 511);
                #pragma unroll
                for (int c = 0; c < 8; c += 2) {
                    __nv_bfloat162 h2, l2;
                    split2(v[c], v[c + 1], h2, l2);
                    *(__nv_bfloat162*)(g_vbh + o + c) = h2;
                    *(__nv_bfloat162*)(g_vbl + o + c) = l2;
                }
            } else {
                int frame, l;
                if (s < 2048) { frame = b * 8 + (s >> 8); l = s & 255; }
                else { int s2 = s - 2048; frame = b * 8 + (s2 >> 8); l = 256 + (s2 & 255); }
                size_t o = ((size_t)frame * 512 + l) * 512 + (gn & 511);
                __nv_bfloat16* hi = z ? g_kbh : g_qbh;
                __nv_bfloat16* lo = z ? g_kbl : g_qbl;
                int tbase = ((s >> 11) << 12) + ((s & 255) << 4);
                #pragma unroll
                for (int c = 0; c < 8; c += 2) {
                    int pj = ((gn + c) >> 1) & 15;
                    float2 tv = g_ropeT[tbase + pj];
                    float xr = v[c] * tv.x - v[c + 1] * tv.y;
                    float xi = v[c] * tv.y + v[c + 1] * tv.x;
                    __nv_bfloat162 h2, l2;
                    split2(xr, xi, h2, l2);
                    *(__nv_bfloat162*)(hi + o + c) = h2;
                    *(__nv_bfloat162*)(lo + o + c) = l2;
                }
            }
            __syncwarp();
        }
}

// ---------------- GEMM with fp32 output (out-proj) ----------------
__global__ void __launch_bounds__(256, 2) gemm_wmma(
    const __nv_bfloat16* __restrict__ Ahi, const __nv_bfloat16* __restrict__ Alo,
    const __nv_bfloat16* __restrict__ Bhi, const __nv_bfloat16* __restrict__ Blo,
    const float* __restrict__ bias, float* __restrict__ C, int N)
{
    extern __shared__ __align__(16) __nv_bfloat16 smp[];
    const int tid = threadIdx.x, w = tid >> 5, lane = tid & 31;
    const int m0 = blockIdx.y * 128, n0 = blockIdx.x * 128;
    const int wm = (w >> 2) * 64, wn = (w & 3) * 32;

    GEMM_MAINLOOP(Ahi, Alo, Bhi, Blo)

    float* cst = reinterpret_cast<float*>(smp) + w * 256;
    const int er = lane >> 1, ec = (lane & 1) * 8;
    #pragma unroll
    for (int i = 0; i < 4; i++)
        #pragma unroll
        for (int j = 0; j < 2; j++) {
            wmma::store_matrix_sync(cst, fc[i][j], 16, wmma::mem_row_major);
            __syncwarp();
            int gr = m0 + wm + i * 16 + er;
            int gn = n0 + wn + j * 16 + ec;
            float4 v0 = *(float4*)&cst[er * 16 + ec];
            float4 v1 = *(float4*)&cst[er * 16 + ec + 4];
            float4 b0 = *(const float4*)(bias + gn);
            float4 b1 = *(const float4*)(bias + gn + 4);
            v0.x += b0.x; v0.y += b0.y; v0.z += b0.z; v0.w += b0.w;
            v1.x += b1.x; v1.y += b1.y; v1.z += b1.z; v1.w += b1.w;
            float* crow = C + (size_t)gr * N + gn;
            *(float4*)crow = v0;
            *(float4*)(crow + 4) = v1;
            __syncwarp();
        }
}

// ---------------- fused second projections (z = 0:q fp16, 1:k-window fp16, 2:v-padded fp16) ----------------
__global__ void __launch_bounds__(256, 2) gemm_small(
    const __nv_bfloat16* __restrict__ qAh, const __nv_bfloat16* __restrict__ qAl,
    const __nv_bfloat16* __restrict__ kAh, const __nv_bfloat16* __restrict__ kAl,
    const __nv_bfloat16* __restrict__ vAh, const __nv_bfloat16* __restrict__ vAl,
    const __nv_bfloat16* __restrict__ Wh,  const __nv_bfloat16* __restrict__ Wl,
    const float* __restrict__ bias_all)
{
    extern __shared__ __align__(16) __nv_bfloat16 smp[];
    const int tid = threadIdx.x, w = tid >> 5, lane = tid & 31;
    const int z = blockIdx.z;
    const int m0 = blockIdx.y * 128, n0 = blockIdx.x * 128;
    const int wm = (w >> 2) * 64, wn = (w & 3) * 32;

    const __nv_bfloat16* Ahi = (z == 0) ? qAh : (z == 1) ? kAh : vAh;
    const __nv_bfloat16* Alo = (z == 0) ? qAl : (z == 1) ? kAl : vAl;
    const __nv_bfloat16* Bhi = Wh + (size_t)z * 512 * 512;
    const __nv_bfloat16* Blo = Wl + (size_t)z * 512 * 512;
    const float* bias = bias_all + z * 512;

    GEMM_MAINLOOP(Ahi, Alo, Bhi, Blo)

    float* cst = reinterpret_cast<float*>(smp) + w * 256;
    const int er = lane >> 1, ec = (lane & 1) * 8;
    // q pre-scale folds 1/sqrt(d) AND log2(e) (attention uses exp2)
    const float scale = 0.17677669529663689f * 1.4426950408889634f;
    #pragma unroll
    for (int i = 0; i < 4; i++)
        #pragma unroll
        for (int j = 0; j < 2; j++) {
            wmma::store_matrix_sync(cst, fc[i][j], 16, wmma::mem_row_major);
            __syncwarp();
            int gr = m0 + wm + i * 16 + er;
            int gn = n0 + wn + j * 16 + ec;
            float v[8];
            #pragma unroll
            for (int c = 0; c < 8; c++) v[c] = cst[er * 16 + ec + c] + bias[gn + c];

            if (z == 0) {
                // q: scale + single fp16
                size_t o = (size_t)gr * 512 + gn;
                #pragma unroll
                for (int c = 0; c < 8; c += 2)
                    *(__half2*)(g_qw + o + c) = __floats2half2_rn(v[c] * scale, v[c + 1] * scale);
            } else if (z == 1) {
                // k: windowed fan-out with teK added, fp16 hi/lo
                int b = gr >> 12, f = (gr >> 9) & 7, l = gr & 511;
                #pragma unroll
                for (int ii = 0; ii < 4; ii++) {
                    int t = f + 3 - ii;
                    if ((unsigned)t < 8u) {
                        size_t o = ((size_t)((b * 8 + t) * 4 + ii) * 512 + l) * 512 + gn;
                        const float* tek = g_teK + ii * 512 + gn;
                        #pragma unroll
                        for (int c = 0; c < 8; c += 2) {
                            __half2 h, lo2;
                            split2h(v[c] + tek[c], v[c + 1] + tek[c + 1], h, lo2);
                            *(__half2*)(g_kwh + o + c) = h;
                            *(__half2*)(g_kwl + o + c) = lo2;
                        }
                    }
                }
            } else {
                // v: padded layout, fp16 hi/lo
                int out_r = gr + ((gr >> 12) + 1) * 1536;
                size_t o = (size_t)out_r * 512 + gn;
                #pragma unroll
                for (int c = 0; c < 8; c += 2) {
                    __half2 h, lo2;
                    split2h(v[c], v[c + 1], h, lo2);
                    *(__half2*)(g_vph + o + c) = h;
                    *(__half2*)(g_vpl + o + c) = lo2;
                }
            }
            __syncwarp();
        }
}

// ---------------- pad fills: k-window pads (bias_k + teK) and v pads (bias_v), fp16 ----------------
__global__ void fill_pad2(const float* __restrict__ bias)
{
    int rid = blockIdx.x;
    int e = threadIdx.x * 2;
    if (rid < 6144) {
        int b = rid / 3072;
        int rem = rid - b * 3072;
        int pr = rem >> 9, l = rem & 511;
        const int tt[6] = {0, 0, 1, 0, 1, 2};
        const int ii[6] = {0, 1, 0, 2, 1, 0};
        int t = tt[pr], i = ii[pr];
        float x = bias[512 + e]     + g_teK[i * 512 + e];
        float y = bias[512 + e + 1] + g_teK[i * 512 + e + 1];
        __half2 h, lo2;
        split2h(x, y, h, lo2);
        size_t o = ((size_t)((b * 8 + t) * 4 + i) * 512 + l) * 512 + e;
        *(__half2*)(g_kwh + o) = h;
        *(__half2*)(g_kwl + o) = lo2;
    } else {
        int rid2 = rid - 6144;
        int b = rid2 / 1536;
        int rem = rid2 - b * 1536;
        int fp = rem >> 9, l = rem & 511;
        __half2 h, lo2;
        split2h(bias[1024 + e], bias[1024 + e + 1], h, lo2);
        size_t o = ((size_t)(b * 11 + fp) * 512 + l) * 512 + e;
        *(__half2*)(g_vph + o) = h;
        *(__half2*)(g_vpl + o) = lo2;
    }
}

// ---------------- teK: warp-per-output ----------------
__global__ void compute_teK(const float* __restrict__ te, const float* __restrict__ W)
{
    int o = blockIdx.x * 8 + (threadIdx.x >> 5);
    int lane = threadIdx.x & 31;
    int i = o >> 9, e = o & 511;
    const float4* wk = (const float4*)(W + (size_t)(512 + e) * 512) + lane * 4;
    const float4* tr = (const float4*)(te + i * 512) + lane * 4;
    float s = 0.f;
    #pragma unroll
    for (int k = 0; k < 4; k++) {
        float4 a = tr[k], b = wk[k];
        s += a.x * b.x + a.y * b.y + a.z * b.z + a.w * b.w;
    }
    #pragma unroll
    for (int d = 16; d > 0; d >>= 1) s += __shfl_xor_sync(0xffffffffu, s, d);
    if (lane == 0) g_teK[i * 512 + e] = s;
}

// ---------------- tensor-core flash attention, fp16 2-pass, 3-stage cp.async pipeline ----------------
// Q single fp16; K fp16 hi+lo (2-pass QK); V fp16 hi+lo (2-pass PV, P as fp16 hi only).
__global__ void __launch_bounds__(256) attn_mma()
{
    const int f = blockIdx.z, head = blockIdx.y;
    const int tid = threadIdx.x, w = tid >> 5, lane = tid & 31;
    const int b = f >> 3, t = f & 7;
    const int n32 = head * 32;
    const int qbase = blockIdx.x * 256 + w * 32;

    __shared__ __align__(16) __half sKV[3][4][32 * 40];

    uint32_t Qh[2][2][4];
    {
        int r = lane >> 2, c = (lane & 3) * 2;
        #pragma unroll
        for (int mt = 0; mt < 2; mt++)
            #pragma unroll
            for (int kt = 0; kt < 2; kt++) {
                size_t base = (size_t)(f * 512 + qbase + mt * 16 + r) * 512 + n32 + kt * 16 + c;
                Qh[mt][kt][0] = *(const uint32_t*)(g_qw + base);
                Qh[mt][kt][1] = *(const uint32_t*)(g_qw + base + 8 * 512);
                Qh[mt][kt][2] = *(const uint32_t*)(g_qw + base + 8);
                Qh[mt][kt][3] = *(const uint32_t*)(g_qw + base + 8 * 512 + 8);
            }
    }

    float O[2][4][4];
    float lsum[2][2] = {{0.f, 0.f}, {0.f, 0.f}};
    #pragma unroll
    for (int m = 0; m < 2; m++)
        #pragma unroll
        for (int n = 0; n < 4; n++)
            #pragma unroll
            for (int c = 0; c < 4; c++) O[m][n][c] = 0.f;

    const int idx0 = tid * 2;
    const int arr0 = idx0 >> 7;
    const int r0s = (idx0 >> 2) & 31, seg0 = idx0 & 3;
    const int r1s = ((idx0 + 1) >> 2) & 31, seg1 = (idx0 + 1) & 3;

    auto stage = [&](int cc, int buf) {
        int slot = cc >> 4, lb = (cc & 15) << 5;
        size_t krow = (size_t)((b * 8 + t) * 4 + slot) * 512 + lb;
        size_t vrow = (size_t)(b * 11 + t + slot) * 512 + lb;
        const __half* base =
            (arr0 == 0) ? g_kwh + (krow * 512 + n32) :
            (arr0 == 1) ? g_kwl + (krow * 512 + n32) :
            (arr0 == 2) ? g_vph + (vrow * 512 + n32) :
                          g_vpl + (vrow * 512 + n32);
        cp16(smem_u32(&sKV[buf][arr0][r0s * 40 + seg0 * 8]), base + (size_t)r0s * 512 + seg0 * 8);
        cp16(smem_u32(&sKV[buf][arr0][r1s * 40 + seg1 * 8]), base + (size_t)r1s * 512 + seg1 * 8);
        CP_COMMIT();
    };

    stage(0, 0);
    stage(1, 1);

    for (int cc = 0; cc < 64; cc++) {
        CP_WAIT1();
        __syncthreads();
        if (cc + 2 < 64) stage(cc + 2, (cc + 2) % 3); else CP_COMMIT();
        const int buf = cc % 3;

        // ---- S = Q @ K^T (2-pass: Qh·Kh + Qh·Kl) ----
        float S[2][4][4];
        #pragma unroll
        for (int m = 0; m < 2; m++)
            #pragma unroll
            for (int n = 0; n < 4; n++)
                #pragma unroll
                for (int c = 0; c < 4; c++) S[m][n][c] = 0.f;

        #pragma unroll
        for (int kt = 0; kt < 2; kt++) {
            #pragma unroll
            for (int nt = 0; nt < 4; nt++) {
                int l = lane & 15;
                int ki = (nt * 8 + (l & 7)) * 40 + kt * 16 + (l >> 3) * 8;
                uint32_t kh0, kh1, kl0, kl1;
                ldsm_x2(kh0, kh1, smem_u32(&sKV[buf][0][ki]));
                ldsm_x2(kl0, kl1, smem_u32(&sKV[buf][1][ki]));
                #pragma unroll
                for (int m = 0; m < 2; m++) {
                    mma16816h(S[m][nt], Qh[m][kt], kh0, kh1);
                    mma16816h(S[m][nt], Qh[m][kt], kl0, kl1);
                }
            }
        }

        // ---- exp2 + lsum ----
        #pragma unroll
        for (int m = 0; m < 2; m++)
            #pragma unroll
            for (int n = 0; n < 4; n++) {
                S[m][n][0] = exp2f(S[m][n][0]);
                S[m][n][1] = exp2f(S[m][n][1]);
                S[m][n][2] = exp2f(S[m][n][2]);
                S[m][n][3] = exp2f(S[m][n][3]);
                lsum[m][0] += S[m][n][0] + S[m][n][1];
                lsum[m][1] += S[m][n][2] + S[m][n][3];
            }

        // ---- O += P @ V (2-pass: Ph·Vh + Ph·Vl) ----
        #pragma unroll
        for (int kt = 0; kt < 2; kt++) {
            uint32_t Ph[2][4];
            #pragma unroll
            for (int m = 0; m < 2; m++) {
                const float* s0 = S[m][2 * kt];
                const float* s1 = S[m][2 * kt + 1];
                Ph[m][0] = hpack(s0[0], s0[1]);
                Ph[m][1] = hpack(s0[2], s0[3]);
                Ph[m][2] = hpack(s1[0], s1[1]);
                Ph[m][3] = hpack(s1[2], s1[3]);
            }
            #pragma unroll
            for (int nt = 0; nt < 4; nt++) {
                int l = lane & 15;
                int vi = (kt * 16 + l) * 40 + nt * 8;
                uint32_t vh0, vh1, vl0, vl1;
                ldsm_x2t(vh0, vh1, smem_u32(&sKV[buf][2][vi]));
                ldsm_x2t(vl0, vl1, smem_u32(&sKV[buf][3][vi]));
                #pragma unroll
                for (int m = 0; m < 2; m++) {
                    mma16816h(O[m][nt], Ph[m], vh0, vh1);
                    mma16816h(O[m][nt], Ph[m], vl0, vl1);
                }
            }
        }
    }

    // ---- epilogue ----
    float inv[2][2];
    #pragma unroll
    for (int m = 0; m < 2; m++)
        #pragma unroll
        for (int h = 0; h < 2; h++) {
            float s = lsum[m][h];
            s += __shfl_xor_sync(0xffffffffu, s, 1);
            s += __shfl_xor_sync(0xffffffffu, s, 2);
            inv[m][h] = 1.f / s;
        }
    #pragma unroll
    for (int m = 0; m < 2; m++) {
        int r0 = f * 512 + qbase + m * 16 + (lane >> 2);
        #pragma unroll
        for (int nt = 0; nt < 4; nt++) {
            int col = n32 + nt * 8 + (lane & 3) * 2;
            float a0 = O[m][nt][0] * inv[m][0], a1 = O[m][nt][1] * inv[m][0];
            float a2 = O[m][nt][2] * inv[m][1], a3 = O[m][nt][3] * inv[m][1];
            __nv_bfloat162 h0, l0, h1, l1;
            split2(a0, a1, h0, l0);
            split2(a2, a3, h1, l1);
            *(__nv_bfloat162*)(g_obh + (size_t)r0 * 512 + col)       = h0;
            *(__nv_bfloat162*)(g_obl + (size_t)r0 * 512 + col)       = l0;
            *(__nv_bfloat162*)(g_obh + (size_t)(r0 + 8) * 512 + col) = h1;
            *(__nv_bfloat162*)(g_obl + (size_t)(r0 + 8) * 512 + col) = l1;
        }
    }
}

// ---------------- launcher ----------------
extern "C" void kernel_launch(void* const* d_in, const int* in_sizes, int n_in,
                              void* d_out, int out_size)
{
    const float* hidden = (const float*)d_in[0];
    const float* W      = (const float*)d_in[1];
    const float* bias   = (const float*)d_in[2];
    const float* Wo     = (const float*)d_in[3];
    const float* bo     = (const float*)d_in[4];
    const float* te     = (const float*)d_in[5];
    float* out = (float*)d_out;

    __nv_bfloat16 *p_hh, *p_hl, *p_Wh, *p_Wl, *p_Woh, *p_Wol;
    __nv_bfloat16 *p_qbh, *p_qbl, *p_kbh, *p_kbl, *p_vbh, *p_vbl, *p_obh, *p_obl;
    cudaGetSymbolAddress((void**)&p_hh,  g_hh);   cudaGetSymbolAddress((void**)&p_hl,  g_hl);
    cudaGetSymbolAddress((void**)&p_Wh,  g_Wh);   cudaGetSymbolAddress((void**)&p_Wl,  g_Wl);
    cudaGetSymbolAddress((void**)&p_Woh, g_Woh);  cudaGetSymbolAddress((void**)&p_Wol, g_Wol);
    cudaGetSymbolAddress((void**)&p_qbh, g_qbh);  cudaGetSymbolAddress((void**)&p_qbl, g_qbl);
    cudaGetSymbolAddress((void**)&p_kbh, g_kbh);  cudaGetSymbolAddress((void**)&p_kbl, g_kbl);
    cudaGetSymbolAddress((void**)&p_vbh, g_vbh);  cudaGetSymbolAddress((void**)&p_vbl, g_vbl);
    cudaGetSymbolAddress((void**)&p_obh, g_obh);  cudaGetSymbolAddress((void**)&p_obl, g_obl);

    cudaFuncSetAttribute(gemm_rope,  cudaFuncAttributeMaxDynamicSharedMemorySize, GEMM_SMEM);
    cudaFuncSetAttribute(gemm_wmma,  cudaFuncAttributeMaxDynamicSharedMemorySize, GEMM_SMEM);
    cudaFuncSetAttribute(gemm_small, cudaFuncAttributeMaxDynamicSharedMemorySize, GEMM_SMEM);

    // 0) rope table + input splits + teK
    rope_table<<<32, 256>>>();
    split_all<<<5120, 256>>>(hidden, W, Wo);
    compute_teK<<<256, 256>>>(te, W);

    // 1) qkv GEMM with fused RoPE + reorder + split epilogue
    gemm_rope<<<dim3(12, 64), 256, GEMM_SMEM>>>(p_hh, p_hl, p_Wh, p_Wl, bias);

    // 2) pad fills
    fill_pad2<<<6144 + 3072, 256>>>(bias);

    // 3) fused second projections (attention operands emitted as fp16)
    gemm_small<<<dim3(4, 64, 3), 256, GEMM_SMEM>>>(p_qbh, p_qbl, p_kbh, p_kbl, p_vbh, p_vbl,
                                                   p_Wh, p_Wl, bias);

    // 4) sliding-window attention (fp16 2-pass)
    attn_mma<<<dim3(2, 16, 16), 256>>>();

    // 5) out = o @ Wo^T + bo
    gemm_wmma<<<dim3(4, 64), 256, GEMM_SMEM>>>(p_obh, p_obl, p_Woh, p_Wol, bo, out, 512);
}

// round 16
// speedup vs baseline: 1.2833x; 1.0026x over previous
#include <cuda_runtime.h>
#include <cuda_bf16.h>
#include <cuda_fp16.h>
#include <mma.h>
#include <math.h>
#include <cstdint>

using namespace nvcuda;

// ---------------- problem constants ----------------
// B=2, T=8, H=16, W=16, E=512, n_heads=16, d=32, S=4096, L2=512, WINDOW=4
// frames BT=16, padded frames per batch TPAD=11, K of all GEMMs = 512

// ---------------- device scratch ----------------
__device__ __align__(128) float g_teK[4 * 512];
__device__ __align__(128) float2 g_ropeT[2 * 256 * 16];    // cos/sin table

__device__ __align__(128) __nv_bfloat16 g_hh [8192ull * 512], g_hl [8192ull * 512];
__device__ __align__(128) __nv_bfloat16 g_Wh [1536ull * 512], g_Wl [1536ull * 512];
__device__ __align__(128) __nv_bfloat16 g_Woh[ 512ull * 512], g_Wol[ 512ull * 512];
__device__ __align__(128) __nv_bfloat16 g_qbh[8192ull * 512], g_qbl[8192ull * 512];
__device__ __align__(128) __nv_bfloat16 g_kbh[8192ull * 512], g_kbl[8192ull * 512];
__device__ __align__(128) __nv_bfloat16 g_vbh[8192ull * 512], g_vbl[8192ull * 512];
__device__ __align__(128) __nv_bfloat16 g_obh[8192ull * 512], g_obl[8192ull * 512];

// attention operands: fp16 (Q single, K/V hi+lo), windowed K
__device__ __align__(128) __half g_qw [8192ull * 512];
__device__ __align__(128) __half g_kwh[2ull*8*4*512*512], g_kwl[2ull*8*4*512*512];
__device__ __align__(128) __half g_vph[2ull*11*512*512],  g_vpl[2ull*11*512*512];

// ---------------- helpers ----------------
__device__ __forceinline__ void split2(float x, float y,
                                       __nv_bfloat162& h, __nv_bfloat162& l) {
    __nv_bfloat16 hx = __float2bfloat16_rn(x);
    __nv_bfloat16 hy = __float2bfloat16_rn(y);
    h = __halves2bfloat162(hx, hy);
    l = __halves2bfloat162(__float2bfloat16_rn(x - __bfloat162float(hx)),
                           __float2bfloat16_rn(y - __bfloat162float(hy)));
}
__device__ __forceinline__ void split2h(float x, float y, __half2& h, __half2& l) {
    __half hx = __float2half_rn(x);
    __half hy = __float2half_rn(y);
    h = __halves2half2(hx, hy);
    l = __halves2half2(__float2half_rn(x - __half2float(hx)),
                       __float2half_rn(y - __half2float(hy)));
}
__device__ __forceinline__ uint32_t hpack(float x, float y) {
    __half2 h = __floats2half2_rn(x, y);
    return *(uint32_t*)&h;
}
__device__ __forceinline__ uint32_t smem_u32(const void* p) {
    uint32_t a;
    asm("{ .reg .u64 t; cvta.to.shared.u64 t, %1; cvt.u32.u64 %0, t; }" : "=r"(a) : "l"(p));
    return a;
}
__device__ __forceinline__ void ldsm_x2(uint32_t& r0, uint32_t& r1, uint32_t addr) {
    asm volatile("ldmatrix.sync.aligned.m8n8.x2.shared.b16 {%0,%1}, [%2];"
        : "=r"(r0), "=r"(r1) : "r"(addr));
}
__device__ __forceinline__ void ldsm_x2t(uint32_t& r0, uint32_t& r1, uint32_t addr) {
    asm volatile("ldmatrix.sync.aligned.m8n8.x2.trans.shared.b16 {%0,%1}, [%2];"
        : "=r"(r0), "=r"(r1) : "r"(addr));
}
__device__ __forceinline__ void mma16816h(float* d, const uint32_t* a, uint32_t b0, uint32_t b1) {
    asm volatile("mma.sync.aligned.m16n8k16.row.col.f32.f16.f16.f32 "
        "{%0,%1,%2,%3}, {%4,%5,%6,%7}, {%8,%9}, {%0,%1,%2,%3};"
        : "+f"(d[0]), "+f"(d[1]), "+f"(d[2]), "+f"(d[3])
        : "r"(a[0]), "r"(a[1]), "r"(a[2]), "r"(a[3]), "r"(b0), "r"(b1));
}
__device__ __forceinline__ void cp16(uint32_t dst, const void* src) {
    asm volatile("cp.async.cg.shared.global [%0], [%1], 16;" :: "r"(dst), "l"(src));
}
#define CP_COMMIT() asm volatile("cp.async.commit_group;" ::: "memory")
#define CP_WAIT0()  asm volatile("cp.async.wait_group 0;" ::: "memory")
#define CP_WAIT1()  asm volatile("cp.async.wait_group 1;" ::: "memory")

// ---------------- rope table precompute ----------------
__global__ void rope_table()
{
    int idx = blockIdx.x * 256 + threadIdx.x;   // 8192 entries
    int tsel = idx >> 12, pos = (idx >> 4) & 255, j = idx & 15;
    int fidx; float posv;
    if (tsel == 0) { fidx = j; posv = (float)pos; }
    else {
        int h = pos >> 4, w = pos & 15;
        if (j < 8) { fidx = 2 * j;           posv = (float)h; }
        else       { fidx = 2 * (j - 8) + 1; posv = (float)w; }
    }
    float freq = __powf(10000.0f, -(float)fidx * (1.0f / 16.0f));
    float sn, cs;
    sincosf(posv * freq, &sn, &cs);
    g_ropeT[idx] = make_float2(cs, sn);
}

// ---------------- fused bf16 split of the 3 fp32 inputs ----------------
__global__ void split_all(const float* __restrict__ hidden, const float* __restrict__ W,
                          const float* __restrict__ Wo)
{
    int bid = blockIdx.x;
    const float* src;
    __nv_bfloat16 *hi, *lo;
    int rb;
    if (bid < 4096)      { src = hidden; hi = g_hh;  lo = g_hl;  rb = bid; }
    else if (bid < 4864) { src = W;      hi = g_Wh;  lo = g_Wl;  rb = bid - 4096; }
    else                 { src = Wo;     hi = g_Woh; lo = g_Wol; rb = bid - 4864; }
    size_t i = ((size_t)rb * 256 + threadIdx.x) * 4;
    float4 v = *(const float4*)(src + i);
    __nv_bfloat162 h0, l0, h1, l1;
    split2(v.x, v.y, h0, l0);
    split2(v.z, v.w, h1, l1);
    *(__nv_bfloat162*)(hi + i)     = h0;
    *(__nv_bfloat162*)(hi + i + 2) = h1;
    *(__nv_bfloat162*)(lo + i)     = l0;
    *(__nv_bfloat162*)(lo + i + 2) = l1;
}

// ---------------- cp.async double-buffered GEMM mainloop (bf16 3-pass) ----------------
#define GEMM_MAINLOOP(Ahi, Alo, Bhi, Blo)                                           \
    wmma::fragment<wmma::accumulator, 16, 16, 16, float> fc[4][2];                  \
    _Pragma("unroll") for (int i = 0; i < 4; i++)                                   \
        _Pragma("unroll") for (int j = 0; j < 2; j++) wmma::fill_fragment(fc[i][j], 0.f); \
    auto stage = [&](int st) {                                                      \
        int k0 = st * 32;                                                           \
        int bo = (st & 1) * 20480;                                                  \
        _Pragma("unroll") for (int i = 0; i < 8; i++) {                             \
            int c = tid + i * 256;                                                  \
            int arr = c >> 9, rem = c & 511, row = rem >> 2, seg = rem & 3;         \
            const __nv_bfloat16* src =                                              \
                (arr == 0) ? Ahi + (size_t)(m0 + row) * 512 + k0 + seg * 8 :        \
                (arr == 1) ? Alo + (size_t)(m0 + row) * 512 + k0 + seg * 8 :        \
                (arr == 2) ? Bhi + (size_t)(n0 + row) * 512 + k0 + seg * 8 :        \
                             Blo + (size_t)(n0 + row) * 512 + k0 + seg * 8;         \
            cp16(smem_u32(smp + bo + arr * 5120 + row * 40 + seg * 8), src);        \
        }                                                                           \
        CP_COMMIT();                                                                \
    };                                                                              \
    stage(0);                                                                       \
    for (int st = 0; st < 16; st++) {                                               \
        CP_WAIT0();                                                                 \
        __syncthreads();                                                            \
        if (st + 1 < 16) stage(st + 1);                                             \
        const __nv_bfloat16* sAh = smp + (st & 1) * 20480;                          \
        const __nv_bfloat16* sAl = sAh + 5120;                                      \
        const __nv_bfloat16* sBh = sAh + 10240;                                     \
        const __nv_bfloat16* sBl = sAh + 15360;                                     \
        _Pragma("unroll") for (int ks = 0; ks < 32; ks += 16) {                     \
            wmma::fragment<wmma::matrix_a, 16, 16, 16, __nv_bfloat16, wmma::row_major> fah[4], fal[4]; \
            wmma::fragment<wmma::matrix_b, 16, 16, 16, __nv_bfloat16, wmma::col_major> fbh[2], fbl[2]; \
            _Pragma("unroll") for (int i = 0; i < 4; i++) {                         \
                wmma::load_matrix_sync(fah[i], &sAh[(wm + i * 16) * 40 + ks], 40);  \
                wmma::load_matrix_sync(fal[i], &sAl[(wm + i * 16) * 40 + ks], 40);  \
            }                                                                       \
            _Pragma("unroll") for (int j = 0; j < 2; j++) {                         \
                wmma::load_matrix_sync(fbh[j], &sBh[(wn + j * 16) * 40 + ks], 40);  \
                wmma::load_matrix_sync(fbl[j], &sBl[(wn + j * 16) * 40 + ks], 40);  \
            }                                                                       \
            _Pragma("unroll") for (int i = 0; i < 4; i++)                           \
                _Pragma("unroll") for (int j = 0; j < 2; j++) {                     \
                    wmma::mma_sync(fc[i][j], fah[i], fbh[j], fc[i][j]);             \
                    wmma::mma_sync(fc[i][j], fah[i], fbl[j], fc[i][j]);             \
                    wmma::mma_sync(fc[i][j], fal[i], fbh[j], fc[i][j]);             \
                }                                                                   \
        }                                                                           \
        __syncthreads();                                                            \
    }

static constexpr int GEMM_SMEM = 2 * 4 * 5120 * 2;  // 81920 bytes

// ---------------- big qkv GEMM with fused RoPE + reorder + bf16-split epilogue ----------------
__global__ void __launch_bounds__(256, 2) gemm_rope(
    const __nv_bfloat16* __restrict__ Ahi, const __nv_bfloat16* __restrict__ Alo,
    const __nv_bfloat16* __restrict__ Bhi, const __nv_bfloat16* __restrict__ Blo,
    const float* __restrict__ bias)
{
    extern __shared__ __align__(16) __nv_bfloat16 smp[];
    const int tid = threadIdx.x, w = tid >> 5, lane = tid & 31;
    const int m0 = blockIdx.y * 128, n0 = blockIdx.x * 128;
    const int wm = (w >> 2) * 64, wn = (w & 3) * 32;

    GEMM_MAINLOOP(Ahi, Alo, Bhi, Blo)

    float* cst = reinterpret_cast<float*>(smp) + w * 256;
    const int er = lane >> 1, ec = (lane & 1) * 8;
    #pragma unroll
    for (int i = 0; i < 4; i++)
        #pragma unroll
        for (int j = 0; j < 2; j++) {
            wmma::store_matrix_sync(cst, fc[i][j], 16, wmma::mem_row_major);
            __syncwarp();
            int gr = m0 + wm + i * 16 + er;
            int gn = n0 + wn + j * 16 + ec;
            int b = gr >> 12, s = gr & 4095;
            float v[8];
            #pragma unroll
            for (int c = 0; c < 8; c++) v[c] = cst[er * 16 + ec + c] + bias[gn + c];

            int z = gn >> 9;   // block-uniform (128 | 512)
            if (z == 2) {
                int frame = b * 8 + (s >> 9), l = s & 511;
                size_t o = ((size_t)frame * 512 + l) * 512 + (gn & 511);
                #pragma unroll
                for (int c = 0; c < 8; c += 2) {
                    __nv_bfloat162 h2, l2;
                    split2(v[c], v[c + 1], h2, l2);
                    *(__nv_bfloat162*)(g_vbh + o + c) = h2;
                    *(__nv_bfloat162*)(g_vbl + o + c) = l2;
                }
            } else {
                int frame, l;
                if (s < 2048) { frame = b * 8 + (s >> 8); l = s & 255; }
                else { int s2 = s - 2048; frame = b * 8 + (s2 >> 8); l = 256 + (s2 & 255); }
                size_t o = ((size_t)frame * 512 + l) * 512 + (gn & 511);
                __nv_bfloat16* hi = z ? g_kbh : g_qbh;
                __nv_bfloat16* lo = z ? g_kbl : g_qbl;
                int tbase = ((s >> 11) << 12) + ((s & 255) << 4);
                #pragma unroll
                for (int c = 0; c < 8; c += 2) {
                    int pj = ((gn + c) >> 1) & 15;
                    float2 tv = g_ropeT[tbase + pj];
                    float xr = v[c] * tv.x - v[c + 1] * tv.y;
                    float xi = v[c] * tv.y + v[c + 1] * tv.x;
                    __nv_bfloat162 h2, l2;
                    split2(xr, xi, h2, l2);
                    *(__nv_bfloat162*)(hi + o + c) = h2;
                    *(__nv_bfloat162*)(lo + o + c) = l2;
                }
            }
            __syncwarp();
        }
}

// ---------------- GEMM with fp32 output (out-proj) ----------------
__global__ void __launch_bounds__(256, 2) gemm_wmma(
    const __nv_bfloat16* __restrict__ Ahi, const __nv_bfloat16* __restrict__ Alo,
    const __nv_bfloat16* __restrict__ Bhi, const __nv_bfloat16* __restrict__ Blo,
    const float* __restrict__ bias, float* __restrict__ C, int N)
{
    extern __shared__ __align__(16) __nv_bfloat16 smp[];
    const int tid = threadIdx.x, w = tid >> 5, lane = tid & 31;
    const int m0 = blockIdx.y * 128, n0 = blockIdx.x * 128;
    const int wm = (w >> 2) * 64, wn = (w & 3) * 32;

    GEMM_MAINLOOP(Ahi, Alo, Bhi, Blo)

    float* cst = reinterpret_cast<float*>(smp) + w * 256;
    const int er = lane >> 1, ec = (lane & 1) * 8;
    #pragma unroll
    for (int i = 0; i < 4; i++)
        #pragma unroll
        for (int j = 0; j < 2; j++) {
            wmma::store_matrix_sync(cst, fc[i][j], 16, wmma::mem_row_major);
            __syncwarp();
            int gr = m0 + wm + i * 16 + er;
            int gn = n0 + wn + j * 16 + ec;
            float4 v0 = *(float4*)&cst[er * 16 + ec];
            float4 v1 = *(float4*)&cst[er * 16 + ec + 4];
            float4 b0 = *(const float4*)(bias + gn);
            float4 b1 = *(const float4*)(bias + gn + 4);
            v0.x += b0.x; v0.y += b0.y; v0.z += b0.z; v0.w += b0.w;
            v1.x += b1.x; v1.y += b1.y; v1.z += b1.z; v1.w += b1.w;
            float* crow = C + (size_t)gr * N + gn;
            *(float4*)crow = v0;
            *(float4*)(crow + 4) = v1;
            __syncwarp();
        }
}

// ---------------- fused second projections (z = 0:q fp16, 1:k-window fp16, 2:v-padded fp16) ----------------
__global__ void __launch_bounds__(256, 2) gemm_small(
    const __nv_bfloat16* __restrict__ qAh, const __nv_bfloat16* __restrict__ qAl,
    const __nv_bfloat16* __restrict__ kAh, const __nv_bfloat16* __restrict__ kAl,
    const __nv_bfloat16* __restrict__ vAh, const __nv_bfloat16* __restrict__ vAl,
    const __nv_bfloat16* __restrict__ Wh,  const __nv_bfloat16* __restrict__ Wl,
    const float* __restrict__ bias_all)
{
    extern __shared__ __align__(16) __nv_bfloat16 smp[];
    const int tid = threadIdx.x, w = tid >> 5, lane = tid & 31;
    const int z = blockIdx.z;
    const int m0 = blockIdx.y * 128, n0 = blockIdx.x * 128;
    const int wm = (w >> 2) * 64, wn = (w & 3) * 32;

    const __nv_bfloat16* Ahi = (z == 0) ? qAh : (z == 1) ? kAh : vAh;
    const __nv_bfloat16* Alo = (z == 0) ? qAl : (z == 1) ? kAl : vAl;
    const __nv_bfloat16* Bhi = Wh + (size_t)z * 512 * 512;
    const __nv_bfloat16* Blo = Wl + (size_t)z * 512 * 512;
    const float* bias = bias_all + z * 512;

    GEMM_MAINLOOP(Ahi, Alo, Bhi, Blo)

    float* cst = reinterpret_cast<float*>(smp) + w * 256;
    const int er = lane >> 1, ec = (lane & 1) * 8;
    // q pre-scale folds 1/sqrt(d) AND log2(e) (attention uses exp2)
    const float scale = 0.17677669529663689f * 1.4426950408889634f;
    #pragma unroll
    for (int i = 0; i < 4; i++)
        #pragma unroll
        for (int j = 0; j < 2; j++) {
            wmma::store_matrix_sync(cst, fc[i][j], 16, wmma::mem_row_major);
            __syncwarp();
            int gr = m0 + wm + i * 16 + er;
            int gn = n0 + wn + j * 16 + ec;
            float v[8];
            #pragma unroll
            for (int c = 0; c < 8; c++) v[c] = cst[er * 16 + ec + c] + bias[gn + c];

            if (z == 0) {
                // q: scale + single fp16
                size_t o = (size_t)gr * 512 + gn;
                #pragma unroll
                for (int c = 0; c < 8; c += 2)
                    *(__half2*)(g_qw + o + c) = __floats2half2_rn(v[c] * scale, v[c + 1] * scale);
            } else if (z == 1) {
                // k: windowed fan-out with teK added, fp16 hi/lo
                int b = gr >> 12, f = (gr >> 9) & 7, l = gr & 511;
                #pragma unroll
                for (int ii = 0; ii < 4; ii++) {
                    int t = f + 3 - ii;
                    if ((unsigned)t < 8u) {
                        size_t o = ((size_t)((b * 8 + t) * 4 + ii) * 512 + l) * 512 + gn;
                        const float* tek = g_teK + ii * 512 + gn;
                        #pragma unroll
                        for (int c = 0; c < 8; c += 2) {
                            __half2 h, lo2;
                            split2h(v[c] + tek[c], v[c + 1] + tek[c + 1], h, lo2);
                            *(__half2*)(g_kwh + o + c) = h;
                            *(__half2*)(g_kwl + o + c) = lo2;
                        }
                    }
                }
            } else {
                // v: padded layout, fp16 hi/lo
                int out_r = gr + ((gr >> 12) + 1) * 1536;
                size_t o = (size_t)out_r * 512 + gn;
                #pragma unroll
                for (int c = 0; c < 8; c += 2) {
                    __half2 h, lo2;
                    split2h(v[c], v[c + 1], h, lo2);
                    *(__half2*)(g_vph + o + c) = h;
                    *(__half2*)(g_vpl + o + c) = lo2;
                }
            }
            __syncwarp();
        }
}

// ---------------- pad fills: k-window pads (bias_k + teK) and v pads (bias_v), fp16 ----------------
__global__ void fill_pad2(const float* __restrict__ bias)
{
    int rid = blockIdx.x;
    int e = threadIdx.x * 2;
    if (rid < 6144) {
        int b = rid / 3072;
        int rem = rid - b * 3072;
        int pr = rem >> 9, l = rem & 511;
        const int tt[6] = {0, 0, 1, 0, 1, 2};
        const int ii[6] = {0, 1, 0, 2, 1, 0};
        int t = tt[pr], i = ii[pr];
        float x = bias[512 + e]     + g_teK[i * 512 + e];
        float y = bias[512 + e + 1] + g_teK[i * 512 + e + 1];
        __half2 h, lo2;
        split2h(x, y, h, lo2);
        size_t o = ((size_t)((b * 8 + t) * 4 + i) * 512 + l) * 512 + e;
        *(__half2*)(g_kwh + o) = h;
        *(__half2*)(g_kwl + o) = lo2;
    } else {
        int rid2 = rid - 6144;
        int b = rid2 / 1536;
        int rem = rid2 - b * 1536;
        int fp = rem >> 9, l = rem & 511;
        __half2 h, lo2;
        split2h(bias[1024 + e], bias[1024 + e + 1], h, lo2);
        size_t o = ((size_t)(b * 11 + fp) * 512 + l) * 512 + e;
        *(__half2*)(g_vph + o) = h;
        *(__half2*)(g_vpl + o) = lo2;
    }
}

// ---------------- teK: warp-per-output ----------------
__global__ void compute_teK(const float* __restrict__ te, const float* __restrict__ W)
{
    int o = blockIdx.x * 8 + (threadIdx.x >> 5);
    int lane = threadIdx.x & 31;
    int i = o >> 9, e = o & 511;
    const float4* wk = (const float4*)(W + (size_t)(512 + e) * 512) + lane * 4;
    const float4* tr = (const float4*)(te + i * 512) + lane * 4;
    float s = 0.f;
    #pragma unroll
    for (int k = 0; k < 4; k++) {
        float4 a = tr[k], b = wk[k];
        s += a.x * b.x + a.y * b.y + a.z * b.z + a.w * b.w;
    }
    #pragma unroll
    for (int d = 16; d > 0; d >>= 1) s += __shfl_xor_sync(0xffffffffu, s, d);
    if (lane == 0) g_teK[i * 512 + e] = s;
}

// ---------------- tensor-core flash attention, fp16 2-pass, 3-stage cp.async pipeline ----------------
// Q single fp16; K fp16 hi+lo (2-pass QK); V fp16 hi+lo (2-pass PV, P as fp16 hi only).
__global__ void __launch_bounds__(256) attn_mma()
{
    const int f = blockIdx.z, head = blockIdx.y;
    const int tid = threadIdx.x, w = tid >> 5, lane = tid & 31;
    const int b = f >> 3, t = f & 7;
    const int n32 = head * 32;
    const int qbase = blockIdx.x * 256 + w * 32;

    __shared__ __align__(16) __half sKV[3][4][32 * 40];

    uint32_t Qh[2][2][4];
    {
        int r = lane >> 2, c = (lane & 3) * 2;
        #pragma unroll
        for (int mt = 0; mt < 2; mt++)
            #pragma unroll
            for (int kt = 0; kt < 2; kt++) {
                size_t base = (size_t)(f * 512 + qbase + mt * 16 + r) * 512 + n32 + kt * 16 + c;
                Qh[mt][kt][0] = *(const uint32_t*)(g_qw + base);
                Qh[mt][kt][1] = *(const uint32_t*)(g_qw + base + 8 * 512);
                Qh[mt][kt][2] = *(const uint32_t*)(g_qw + base + 8);
                Qh[mt][kt][3] = *(const uint32_t*)(g_qw + base + 8 * 512 + 8);
            }
    }

    float O[2][4][4];
    float lsum[2][2] = {{0.f, 0.f}, {0.f, 0.f}};
    #pragma unroll
    for (int m = 0; m < 2; m++)
        #pragma unroll
        for (int n = 0; n < 4; n++)
            #pragma unroll
            for (int c = 0; c < 4; c++) O[m][n][c] = 0.f;

    const int idx0 = tid * 2;
    const int arr0 = idx0 >> 7;
    const int r0s = (idx0 >> 2) & 31, seg0 = idx0 & 3;
    const int r1s = ((idx0 + 1) >> 2) & 31, seg1 = (idx0 + 1) & 3;

    auto stage = [&](int cc, int buf) {
        int slot = cc >> 4, lb = (cc & 15) << 5;
        size_t krow = (size_t)((b * 8 + t) * 4 + slot) * 512 + lb;
        size_t vrow = (size_t)(b * 11 + t + slot) * 512 + lb;
        const __half* base =
            (arr0 == 0) ? g_kwh + (krow * 512 + n32) :
            (arr0 == 1) ? g_kwl + (krow * 512 + n32) :
            (arr0 == 2) ? g_vph + (vrow * 512 + n32) :
                          g_vpl + (vrow * 512 + n32);
        cp16(smem_u32(&sKV[buf][arr0][r0s * 40 + seg0 * 8]), base + (size_t)r0s * 512 + seg0 * 8);
        cp16(smem_u32(&sKV[buf][arr0][r1s * 40 + seg1 * 8]), base + (size_t)r1s * 512 + seg1 * 8);
        CP_COMMIT();
    };

    stage(0, 0);
    stage(1, 1);

    for (int cc = 0; cc < 64; cc++) {
        CP_WAIT1();
        __syncthreads();
        if (cc + 2 < 64) stage(cc + 2, (cc + 2) % 3); else CP_COMMIT();
        const int buf = cc % 3;

        // ---- S = Q @ K^T (2-pass: Qh·Kh + Qh·Kl) ----
        float S[2][4][4];
        #pragma unroll
        for (int m = 0; m < 2; m++)
            #pragma unroll
            for (int n = 0; n < 4; n++)
                #pragma unroll
                for (int c = 0; c < 4; c++) S[m][n][c] = 0.f;

        #pragma unroll
        for (int kt = 0; kt < 2; kt++) {
            #pragma unroll
            for (int nt = 0; nt < 4; nt++) {
                int l = lane & 15;
                int ki = (nt * 8 + (l & 7)) * 40 + kt * 16 + (l >> 3) * 8;
                uint32_t kh0, kh1, kl0, kl1;
                ldsm_x2(kh0, kh1, smem_u32(&sKV[buf][0][ki]));
                ldsm_x2(kl0, kl1, smem_u32(&sKV[buf][1][ki]));
                #pragma unroll
                for (int m = 0; m < 2; m++) {
                    mma16816h(S[m][nt], Qh[m][kt], kh0, kh1);
                    mma16816h(S[m][nt], Qh[m][kt], kl0, kl1);
                }
            }
        }

        // ---- exp2 + lsum ----
        #pragma unroll
        for (int m = 0; m < 2; m++)
            #pragma unroll
            for (int n = 0; n < 4; n++) {
                S[m][n][0] = exp2f(S[m][n][0]);
                S[m][n][1] = exp2f(S[m][n][1]);
                S[m][n][2] = exp2f(S[m][n][2]);
                S[m][n][3] = exp2f(S[m][n][3]);
                lsum[m][0] += S[m][n][0] + S[m][n][1];
                lsum[m][1] += S[m][n][2] + S[m][n][3];
            }

        // ---- O += P @ V (2-pass: Ph·Vh + Ph·Vl) ----
        #pragma unroll
        for (int kt = 0; kt < 2; kt++) {
            uint32_t Ph[2][4];
            #pragma unroll
            for (int m = 0; m < 2; m++) {
                const float* s0 = S[m][2 * kt];
                const float* s1 = S[m][2 * kt + 1];
                Ph[m][0] = hpack(s0[0], s0[1]);
                Ph[m][1] = hpack(s0[2], s0[3]);
                Ph[m][2] = hpack(s1[0], s1[1]);
                Ph[m][3] = hpack(s1[2], s1[3]);
            }
            #pragma unroll
            for (int nt = 0; nt < 4; nt++) {
                int l = lane & 15;
                int vi = (kt * 16 + l) * 40 + nt * 8;
                uint32_t vh0, vh1, vl0, vl1;
                ldsm_x2t(vh0, vh1, smem_u32(&sKV[buf][2][vi]));
                ldsm_x2t(vl0, vl1, smem_u32(&sKV[buf][3][vi]));
                #pragma unroll
                for (int m = 0; m < 2; m++) {
                    mma16816h(O[m][nt], Ph[m], vh0, vh1);
                    mma16816h(O[m][nt], Ph[m], vl0, vl1);
                }
            }
        }
    }

    // ---- epilogue ----
    float inv[2][2];
    #pragma unroll
    for (int m = 0; m < 2; m++)
        #pragma unroll
        for (int h = 0; h < 2; h++) {
            float s = lsum[m][h];
            s += __shfl_xor_sync(0xffffffffu, s, 1);
            s += __shfl_xor_sync(0xffffffffu, s, 2);
            inv[m][h] = 1.f / s;
        }
    #pragma unroll
    for (int m = 0; m < 2; m++) {
        int r0 = f * 512 + qbase + m * 16 + (lane >> 2);
        #pragma unroll
        for (int nt = 0; nt < 4; nt++) {
            int col = n32 + nt * 8 + (lane & 3) * 2;
            float a0 = O[m][nt][0] * inv[m][0], a1 = O[m][nt][1] * inv[m][0];
            float a2 = O[m][nt][2] * inv[m][1], a3 = O[m][nt][3] * inv[m][1];
            __nv_bfloat162 h0, l0, h1, l1;
            split2(a0, a1, h0, l0);
            split2(a2, a3, h1, l1);
            *(__nv_bfloat162*)(g_obh + (size_t)r0 * 512 + col)       = h0;
            *(__nv_bfloat162*)(g_obl + (size_t)r0 * 512 + col)       = l0;
            *(__nv_bfloat162*)(g_obh + (size_t)(r0 + 8) * 512 + col) = h1;
            *(__nv_bfloat162*)(g_obl + (size_t)(r0 + 8) * 512 + col) = l1;
        }
    }
}

// ---------------- launcher ----------------
extern "C" void kernel_launch(void* const* d_in, const int* in_sizes, int n_in,
                              void* d_out, int out_size)
{
    const float* hidden = (const float*)d_in[0];
    const float* W      = (const float*)d_in[1];
    const float* bias   = (const float*)d_in[2];
    const float* Wo     = (const float*)d_in[3];
    const float* bo     = (const float*)d_in[4];
    const float* te     = (const float*)d_in[5];
    float* out = (float*)d_out;

    __nv_bfloat16 *p_hh, *p_hl, *p_Wh, *p_Wl, *p_Woh, *p_Wol;
    __nv_bfloat16 *p_qbh, *p_qbl, *p_kbh, *p_kbl, *p_vbh, *p_vbl, *p_obh, *p_obl;
    cudaGetSymbolAddress((void**)&p_hh,  g_hh);   cudaGetSymbolAddress((void**)&p_hl,  g_hl);
    cudaGetSymbolAddress((void**)&p_Wh,  g_Wh);   cudaGetSymbolAddress((void**)&p_Wl,  g_Wl);
    cudaGetSymbolAddress((void**)&p_Woh, g_Woh);  cudaGetSymbolAddress((void**)&p_Wol, g_Wol);
    cudaGetSymbolAddress((void**)&p_qbh, g_qbh);  cudaGetSymbolAddress((void**)&p_qbl, g_qbl);
    cudaGetSymbolAddress((void**)&p_kbh, g_kbh);  cudaGetSymbolAddress((void**)&p_kbl, g_kbl);
    cudaGetSymbolAddress((void**)&p_vbh, g_vbh);  cudaGetSymbolAddress((void**)&p_vbl, g_vbl);
    cudaGetSymbolAddress((void**)&p_obh, g_obh);  cudaGetSymbolAddress((void**)&p_obl, g_obl);

    cudaFuncSetAttribute(gemm_rope,  cudaFuncAttributeMaxDynamicSharedMemorySize, GEMM_SMEM);
    cudaFuncSetAttribute(gemm_wmma,  cudaFuncAttributeMaxDynamicSharedMemorySize, GEMM_SMEM);
    cudaFuncSetAttribute(gemm_small, cudaFuncAttributeMaxDynamicSharedMemorySize, GEMM_SMEM);

    // 0) rope table + input splits + teK
    rope_table<<<32, 256>>>();
    split_all<<<5120, 256>>>(hidden, W, Wo);
    compute_teK<<<256, 256>>>(te, W);

    // 1) qkv GEMM with fused RoPE + reorder + split epilogue
    gemm_rope<<<dim3(12, 64), 256, GEMM_SMEM>>>(p_hh, p_hl, p_Wh, p_Wl, bias);

    // 2) pad fills
    fill_pad2<<<6144 + 3072, 256>>>(bias);

    // 3) fused second projections (attention operands emitted as fp16)
    gemm_small<<<dim3(4, 64, 3), 256, GEMM_SMEM>>>(p_qbh, p_qbl, p_kbh, p_kbl, p_vbh, p_vbl,
                                                   p_Wh, p_Wl, bias);

    // 4) sliding-window attention (fp16 2-pass)
    attn_mma<<<dim3(2, 16, 16), 256>>>();

    // 5) out = o @ Wo^T + bo
    gemm_wmma<<<dim3(4, 64), 256, GEMM_SMEM>>>(p_obh, p_obl, p_Woh, p_Wol, bo, out, 512);
}